// round 1
// baseline (speedup 1.0000x reference)
#include <cuda_runtime.h>
#include <math.h>

// Problem constants
#define Bb  4
#define Ss  2048
#define Dd  1024
#define Hh  16
#define HD  64
#define BH  (Bb*Hh)     // 64
#define MM  (Bb*Ss)     // 8192

// Scratch (device globals -> no allocation)
__device__ float g_Q[(size_t)BH*Ss*HD];     // [b,h,s,hd]
__device__ float g_K[(size_t)BH*Ss*HD];
__device__ float g_V[(size_t)BH*Ss*HD];
__device__ float g_ctx[(size_t)MM*Dd];      // [b,s,h*hd]

// ---------------------------------------------------------------------------
// SGEMM: Y[m,e] = sum_d X[m,d]*W[e,d] + bias[e]
// mode 0: scatter into [b,h,s,hd] layout (QKV).  mode 1: row-major [m,e].
// BM=128, BN=128, BK=8, 256 threads, 8x8 register tile, double-buffered smem.
// ---------------------------------------------------------------------------
#define GBM 128
#define GBN 128
#define GBK 8

__global__ __launch_bounds__(256, 2)
void gemm_kernel(const float* __restrict__ X, const float* __restrict__ W,
                 const float* __restrict__ bias, float* __restrict__ out, int mode)
{
    __shared__ float As[2][GBK][GBM];   // [k][m]
    __shared__ float Bs[2][GBK][GBN];   // [k][n]
    const int t  = threadIdx.x;
    const int bm = blockIdx.y * GBM;
    const int bn = blockIdx.x * GBN;

    const int lr = t >> 1;            // 0..127 : row of A / row (e) of W
    const int lk = (t & 1) * 4;       // 0 or 4 : k sub-offset
    const float* Ap = X + (size_t)(bm + lr) * Dd + lk;
    const float* Bp = W + (size_t)(bn + lr) * Dd + lk;

    float4 aR = *(const float4*)Ap;
    float4 bR = *(const float4*)Bp;
    As[0][lk+0][lr]=aR.x; As[0][lk+1][lr]=aR.y; As[0][lk+2][lr]=aR.z; As[0][lk+3][lr]=aR.w;
    Bs[0][lk+0][lr]=bR.x; Bs[0][lk+1][lr]=bR.y; Bs[0][lk+2][lr]=bR.z; Bs[0][lk+3][lr]=bR.w;
    __syncthreads();

    const int ry = t >> 4;            // 0..15 -> rows ry*8..ry*8+7
    const int cx = t & 15;            // 0..15 -> cols cx*4..+3 and 64+cx*4..+3
    float acc[8][8];
    #pragma unroll
    for (int i = 0; i < 8; i++)
        #pragma unroll
        for (int j = 0; j < 8; j++) acc[i][j] = 0.f;

    const int NT = Dd / GBK;          // 128
    for (int kt = 0; kt < NT; kt++) {
        const int cur = kt & 1;
        if (kt + 1 < NT) {
            aR = *(const float4*)(Ap + (size_t)(kt+1)*GBK);
            bR = *(const float4*)(Bp + (size_t)(kt+1)*GBK);
        }
        #pragma unroll
        for (int kk = 0; kk < GBK; kk++) {
            float a[8], b[8];
            *(float4*)(a)   = *(const float4*)&As[cur][kk][ry*8];
            *(float4*)(a+4) = *(const float4*)&As[cur][kk][ry*8+4];
            *(float4*)(b)   = *(const float4*)&Bs[cur][kk][cx*4];
            *(float4*)(b+4) = *(const float4*)&Bs[cur][kk][64 + cx*4];
            #pragma unroll
            for (int i = 0; i < 8; i++)
                #pragma unroll
                for (int j = 0; j < 8; j++)
                    acc[i][j] += a[i] * b[j];
        }
        if (kt + 1 < NT) {
            const int nxt = cur ^ 1;
            As[nxt][lk+0][lr]=aR.x; As[nxt][lk+1][lr]=aR.y; As[nxt][lk+2][lr]=aR.z; As[nxt][lk+3][lr]=aR.w;
            Bs[nxt][lk+0][lr]=bR.x; Bs[nxt][lk+1][lr]=bR.y; Bs[nxt][lk+2][lr]=bR.z; Bs[nxt][lk+3][lr]=bR.w;
            __syncthreads();
        }
    }

    // Epilogue: bias + write
    #pragma unroll
    for (int i = 0; i < 8; i++) {
        const int m = bm + ry*8 + i;
        const int b_idx = m >> 11;            // /2048
        const int s_idx = m & (Ss-1);
        #pragma unroll
        for (int half = 0; half < 2; half++) {
            const int e0 = bn + half*64 + cx*4;
            float4 r;
            r.x = acc[i][half*4+0] + bias[e0+0];
            r.y = acc[i][half*4+1] + bias[e0+1];
            r.z = acc[i][half*4+2] + bias[e0+2];
            r.w = acc[i][half*4+3] + bias[e0+3];
            if (mode == 0) {
                const int h  = e0 >> 6;
                const int d0 = e0 & 63;
                *(float4*)&out[(((size_t)b_idx*Hh + h)*Ss + s_idx)*HD + d0] = r;
            } else {
                *(float4*)&out[(size_t)m*Dd + e0] = r;
            }
        }
    }
}

// ---------------------------------------------------------------------------
// RoPE (replicating the reference's swapped sin/cos naming):
//   out[i]    = x[i]*sin(s*f_i)    - x[i+32]*cos(s*f_i)
//   out[i+32] = x[i+32]*sin(s*f_i) + x[i]*cos(s*f_i)
// Double-precision trig so fast-math cannot break range reduction (arg <= 2047).
// ---------------------------------------------------------------------------
__global__ void rope_kernel(float* __restrict__ Q, float* __restrict__ K)
{
    const size_t idx = (size_t)blockIdx.x * blockDim.x + threadIdx.x; // BH*Ss*32 total
    const int    i   = (int)(idx & 31);
    const size_t row = idx >> 5;                 // bh*Ss + s
    const int    s   = (int)(row & (Ss-1));

    const double freq = exp(-((double)(2*i) / 64.0) * 9.210340371976184); // ln(10000)
    const double arg  = (double)((float)((float)s * (float)freq));        // fp32 arg like ref
    const float  sv   = (float)sin(arg);
    const float  cv   = (float)cos(arg);

    const size_t base = row*HD + i;
    float q1 = Q[base], q2 = Q[base+32];
    Q[base]    = q1*sv - q2*cv;
    Q[base+32] = q2*sv + q1*cv;
    float k1 = K[base], k2 = K[base+32];
    K[base]    = k1*sv - k2*cv;
    K[base+32] = k2*sv + k1*cv;
}

// ---------------------------------------------------------------------------
// Flash attention, fp32 SIMT. BQ=128 queries/block, KV tile 64, 256 threads.
// Thread map 16x16: rows ty*8+i (i<8), cols tx*4+j (j<4).
// smem rows padded to 65 floats (conflict-free column reads).
// ---------------------------------------------------------------------------
#define BQ   128
#define BKT  64
#define APAD 65
#define ATTN_SMEM_FLOATS ((BQ + BKT + BKT + BQ) * APAD)   // 24960
#define ATTN_SMEM_BYTES  (ATTN_SMEM_FLOATS * 4)           // 99840

__global__ __launch_bounds__(256, 1)
void attn_kernel(const float* __restrict__ Q, const float* __restrict__ K,
                 const float* __restrict__ V, float* __restrict__ ctx)
{
    extern __shared__ float sm[];
    float* Qs = sm;                       // [BQ ][APAD]
    float* Ks = Qs + BQ*APAD;             // [BKT][APAD]
    float* Vs = Ks + BKT*APAD;            // [BKT][APAD]
    float* Ps = Vs + BKT*APAD;            // [BQ ][APAD]

    const int bh = blockIdx.y;
    const int q0 = blockIdx.x * BQ;
    const int t  = threadIdx.x;
    const int ty = t >> 4;                // 0..15
    const int tx = t & 15;                // 0..15

    // Load Q tile [128 x 64]
    const float* Qg = Q + ((size_t)bh*Ss + q0)*HD;
    for (int i = t; i < BQ*16; i += 256) {
        const int r  = i >> 4;
        const int c4 = (i & 15) * 4;
        float4 v = *(const float4*)(Qg + (size_t)r*HD + c4);
        float* d = &Qs[r*APAD + c4];
        d[0]=v.x; d[1]=v.y; d[2]=v.z; d[3]=v.w;
    }

    float m_i[8], l_i[8], O[8][4];
    #pragma unroll
    for (int i = 0; i < 8; i++) {
        m_i[i] = -1e30f; l_i[i] = 0.f;
        #pragma unroll
        for (int j = 0; j < 4; j++) O[i][j] = 0.f;
    }

    const float* Kg = K + (size_t)bh*Ss*HD;
    const float* Vg = V + (size_t)bh*Ss*HD;

    for (int kv = 0; kv < Ss; kv += BKT) {
        __syncthreads();   // prior-iter readers done before overwriting K/V/P
        for (int i = t; i < BKT*16; i += 256) {
            const int r  = i >> 4;
            const int c4 = (i & 15) * 4;
            float4 k4 = *(const float4*)(Kg + (size_t)(kv+r)*HD + c4);
            float* kd = &Ks[r*APAD + c4];
            kd[0]=k4.x; kd[1]=k4.y; kd[2]=k4.z; kd[3]=k4.w;
            float4 v4 = *(const float4*)(Vg + (size_t)(kv+r)*HD + c4);
            float* vd = &Vs[r*APAD + c4];
            vd[0]=v4.x; vd[1]=v4.y; vd[2]=v4.z; vd[3]=v4.w;
        }
        __syncthreads();

        // S = (Q K^T) * scale
        float Sreg[8][4];
        #pragma unroll
        for (int i = 0; i < 8; i++)
            #pragma unroll
            for (int j = 0; j < 4; j++) Sreg[i][j] = 0.f;

        #pragma unroll 8
        for (int k = 0; k < HD; k++) {
            float a[8], bb[4];
            #pragma unroll
            for (int i = 0; i < 8; i++) a[i]  = Qs[(ty*8+i)*APAD + k];
            #pragma unroll
            for (int j = 0; j < 4; j++) bb[j] = Ks[(tx*4+j)*APAD + k];
            #pragma unroll
            for (int i = 0; i < 8; i++)
                #pragma unroll
                for (int j = 0; j < 4; j++)
                    Sreg[i][j] += a[i] * bb[j];
        }

        // Online softmax (per row; 16 tx lanes cooperate via xor-shfl in 16-groups)
        #pragma unroll
        for (int i = 0; i < 8; i++) {
            #pragma unroll
            for (int j = 0; j < 4; j++) Sreg[i][j] *= 0.125f;   // 1/sqrt(64)
            float mx = fmaxf(fmaxf(Sreg[i][0], Sreg[i][1]), fmaxf(Sreg[i][2], Sreg[i][3]));
            #pragma unroll
            for (int off = 1; off < 16; off <<= 1)
                mx = fmaxf(mx, __shfl_xor_sync(0xffffffffu, mx, off));
            const float mn    = fmaxf(m_i[i], mx);
            const float alpha = __expf(m_i[i] - mn);
            float ps = 0.f;
            #pragma unroll
            for (int j = 0; j < 4; j++) {
                float p = __expf(Sreg[i][j] - mn);
                Sreg[i][j] = p; ps += p;
            }
            #pragma unroll
            for (int off = 1; off < 16; off <<= 1)
                ps += __shfl_xor_sync(0xffffffffu, ps, off);
            m_i[i] = mn;
            l_i[i] = l_i[i]*alpha + ps;
            #pragma unroll
            for (int j = 0; j < 4; j++) {
                O[i][j] *= alpha;
                Ps[(ty*8+i)*APAD + tx*4 + j] = Sreg[i][j];
            }
        }
        __syncthreads();

        // O += P @ V
        #pragma unroll 8
        for (int c = 0; c < BKT; c++) {
            float p[8], vv[4];
            #pragma unroll
            for (int i = 0; i < 8; i++) p[i]  = Ps[(ty*8+i)*APAD + c];
            #pragma unroll
            for (int j = 0; j < 4; j++) vv[j] = Vs[c*APAD + tx*4 + j];
            #pragma unroll
            for (int i = 0; i < 8; i++)
                #pragma unroll
                for (int j = 0; j < 4; j++)
                    O[i][j] += p[i] * vv[j];
        }
    }

    // Normalize, write ctx in [b, s, h*hd] layout
    const int b_idx = bh >> 4;
    const int h     = bh & 15;
    #pragma unroll
    for (int i = 0; i < 8; i++) {
        const int s_idx = q0 + ty*8 + i;
        const float inv = 1.f / l_i[i];
        float4 r;
        r.x = O[i][0]*inv; r.y = O[i][1]*inv; r.z = O[i][2]*inv; r.w = O[i][3]*inv;
        *(float4*)&ctx[((size_t)b_idx*Ss + s_idx)*Dd + h*HD + tx*4] = r;
    }
}

// ---------------------------------------------------------------------------
extern "C" void kernel_launch(void* const* d_in, const int* in_sizes, int n_in,
                              void* d_out, int out_size)
{
    (void)in_sizes; (void)n_in; (void)out_size;
    const float* X  = (const float*)d_in[0];
    const float* Wq = (const float*)d_in[1];
    const float* bq = (const float*)d_in[2];
    const float* Wk = (const float*)d_in[3];
    const float* bk = (const float*)d_in[4];
    const float* Wv = (const float*)d_in[5];
    const float* bv = (const float*)d_in[6];
    const float* Wo = (const float*)d_in[7];
    const float* bo = (const float*)d_in[8];
    float* out = (float*)d_out;

    void *pQ, *pK, *pV, *pC;
    cudaGetSymbolAddress(&pQ, g_Q);
    cudaGetSymbolAddress(&pK, g_K);
    cudaGetSymbolAddress(&pV, g_V);
    cudaGetSymbolAddress(&pC, g_ctx);

    cudaFuncSetAttribute(attn_kernel, cudaFuncAttributeMaxDynamicSharedMemorySize,
                         ATTN_SMEM_BYTES);

    dim3 gg(Dd/GBN, MM/GBM);   // (8, 64)
    gemm_kernel<<<gg, 256>>>(X, Wq, bq, (float*)pQ, 0);
    gemm_kernel<<<gg, 256>>>(X, Wk, bk, (float*)pK, 0);
    gemm_kernel<<<gg, 256>>>(X, Wv, bv, (float*)pV, 0);

    rope_kernel<<<(BH*Ss*32)/256, 256>>>((float*)pQ, (float*)pK);

    attn_kernel<<<dim3(Ss/BQ, BH), 256, ATTN_SMEM_BYTES>>>(
        (const float*)pQ, (const float*)pK, (const float*)pV, (float*)pC);

    gemm_kernel<<<gg, 256>>>((const float*)pC, Wo, bo, out, 1);
}

// round 3
// speedup vs baseline: 1.6658x; 1.6658x over previous
#include <cuda_runtime.h>
#include <cuda_bf16.h>
#include <math.h>
#include <stdint.h>

// Problem constants
#define Bb  4
#define Ss  2048
#define Dd  1024
#define Hh  16
#define HD  64
#define BH  (Bb*Hh)     // 64
#define MM  (Bb*Ss)     // 8192

// Scratch (device globals -> no allocation)
__device__ float g_Q[(size_t)BH*Ss*HD];     // [b,h,s,hd]
__device__ float g_K[(size_t)BH*Ss*HD];
__device__ float g_V[(size_t)BH*Ss*HD];
__device__ float g_ctx[(size_t)MM*Dd];      // [b,s,h*hd]
__device__ float g_sin[Ss*32];
__device__ float g_cos[Ss*32];

__device__ __forceinline__ uint32_t smem_u32(const void* p) {
    uint32_t a;
    asm("{ .reg .u64 t; cvta.to.shared.u64 t, %1; cvt.u32.u64 %0, t; }" : "=r"(a) : "l"(p));
    return a;
}

__device__ __forceinline__ void ldsm4(uint32_t (&r)[4], uint32_t addr) {
    asm volatile("ldmatrix.sync.aligned.m8n8.x4.shared.b16 {%0,%1,%2,%3}, [%4];"
        : "=r"(r[0]), "=r"(r[1]), "=r"(r[2]), "=r"(r[3]) : "r"(addr));
}

__device__ __forceinline__ void mma16816(float (&d)[4], const uint32_t (&a)[4],
                                         uint32_t b0, uint32_t b1) {
    asm volatile("mma.sync.aligned.m16n8k16.row.col.f32.bf16.bf16.f32 "
        "{%0,%1,%2,%3}, {%4,%5,%6,%7}, {%8,%9}, {%0,%1,%2,%3};"
        : "+f"(d[0]), "+f"(d[1]), "+f"(d[2]), "+f"(d[3])
        : "r"(a[0]), "r"(a[1]), "r"(a[2]), "r"(a[3]), "r"(b0), "r"(b1));
}

// ============================================================================
// mma.sync bf16x3 GEMM: Y[m,e] = sum_d X[m,d]*W[e,d] + bias[e]
// Tile 128x128x32, 8 warps (warp tile 32m x 64n), double-buffered smem.
// mode 0: scatter into [b,h,s,hd] (QKV).  mode 1: row-major [m,e].
// ============================================================================
#define LDA 40                         // bf16 per smem row (32 + 8 pad) = 80B stride
#define TILE_B (128*LDA*2)             // 10240 B per matrix
#define STAGE_B (4*TILE_B)             // Ah, Al, Bh, Bl
#define GEMM_SMEM (2*STAGE_B)          // 81920

__global__ __launch_bounds__(256, 1)
void gemm_mma(const float* __restrict__ X, const float* __restrict__ W,
              const float* __restrict__ bias, float* __restrict__ out, int mode)
{
    extern __shared__ char smc[];
    const uint32_t sb = smem_u32(smc);
    const int t    = threadIdx.x;
    const int lane = t & 31;
    const int warp = t >> 5;
    const int wm   = warp >> 1;            // 0..3
    const int wn   = warp & 1;             // 0..1
    const int bn   = blockIdx.x * 128;
    const int bm   = blockIdx.y * 128;

    float acc[2][8][4];
    #pragma unroll
    for (int mt = 0; mt < 2; mt++)
        #pragma unroll
        for (int nt = 0; nt < 8; nt++)
            #pragma unroll
            for (int j = 0; j < 4; j++) acc[mt][nt][j] = 0.f;

    // loader mapping: 1024 float4 slots over 256 threads
    const int lrow[4] = { (t+0)>>3, (t+256)>>3, (t+512)>>3, (t+768)>>3 };
    const int lc4     = (t & 7) * 4;

    float4 pa[4], pb[4];
    #pragma unroll
    for (int i = 0; i < 4; i++) {
        pa[i] = *(const float4*)(X + (size_t)(bm + lrow[i]) * Dd + lc4);
        pb[i] = *(const float4*)(W + (size_t)(bn + lrow[i]) * Dd + lc4);
    }

    auto store_stage = [&](int s, const float4* va, const float4* vb) {
        const uint32_t base = sb + (uint32_t)s * STAGE_B;
        #pragma unroll
        for (int i = 0; i < 4; i++) {
            const uint32_t off = (uint32_t)(lrow[i] * LDA + lc4) * 2;
            float f[4] = { va[i].x, va[i].y, va[i].z, va[i].w };
            uint32_t h[2], l[2];
            #pragma unroll
            for (int p = 0; p < 2; p++) {
                __nv_bfloat16 h0 = __float2bfloat16_rn(f[2*p]);
                __nv_bfloat16 h1 = __float2bfloat16_rn(f[2*p+1]);
                __nv_bfloat16 l0 = __float2bfloat16_rn(f[2*p]   - __bfloat162float(h0));
                __nv_bfloat16 l1 = __float2bfloat16_rn(f[2*p+1] - __bfloat162float(h1));
                __nv_bfloat162 hh; hh.x = h0; hh.y = h1;
                __nv_bfloat162 ll; ll.x = l0; ll.y = l1;
                h[p] = *(uint32_t*)&hh; l[p] = *(uint32_t*)&ll;
            }
            asm volatile("st.shared.v2.b32 [%0], {%1,%2};" :: "r"(base + off),           "r"(h[0]), "r"(h[1]));
            asm volatile("st.shared.v2.b32 [%0], {%1,%2};" :: "r"(base + TILE_B + off),  "r"(l[0]), "r"(l[1]));
            float g[4] = { vb[i].x, vb[i].y, vb[i].z, vb[i].w };
            #pragma unroll
            for (int p = 0; p < 2; p++) {
                __nv_bfloat16 h0 = __float2bfloat16_rn(g[2*p]);
                __nv_bfloat16 h1 = __float2bfloat16_rn(g[2*p+1]);
                __nv_bfloat16 l0 = __float2bfloat16_rn(g[2*p]   - __bfloat162float(h0));
                __nv_bfloat16 l1 = __float2bfloat16_rn(g[2*p+1] - __bfloat162float(h1));
                __nv_bfloat162 hh; hh.x = h0; hh.y = h1;
                __nv_bfloat162 ll; ll.x = l0; ll.y = l1;
                h[p] = *(uint32_t*)&hh; l[p] = *(uint32_t*)&ll;
            }
            asm volatile("st.shared.v2.b32 [%0], {%1,%2};" :: "r"(base + 2*TILE_B + off), "r"(h[0]), "r"(h[1]));
            asm volatile("st.shared.v2.b32 [%0], {%1,%2};" :: "r"(base + 3*TILE_B + off), "r"(h[0] ? l[0] : l[0]), "r"(l[1]));
        }
    };

    store_stage(0, pa, pb);
    __syncthreads();

    // frag smem addresses (lane-dependent parts)
    const int g8 = lane >> 3;
    const int l8 = lane & 7;
    // A matrices: (m, k0), (m+8, k0), (m, k8), (m+8, k8)
    const int aRow = (g8 & 1) * 8 + l8;
    const int aCol = (g8 >> 1) * 8;
    // B matrices: (n, k0), (n, k8), (n+8, k0), (n+8, k8)
    const int bRow = (g8 >> 1) * 8 + l8;
    const int bCol = (g8 & 1) * 8;

    const int NT = Dd / 32;   // 32
    for (int kt = 0; kt < NT; kt++) {
        const int s = kt & 1;
        const int last = (kt + 1 == NT);
        if (!last) {
            const int kc = (kt + 1) * 32;
            #pragma unroll
            for (int i = 0; i < 4; i++) {
                pa[i] = *(const float4*)(X + (size_t)(bm + lrow[i]) * Dd + kc + lc4);
                pb[i] = *(const float4*)(W + (size_t)(bn + lrow[i]) * Dd + kc + lc4);
            }
        }

        const uint32_t Ah = sb + (uint32_t)s * STAGE_B;
        const uint32_t Al = Ah + TILE_B;
        const uint32_t Bh = Ah + 2*TILE_B;
        const uint32_t Bl = Ah + 3*TILE_B;

        #pragma unroll
        for (int ks = 0; ks < 2; ks++) {
            const int k0 = ks * 16;
            uint32_t aF[2][4], bF[4][4];
            // --- product 1: Ah * Bh ---
            #pragma unroll
            for (int mt = 0; mt < 2; mt++)
                ldsm4(aF[mt], Ah + (uint32_t)((wm*32 + mt*16 + aRow) * LDA + k0 + aCol) * 2);
            #pragma unroll
            for (int q = 0; q < 4; q++)
                ldsm4(bF[q], Bh + (uint32_t)((wn*64 + q*16 + bRow) * LDA + k0 + bCol) * 2);
            #pragma unroll
            for (int mt = 0; mt < 2; mt++)
                #pragma unroll
                for (int q = 0; q < 4; q++) {
                    mma16816(acc[mt][q*2+0], aF[mt], bF[q][0], bF[q][1]);
                    mma16816(acc[mt][q*2+1], aF[mt], bF[q][2], bF[q][3]);
                }
            // --- product 2: Al * Bh ---
            #pragma unroll
            for (int mt = 0; mt < 2; mt++)
                ldsm4(aF[mt], Al + (uint32_t)((wm*32 + mt*16 + aRow) * LDA + k0 + aCol) * 2);
            #pragma unroll
            for (int mt = 0; mt < 2; mt++)
                #pragma unroll
                for (int q = 0; q < 4; q++) {
                    mma16816(acc[mt][q*2+0], aF[mt], bF[q][0], bF[q][1]);
                    mma16816(acc[mt][q*2+1], aF[mt], bF[q][2], bF[q][3]);
                }
            // --- product 3: Ah * Bl ---
            #pragma unroll
            for (int mt = 0; mt < 2; mt++)
                ldsm4(aF[mt], Ah + (uint32_t)((wm*32 + mt*16 + aRow) * LDA + k0 + aCol) * 2);
            #pragma unroll
            for (int q = 0; q < 4; q++)
                ldsm4(bF[q], Bl + (uint32_t)((wn*64 + q*16 + bRow) * LDA + k0 + bCol) * 2);
            #pragma unroll
            for (int mt = 0; mt < 2; mt++)
                #pragma unroll
                for (int q = 0; q < 4; q++) {
                    mma16816(acc[mt][q*2+0], aF[mt], bF[q][0], bF[q][1]);
                    mma16816(acc[mt][q*2+1], aF[mt], bF[q][2], bF[q][3]);
                }
        }

        if (!last) {
            __syncthreads();          // all warps done reading stage s^1 (2 iters ago)
            store_stage(s ^ 1, pa, pb);
            __syncthreads();
        }
    }

    // Epilogue: bias + store fp32
    #pragma unroll
    for (int mt = 0; mt < 2; mt++) {
        #pragma unroll
        for (int half = 0; half < 2; half++) {
            const int m  = bm + wm*32 + mt*16 + (lane >> 2) + half*8;
            const int bi = m >> 11;
            const int si = m & (Ss - 1);
            #pragma unroll
            for (int nt = 0; nt < 8; nt++) {
                const int eloc = wn*64 + nt*8 + (lane & 3)*2;
                const int e0   = bn + eloc;
                float2 r;
                r.x = acc[mt][nt][half*2+0] + bias[e0];
                r.y = acc[mt][nt][half*2+1] + bias[e0+1];
                if (mode == 0) {
                    const int h  = e0 >> 6;
                    const int d0 = e0 & 63;
                    *(float2*)&out[(((size_t)bi*Hh + h)*Ss + si)*HD + d0] = r;
                } else {
                    *(float2*)&out[(size_t)m*Dd + e0] = r;
                }
            }
        }
    }
}

// ============================================================================
// RoPE: table build (DP trig once) + fp32 apply (reference's swapped naming):
//   out[i]    = x[i]*sin - x[i+32]*cos
//   out[i+32] = x[i+32]*sin + x[i]*cos
// ============================================================================
__global__ void rope_table()
{
    const int tid = blockIdx.x * blockDim.x + threadIdx.x;
    if (tid >= Ss * 32) return;
    const int s = tid >> 5;
    const int i = tid & 31;
    const double freq = exp(-((double)(2 * i) / 64.0) * 9.210340371976184); // ln(10000)
    const float  argf = (float)s * (float)freq;
    const double a    = (double)argf;
    g_sin[tid] = (float)sin(a);
    g_cos[tid] = (float)cos(a);
}

__global__ void rope_apply(float* __restrict__ Q, float* __restrict__ K)
{
    const int idx = blockIdx.x * blockDim.x + threadIdx.x;   // BH*Ss*8
    const int c   = idx & 7;
    const int row = idx >> 3;
    const int s   = row & (Ss - 1);
    const size_t b0 = (size_t)row * HD + c * 4;

    const float4 sv = *(const float4*)&g_sin[s * 32 + c * 4];
    const float4 cv = *(const float4*)&g_cos[s * 32 + c * 4];

    float4 q1 = *(float4*)&Q[b0], q2 = *(float4*)&Q[b0 + 32];
    float4 o1, o2;
    o1.x = q1.x*sv.x - q2.x*cv.x;  o2.x = q2.x*sv.x + q1.x*cv.x;
    o1.y = q1.y*sv.y - q2.y*cv.y;  o2.y = q2.y*sv.y + q1.y*cv.y;
    o1.z = q1.z*sv.z - q2.z*cv.z;  o2.z = q2.z*sv.z + q1.z*cv.z;
    o1.w = q1.w*sv.w - q2.w*cv.w;  o2.w = q2.w*sv.w + q1.w*cv.w;
    *(float4*)&Q[b0] = o1; *(float4*)&Q[b0 + 32] = o2;

    float4 k1 = *(float4*)&K[b0], k2 = *(float4*)&K[b0 + 32];
    o1.x = k1.x*sv.x - k2.x*cv.x;  o2.x = k2.x*sv.x + k1.x*cv.x;
    o1.y = k1.y*sv.y - k2.y*cv.y;  o2.y = k2.y*sv.y + k1.y*cv.y;
    o1.z = k1.z*sv.z - k2.z*cv.z;  o2.z = k2.z*sv.z + k1.z*cv.z;
    o1.w = k1.w*sv.w - k2.w*cv.w;  o2.w = k2.w*sv.w + k1.w*cv.w;
    *(float4*)&K[b0] = o1; *(float4*)&K[b0 + 32] = o2;
}

// ---------------------------------------------------------------------------
// Flash attention, fp32 SIMT, occupancy 2
// ---------------------------------------------------------------------------
#define BQ   128
#define BKT  64
#define APAD 65
#define ATTN_SMEM_BYTES (((BQ + BKT + BKT + BQ) * APAD) * 4)   // 99840

__global__ __launch_bounds__(256, 2)
void attn_kernel(const float* __restrict__ Q, const float* __restrict__ K,
                 const float* __restrict__ V, float* __restrict__ ctx)
{
    extern __shared__ float smf[];
    float* Qs = smf;
    float* Ks = Qs + BQ*APAD;
    float* Vs = Ks + BKT*APAD;
    float* Ps = Vs + BKT*APAD;

    const int bh = blockIdx.y;
    const int q0 = blockIdx.x * BQ;
    const int t  = threadIdx.x;
    const int ty = t >> 4;
    const int tx = t & 15;

    const float* Qg = Q + ((size_t)bh*Ss + q0)*HD;
    for (int i = t; i < BQ*16; i += 256) {
        const int r  = i >> 4;
        const int c4 = (i & 15) * 4;
        float4 v = *(const float4*)(Qg + (size_t)r*HD + c4);
        float* d = &Qs[r*APAD + c4];
        d[0]=v.x; d[1]=v.y; d[2]=v.z; d[3]=v.w;
    }

    float m_i[8], l_i[8], O[8][4];
    #pragma unroll
    for (int i = 0; i < 8; i++) {
        m_i[i] = -1e30f; l_i[i] = 0.f;
        #pragma unroll
        for (int j = 0; j < 4; j++) O[i][j] = 0.f;
    }

    const float* Kg = K + (size_t)bh*Ss*HD;
    const float* Vg = V + (size_t)bh*Ss*HD;

    for (int kv = 0; kv < Ss; kv += BKT) {
        __syncthreads();
        for (int i = t; i < BKT*16; i += 256) {
            const int r  = i >> 4;
            const int c4 = (i & 15) * 4;
            float4 k4 = *(const float4*)(Kg + (size_t)(kv+r)*HD + c4);
            float* kd = &Ks[r*APAD + c4];
            kd[0]=k4.x; kd[1]=k4.y; kd[2]=k4.z; kd[3]=k4.w;
            float4 v4 = *(const float4*)(Vg + (size_t)(kv+r)*HD + c4);
            float* vd = &Vs[r*APAD + c4];
            vd[0]=v4.x; vd[1]=v4.y; vd[2]=v4.z; vd[3]=v4.w;
        }
        __syncthreads();

        float Sreg[8][4];
        #pragma unroll
        for (int i = 0; i < 8; i++)
            #pragma unroll
            for (int j = 0; j < 4; j++) Sreg[i][j] = 0.f;

        #pragma unroll 8
        for (int k = 0; k < HD; k++) {
            float a[8], bb[4];
            #pragma unroll
            for (int i = 0; i < 8; i++) a[i]  = Qs[(ty*8+i)*APAD + k];
            #pragma unroll
            for (int j = 0; j < 4; j++) bb[j] = Ks[(tx*4+j)*APAD + k];
            #pragma unroll
            for (int i = 0; i < 8; i++)
                #pragma unroll
                for (int j = 0; j < 4; j++)
                    Sreg[i][j] += a[i] * bb[j];
        }

        #pragma unroll
        for (int i = 0; i < 8; i++) {
            #pragma unroll
            for (int j = 0; j < 4; j++) Sreg[i][j] *= 0.125f;
            float mx = fmaxf(fmaxf(Sreg[i][0], Sreg[i][1]), fmaxf(Sreg[i][2], Sreg[i][3]));
            #pragma unroll
            for (int off = 1; off < 16; off <<= 1)
                mx = fmaxf(mx, __shfl_xor_sync(0xffffffffu, mx, off));
            const float mn    = fmaxf(m_i[i], mx);
            const float alpha = __expf(m_i[i] - mn);
            float ps = 0.f;
            #pragma unroll
            for (int j = 0; j < 4; j++) {
                float p = __expf(Sreg[i][j] - mn);
                Sreg[i][j] = p; ps += p;
            }
            #pragma unroll
            for (int off = 1; off < 16; off <<= 1)
                ps += __shfl_xor_sync(0xffffffffu, ps, off);
            m_i[i] = mn;
            l_i[i] = l_i[i]*alpha + ps;
            #pragma unroll
            for (int j = 0; j < 4; j++) {
                O[i][j] *= alpha;
                Ps[(ty*8+i)*APAD + tx*4 + j] = Sreg[i][j];
            }
        }
        __syncthreads();

        #pragma unroll 8
        for (int c = 0; c < BKT; c++) {
            float p[8], vv[4];
            #pragma unroll
            for (int i = 0; i < 8; i++) p[i]  = Ps[(ty*8+i)*APAD + c];
            #pragma unroll
            for (int j = 0; j < 4; j++) vv[j] = Vs[c*APAD + tx*4 + j];
            #pragma unroll
            for (int i = 0; i < 8; i++)
                #pragma unroll
                for (int j = 0; j < 4; j++)
                    O[i][j] += p[i] * vv[j];
        }
    }

    const int b_idx = bh >> 4;
    const int h     = bh & 15;
    #pragma unroll
    for (int i = 0; i < 8; i++) {
        const int s_idx = q0 + ty*8 + i;
        const float inv = 1.f / l_i[i];
        float4 r;
        r.x = O[i][0]*inv; r.y = O[i][1]*inv; r.z = O[i][2]*inv; r.w = O[i][3]*inv;
        *(float4*)&ctx[((size_t)b_idx*Ss + s_idx)*Dd + h*HD + tx*4] = r;
    }
}

// ---------------------------------------------------------------------------
extern "C" void kernel_launch(void* const* d_in, const int* in_sizes, int n_in,
                              void* d_out, int out_size)
{
    (void)in_sizes; (void)n_in; (void)out_size;
    const float* X  = (const float*)d_in[0];
    const float* Wq = (const float*)d_in[1];
    const float* bq = (const float*)d_in[2];
    const float* Wk = (const float*)d_in[3];
    const float* bk = (const float*)d_in[4];
    const float* Wv = (const float*)d_in[5];
    const float* bv = (const float*)d_in[6];
    const float* Wo = (const float*)d_in[7];
    const float* bo = (const float*)d_in[8];
    float* out = (float*)d_out;

    void *pQ, *pK, *pV, *pC;
    cudaGetSymbolAddress(&pQ, g_Q);
    cudaGetSymbolAddress(&pK, g_K);
    cudaGetSymbolAddress(&pV, g_V);
    cudaGetSymbolAddress(&pC, g_ctx);

    cudaFuncSetAttribute(gemm_mma, cudaFuncAttributeMaxDynamicSharedMemorySize,
                         GEMM_SMEM);
    cudaFuncSetAttribute(attn_kernel, cudaFuncAttributeMaxDynamicSharedMemorySize,
                         ATTN_SMEM_BYTES);

    rope_table<<<(Ss*32)/256, 256>>>();

    dim3 gg(Dd/128, MM/128);   // (8, 64)
    gemm_mma<<<gg, 256, GEMM_SMEM>>>(X, Wq, bq, (float*)pQ, 0);
    gemm_mma<<<gg, 256, GEMM_SMEM>>>(X, Wk, bk, (float*)pK, 0);
    gemm_mma<<<gg, 256, GEMM_SMEM>>>(X, Wv, bv, (float*)pV, 0);

    rope_apply<<<(BH*Ss*8)/256, 256>>>((float*)pQ, (float*)pK);

    attn_kernel<<<dim3(Ss/BQ, BH), 256, ATTN_SMEM_BYTES>>>(
        (const float*)pQ, (const float*)pK, (const float*)pV, (float*)pC);

    gemm_mma<<<gg, 256, GEMM_SMEM>>>((const float*)pC, Wo, bo, out, 1);
}

// round 4
// speedup vs baseline: 2.6006x; 1.5611x over previous
#include <cuda_runtime.h>
#include <cuda_bf16.h>
#include <math.h>
#include <stdint.h>

// Problem constants
#define Bb  4
#define Ss  2048
#define Dd  1024
#define Hh  16
#define HD  64
#define BH  (Bb*Hh)     // 64
#define MM  (Bb*Ss)     // 8192

// Scratch (device globals -> no allocation)
__device__ float g_Q[(size_t)BH*Ss*HD];     // [b,h,s,hd]
__device__ float g_K[(size_t)BH*Ss*HD];
__device__ float g_V[(size_t)BH*Ss*HD];
__device__ float g_ctx[(size_t)MM*Dd];      // [b,s,h*hd]
__device__ float g_sin[Ss*32];
__device__ float g_cos[Ss*32];

__device__ __forceinline__ uint32_t smem_u32(const void* p) {
    uint32_t a;
    asm("{ .reg .u64 t; cvta.to.shared.u64 t, %1; cvt.u32.u64 %0, t; }" : "=r"(a) : "l"(p));
    return a;
}

__device__ __forceinline__ void ldsm4(uint32_t (&r)[4], uint32_t addr) {
    asm volatile("ldmatrix.sync.aligned.m8n8.x4.shared.b16 {%0,%1,%2,%3}, [%4];"
        : "=r"(r[0]), "=r"(r[1]), "=r"(r[2]), "=r"(r[3]) : "r"(addr));
}

__device__ __forceinline__ void mma16816(float (&d)[4], const uint32_t (&a)[4],
                                         uint32_t b0, uint32_t b1) {
    asm volatile("mma.sync.aligned.m16n8k16.row.col.f32.bf16.bf16.f32 "
        "{%0,%1,%2,%3}, {%4,%5,%6,%7}, {%8,%9}, {%0,%1,%2,%3};"
        : "+f"(d[0]), "+f"(d[1]), "+f"(d[2]), "+f"(d[3])
        : "r"(a[0]), "r"(a[1]), "r"(a[2]), "r"(a[3]), "r"(b0), "r"(b1));
}

__device__ __forceinline__ uint32_t pack_hi(float x, float y) {
    __nv_bfloat162 h; h.x = __float2bfloat16_rn(x); h.y = __float2bfloat16_rn(y);
    return *(uint32_t*)&h;
}
__device__ __forceinline__ uint32_t pack_lo(float x, float y) {
    __nv_bfloat16 hx = __float2bfloat16_rn(x), hy = __float2bfloat16_rn(y);
    __nv_bfloat162 l;
    l.x = __float2bfloat16_rn(x - __bfloat162float(hx));
    l.y = __float2bfloat16_rn(y - __bfloat162float(hy));
    return *(uint32_t*)&l;
}

// ============================================================================
// mma.sync bf16x3 GEMM (unchanged from R3): Y = X W^T + b
// ============================================================================
#define LDA 40
#define TILE_B (128*LDA*2)
#define STAGE_B (4*TILE_B)
#define GEMM_SMEM (2*STAGE_B)

__global__ __launch_bounds__(256, 1)
void gemm_mma(const float* __restrict__ X, const float* __restrict__ W,
              const float* __restrict__ bias, float* __restrict__ out, int mode)
{
    extern __shared__ char smc[];
    const uint32_t sb = smem_u32(smc);
    const int t    = threadIdx.x;
    const int lane = t & 31;
    const int warp = t >> 5;
    const int wm   = warp >> 1;
    const int wn   = warp & 1;
    const int bn   = blockIdx.x * 128;
    const int bm   = blockIdx.y * 128;

    float acc[2][8][4];
    #pragma unroll
    for (int mt = 0; mt < 2; mt++)
        #pragma unroll
        for (int nt = 0; nt < 8; nt++)
            #pragma unroll
            for (int j = 0; j < 4; j++) acc[mt][nt][j] = 0.f;

    const int lrow[4] = { (t+0)>>3, (t+256)>>3, (t+512)>>3, (t+768)>>3 };
    const int lc4     = (t & 7) * 4;

    float4 pa[4], pb[4];
    #pragma unroll
    for (int i = 0; i < 4; i++) {
        pa[i] = *(const float4*)(X + (size_t)(bm + lrow[i]) * Dd + lc4);
        pb[i] = *(const float4*)(W + (size_t)(bn + lrow[i]) * Dd + lc4);
    }

    auto store_stage = [&](int s, const float4* va, const float4* vb) {
        const uint32_t base = sb + (uint32_t)s * STAGE_B;
        #pragma unroll
        for (int i = 0; i < 4; i++) {
            const uint32_t off = (uint32_t)(lrow[i] * LDA + lc4) * 2;
            uint32_t h0 = pack_hi(va[i].x, va[i].y), h1 = pack_hi(va[i].z, va[i].w);
            uint32_t l0 = pack_lo(va[i].x, va[i].y), l1 = pack_lo(va[i].z, va[i].w);
            asm volatile("st.shared.v2.b32 [%0], {%1,%2};" :: "r"(base + off),          "r"(h0), "r"(h1));
            asm volatile("st.shared.v2.b32 [%0], {%1,%2};" :: "r"(base + TILE_B + off), "r"(l0), "r"(l1));
            h0 = pack_hi(vb[i].x, vb[i].y); h1 = pack_hi(vb[i].z, vb[i].w);
            l0 = pack_lo(vb[i].x, vb[i].y); l1 = pack_lo(vb[i].z, vb[i].w);
            asm volatile("st.shared.v2.b32 [%0], {%1,%2};" :: "r"(base + 2*TILE_B + off), "r"(h0), "r"(h1));
            asm volatile("st.shared.v2.b32 [%0], {%1,%2};" :: "r"(base + 3*TILE_B + off), "r"(l0), "r"(l1));
        }
    };

    store_stage(0, pa, pb);
    __syncthreads();

    const int g8 = lane >> 3;
    const int l8 = lane & 7;
    const int aRow = (g8 & 1) * 8 + l8;
    const int aCol = (g8 >> 1) * 8;
    const int bRow = (g8 >> 1) * 8 + l8;
    const int bCol = (g8 & 1) * 8;

    const int NT = Dd / 32;
    for (int kt = 0; kt < NT; kt++) {
        const int s = kt & 1;
        const int last = (kt + 1 == NT);
        if (!last) {
            const int kc = (kt + 1) * 32;
            #pragma unroll
            for (int i = 0; i < 4; i++) {
                pa[i] = *(const float4*)(X + (size_t)(bm + lrow[i]) * Dd + kc + lc4);
                pb[i] = *(const float4*)(W + (size_t)(bn + lrow[i]) * Dd + kc + lc4);
            }
        }

        const uint32_t Ah = sb + (uint32_t)s * STAGE_B;
        const uint32_t Al = Ah + TILE_B;
        const uint32_t Bh = Ah + 2*TILE_B;
        const uint32_t Bl = Ah + 3*TILE_B;

        #pragma unroll
        for (int ks = 0; ks < 2; ks++) {
            const int k0 = ks * 16;
            uint32_t aF[2][4], bF[4][4];
            #pragma unroll
            for (int mt = 0; mt < 2; mt++)
                ldsm4(aF[mt], Ah + (uint32_t)((wm*32 + mt*16 + aRow) * LDA + k0 + aCol) * 2);
            #pragma unroll
            for (int q = 0; q < 4; q++)
                ldsm4(bF[q], Bh + (uint32_t)((wn*64 + q*16 + bRow) * LDA + k0 + bCol) * 2);
            #pragma unroll
            for (int mt = 0; mt < 2; mt++)
                #pragma unroll
                for (int q = 0; q < 4; q++) {
                    mma16816(acc[mt][q*2+0], aF[mt], bF[q][0], bF[q][1]);
                    mma16816(acc[mt][q*2+1], aF[mt], bF[q][2], bF[q][3]);
                }
            #pragma unroll
            for (int mt = 0; mt < 2; mt++)
                ldsm4(aF[mt], Al + (uint32_t)((wm*32 + mt*16 + aRow) * LDA + k0 + aCol) * 2);
            #pragma unroll
            for (int mt = 0; mt < 2; mt++)
                #pragma unroll
                for (int q = 0; q < 4; q++) {
                    mma16816(acc[mt][q*2+0], aF[mt], bF[q][0], bF[q][1]);
                    mma16816(acc[mt][q*2+1], aF[mt], bF[q][2], bF[q][3]);
                }
            #pragma unroll
            for (int mt = 0; mt < 2; mt++)
                ldsm4(aF[mt], Ah + (uint32_t)((wm*32 + mt*16 + aRow) * LDA + k0 + aCol) * 2);
            #pragma unroll
            for (int q = 0; q < 4; q++)
                ldsm4(bF[q], Bl + (uint32_t)((wn*64 + q*16 + bRow) * LDA + k0 + bCol) * 2);
            #pragma unroll
            for (int mt = 0; mt < 2; mt++)
                #pragma unroll
                for (int q = 0; q < 4; q++) {
                    mma16816(acc[mt][q*2+0], aF[mt], bF[q][0], bF[q][1]);
                    mma16816(acc[mt][q*2+1], aF[mt], bF[q][2], bF[q][3]);
                }
        }

        if (!last) {
            __syncthreads();
            store_stage(s ^ 1, pa, pb);
            __syncthreads();
        }
    }

    #pragma unroll
    for (int mt = 0; mt < 2; mt++) {
        #pragma unroll
        for (int half = 0; half < 2; half++) {
            const int m  = bm + wm*32 + mt*16 + (lane >> 2) + half*8;
            const int bi = m >> 11;
            const int si = m & (Ss - 1);
            #pragma unroll
            for (int nt = 0; nt < 8; nt++) {
                const int eloc = wn*64 + nt*8 + (lane & 3)*2;
                const int e0   = bn + eloc;
                float2 r;
                r.x = acc[mt][nt][half*2+0] + bias[e0];
                r.y = acc[mt][nt][half*2+1] + bias[e0+1];
                if (mode == 0) {
                    const int h  = e0 >> 6;
                    const int d0 = e0 & 63;
                    *(float2*)&out[(((size_t)bi*Hh + h)*Ss + si)*HD + d0] = r;
                } else {
                    *(float2*)&out[(size_t)m*Dd + e0] = r;
                }
            }
        }
    }
}

// ============================================================================
// RoPE (table + apply)
// ============================================================================
__global__ void rope_table()
{
    const int tid = blockIdx.x * blockDim.x + threadIdx.x;
    if (tid >= Ss * 32) return;
    const int s = tid >> 5;
    const int i = tid & 31;
    const double freq = exp(-((double)(2 * i) / 64.0) * 9.210340371976184);
    const float  argf = (float)s * (float)freq;
    const double a    = (double)argf;
    g_sin[tid] = (float)sin(a);
    g_cos[tid] = (float)cos(a);
}

__global__ void rope_apply(float* __restrict__ Q, float* __restrict__ K)
{
    const int idx = blockIdx.x * blockDim.x + threadIdx.x;
    const int c   = idx & 7;
    const int row = idx >> 3;
    const int s   = row & (Ss - 1);
    const size_t b0 = (size_t)row * HD + c * 4;

    const float4 sv = *(const float4*)&g_sin[s * 32 + c * 4];
    const float4 cv = *(const float4*)&g_cos[s * 32 + c * 4];

    float4 q1 = *(float4*)&Q[b0], q2 = *(float4*)&Q[b0 + 32];
    float4 o1, o2;
    o1.x = q1.x*sv.x - q2.x*cv.x;  o2.x = q2.x*sv.x + q1.x*cv.x;
    o1.y = q1.y*sv.y - q2.y*cv.y;  o2.y = q2.y*sv.y + q1.y*cv.y;
    o1.z = q1.z*sv.z - q2.z*cv.z;  o2.z = q2.z*sv.z + q1.z*cv.z;
    o1.w = q1.w*sv.w - q2.w*cv.w;  o2.w = q2.w*sv.w + q1.w*cv.w;
    *(float4*)&Q[b0] = o1; *(float4*)&Q[b0 + 32] = o2;

    float4 k1 = *(float4*)&K[b0], k2 = *(float4*)&K[b0 + 32];
    o1.x = k1.x*sv.x - k2.x*cv.x;  o2.x = k2.x*sv.x + k1.x*cv.x;
    o1.y = k1.y*sv.y - k2.y*cv.y;  o2.y = k2.y*sv.y + k1.y*cv.y;
    o1.z = k1.z*sv.z - k2.z*cv.z;  o2.z = k2.z*sv.z + k1.z*cv.z;
    o1.w = k1.w*sv.w - k2.w*cv.w;  o2.w = k2.w*sv.w + k1.w*cv.w;
    *(float4*)&K[b0] = o1; *(float4*)&K[b0 + 32] = o2;
}

// ============================================================================
// Flash attention via mma.sync bf16x3 split (FA-2 register P trick)
// 8 warps, BQ=128 (16 q-rows/warp), KV tile 64.
// smem: Qh,Ql [128][72] ; Kh,Kl [64][72] ; VhT,VlT [64(hd)][72(key)]
// ============================================================================
#define ALD 72
#define AQ_B (128*ALD*2)       // 18432
#define AK_B (64*ALD*2)        // 9216
#define ATTN_SMEM (2*AQ_B + 4*AK_B)   // 73728

__global__ __launch_bounds__(256, 1)
void attn_mma(const float* __restrict__ Q, const float* __restrict__ K,
              const float* __restrict__ V, float* __restrict__ ctx)
{
    extern __shared__ char smc[];
    const uint32_t sb = smem_u32(smc);
    const uint32_t Qh = sb;
    const uint32_t Ql = Qh + AQ_B;
    const uint32_t Kh = Ql + AQ_B;
    const uint32_t Kl = Kh + AK_B;
    const uint32_t Vh = Kl + AK_B;
    const uint32_t Vl = Vh + AK_B;

    const int t    = threadIdx.x;
    const int lane = t & 31;
    const int warp = t >> 5;
    const int bh   = blockIdx.y;
    const int q0   = blockIdx.x * 128;

    const float* Qg = Q + ((size_t)bh*Ss + q0)*HD;
    const float* Kg = K + (size_t)bh*Ss*HD;
    const float* Vg = V + (size_t)bh*Ss*HD;

    // Load + split Q tile [128][64]
    #pragma unroll
    for (int i = 0; i < 8; i++) {
        const int slot = t + i*256;          // 0..2047
        const int r  = slot >> 4;
        const int c4 = (slot & 15) * 4;
        float4 v = *(const float4*)(Qg + (size_t)r*HD + c4);
        const uint32_t off = (uint32_t)(r*ALD + c4) * 2;
        uint32_t h0 = pack_hi(v.x, v.y), h1 = pack_hi(v.z, v.w);
        uint32_t l0 = pack_lo(v.x, v.y), l1 = pack_lo(v.z, v.w);
        asm volatile("st.shared.v2.b32 [%0], {%1,%2};" :: "r"(Qh + off), "r"(h0), "r"(h1));
        asm volatile("st.shared.v2.b32 [%0], {%1,%2};" :: "r"(Ql + off), "r"(l0), "r"(l1));
    }

    const int g8 = lane >> 3;
    const int l8 = lane & 7;
    const int aRow = (g8 & 1) * 8 + l8;
    const int aCol = (g8 >> 1) * 8;
    const int bRow = (g8 >> 1) * 8 + l8;
    const int bCol = (g8 & 1) * 8;

    float m_i[2], l_i[2];
    float O[8][4];
    m_i[0] = m_i[1] = -1e30f;
    l_i[0] = l_i[1] = 0.f;
    #pragma unroll
    for (int nf = 0; nf < 8; nf++)
        #pragma unroll
        for (int j = 0; j < 4; j++) O[nf][j] = 0.f;

    for (int kv = 0; kv < Ss; kv += 64) {
        __syncthreads();
        // K tile [64][64] row-major split ; V tile transposed [hd][key] split
        #pragma unroll
        for (int i = 0; i < 4; i++) {
            const int slot = t + i*256;      // 0..1023
            const int r  = slot >> 4;
            const int c4 = (slot & 15) * 4;
            float4 kk = *(const float4*)(Kg + (size_t)(kv + r)*HD + c4);
            const uint32_t off = (uint32_t)(r*ALD + c4) * 2;
            uint32_t h0 = pack_hi(kk.x, kk.y), h1 = pack_hi(kk.z, kk.w);
            uint32_t l0 = pack_lo(kk.x, kk.y), l1 = pack_lo(kk.z, kk.w);
            asm volatile("st.shared.v2.b32 [%0], {%1,%2};" :: "r"(Kh + off), "r"(h0), "r"(h1));
            asm volatile("st.shared.v2.b32 [%0], {%1,%2};" :: "r"(Kl + off), "r"(l0), "r"(l1));

            const int key = slot & 63;
            const int d4  = (slot >> 6) * 4;
            float4 vv = *(const float4*)(Vg + (size_t)(kv + key)*HD + d4);
            float vf[4] = { vv.x, vv.y, vv.z, vv.w };
            #pragma unroll
            for (int j = 0; j < 4; j++) {
                __nv_bfloat16 hb = __float2bfloat16_rn(vf[j]);
                __nv_bfloat16 lb = __float2bfloat16_rn(vf[j] - __bfloat162float(hb));
                const uint32_t voff = (uint32_t)((d4 + j)*ALD + key) * 2;
                asm volatile("st.shared.b16 [%0], %1;" :: "r"(Vh + voff), "h"(*(uint16_t*)&hb));
                asm volatile("st.shared.b16 [%0], %1;" :: "r"(Vl + voff), "h"(*(uint16_t*)&lb));
            }
        }
        __syncthreads();

        // ---- S = Q K^T (x3 split), M=16/warp, N=64, K=64 ----
        float S[8][4];
        #pragma unroll
        for (int nf = 0; nf < 8; nf++)
            #pragma unroll
            for (int j = 0; j < 4; j++) S[nf][j] = 0.f;

        #pragma unroll
        for (int ks = 0; ks < 4; ks++) {
            const int k0 = ks * 16;
            uint32_t aH[4], aL[4], bF[4][4];
            ldsm4(aH, Qh + (uint32_t)((warp*16 + aRow)*ALD + k0 + aCol) * 2);
            ldsm4(aL, Ql + (uint32_t)((warp*16 + aRow)*ALD + k0 + aCol) * 2);
            #pragma unroll
            for (int q = 0; q < 4; q++) {
                ldsm4(bF[q], Kh + (uint32_t)((q*16 + bRow)*ALD + k0 + bCol) * 2);
                mma16816(S[2*q+0], aH, bF[q][0], bF[q][1]);
                mma16816(S[2*q+1], aH, bF[q][2], bF[q][3]);
                mma16816(S[2*q+0], aL, bF[q][0], bF[q][1]);
                mma16816(S[2*q+1], aL, bF[q][2], bF[q][3]);
            }
            #pragma unroll
            for (int q = 0; q < 4; q++) {
                ldsm4(bF[q], Kl + (uint32_t)((q*16 + bRow)*ALD + k0 + bCol) * 2);
                mma16816(S[2*q+0], aH, bF[q][0], bF[q][1]);
                mma16816(S[2*q+1], aH, bF[q][2], bF[q][3]);
            }
        }

        // ---- online softmax on register fragments ----
        #pragma unroll
        for (int nf = 0; nf < 8; nf++)
            #pragma unroll
            for (int j = 0; j < 4; j++) S[nf][j] *= 0.125f;

        #pragma unroll
        for (int h = 0; h < 2; h++) {
            float mx = -1e30f;
            #pragma unroll
            for (int nf = 0; nf < 8; nf++)
                mx = fmaxf(mx, fmaxf(S[nf][2*h], S[nf][2*h+1]));
            mx = fmaxf(mx, __shfl_xor_sync(0xffffffffu, mx, 1));
            mx = fmaxf(mx, __shfl_xor_sync(0xffffffffu, mx, 2));
            const float mn    = fmaxf(m_i[h], mx);
            const float alpha = __expf(m_i[h] - mn);
            float ps = 0.f;
            #pragma unroll
            for (int nf = 0; nf < 8; nf++) {
                float p0 = __expf(S[nf][2*h]   - mn);
                float p1 = __expf(S[nf][2*h+1] - mn);
                S[nf][2*h] = p0; S[nf][2*h+1] = p1;
                ps += p0 + p1;
            }
            ps += __shfl_xor_sync(0xffffffffu, ps, 1);
            ps += __shfl_xor_sync(0xffffffffu, ps, 2);
            m_i[h] = mn;
            l_i[h] = l_i[h]*alpha + ps;
            #pragma unroll
            for (int nf = 0; nf < 8; nf++) {
                O[nf][2*h]   *= alpha;
                O[nf][2*h+1] *= alpha;
            }
        }

        // ---- O += P V  (P in registers, x3 split) ----
        #pragma unroll
        for (int ks = 0; ks < 4; ks++) {
            uint32_t aP[4], aQl[4];
            aP[0]  = pack_hi(S[2*ks][0],   S[2*ks][1]);
            aP[1]  = pack_hi(S[2*ks][2],   S[2*ks][3]);
            aP[2]  = pack_hi(S[2*ks+1][0], S[2*ks+1][1]);
            aP[3]  = pack_hi(S[2*ks+1][2], S[2*ks+1][3]);
            aQl[0] = pack_lo(S[2*ks][0],   S[2*ks][1]);
            aQl[1] = pack_lo(S[2*ks][2],   S[2*ks][3]);
            aQl[2] = pack_lo(S[2*ks+1][0], S[2*ks+1][1]);
            aQl[3] = pack_lo(S[2*ks+1][2], S[2*ks+1][3]);
            const int k0 = ks * 16;
            uint32_t bF[4];
            #pragma unroll
            for (int q = 0; q < 4; q++) {
                uint32_t bb[4];
                ldsm4(bb, Vh + (uint32_t)((q*16 + bRow)*ALD + k0 + bCol) * 2);
                mma16816(O[2*q+0], aP,  bb[0], bb[1]);
                mma16816(O[2*q+1], aP,  bb[2], bb[3]);
                mma16816(O[2*q+0], aQl, bb[0], bb[1]);
                mma16816(O[2*q+1], aQl, bb[2], bb[3]);
                ldsm4(bb, Vl + (uint32_t)((q*16 + bRow)*ALD + k0 + bCol) * 2);
                mma16816(O[2*q+0], aP, bb[0], bb[1]);
                mma16816(O[2*q+1], aP, bb[2], bb[3]);
            }
            (void)bF;
        }
    }

    // Normalize + write ctx [b, s, h*64 + d]
    const int b_idx = bh >> 4;
    const int hidx  = bh & 15;
    #pragma unroll
    for (int h = 0; h < 2; h++) {
        const int s_idx = q0 + warp*16 + (lane >> 2) + h*8;
        const float inv = 1.f / l_i[h];
        float* dst = &g_ctx[0]; (void)dst;
        #pragma unroll
        for (int nf = 0; nf < 8; nf++) {
            const int d0 = nf*8 + (lane & 3)*2;
            float2 r;
            r.x = O[nf][2*h]   * inv;
            r.y = O[nf][2*h+1] * inv;
            *(float2*)&ctx[((size_t)b_idx*Ss + s_idx)*Dd + hidx*HD + d0] = r;
        }
    }
}

// ---------------------------------------------------------------------------
extern "C" void kernel_launch(void* const* d_in, const int* in_sizes, int n_in,
                              void* d_out, int out_size)
{
    (void)in_sizes; (void)n_in; (void)out_size;
    const float* X  = (const float*)d_in[0];
    const float* Wq = (const float*)d_in[1];
    const float* bq = (const float*)d_in[2];
    const float* Wk = (const float*)d_in[3];
    const float* bk = (const float*)d_in[4];
    const float* Wv = (const float*)d_in[5];
    const float* bv = (const float*)d_in[6];
    const float* Wo = (const float*)d_in[7];
    const float* bo = (const float*)d_in[8];
    float* out = (float*)d_out;

    void *pQ, *pK, *pV, *pC;
    cudaGetSymbolAddress(&pQ, g_Q);
    cudaGetSymbolAddress(&pK, g_K);
    cudaGetSymbolAddress(&pV, g_V);
    cudaGetSymbolAddress(&pC, g_ctx);

    cudaFuncSetAttribute(gemm_mma, cudaFuncAttributeMaxDynamicSharedMemorySize, GEMM_SMEM);
    cudaFuncSetAttribute(attn_mma, cudaFuncAttributeMaxDynamicSharedMemorySize, ATTN_SMEM);

    rope_table<<<(Ss*32)/256, 256>>>();

    dim3 gg(Dd/128, MM/128);
    gemm_mma<<<gg, 256, GEMM_SMEM>>>(X, Wq, bq, (float*)pQ, 0);
    gemm_mma<<<gg, 256, GEMM_SMEM>>>(X, Wk, bk, (float*)pK, 0);
    gemm_mma<<<gg, 256, GEMM_SMEM>>>(X, Wv, bv, (float*)pV, 0);

    rope_apply<<<(BH*Ss*8)/256, 256>>>((float*)pQ, (float*)pK);

    attn_mma<<<dim3(Ss/128, BH), 256, ATTN_SMEM>>>(
        (const float*)pQ, (const float*)pK, (const float*)pV, (float*)pC);

    gemm_mma<<<gg, 256, GEMM_SMEM>>>((const float*)pC, Wo, bo, out, 1);
}

// round 5
// speedup vs baseline: 2.6972x; 1.0372x over previous
#include <cuda_runtime.h>
#include <cuda_bf16.h>
#include <math.h>
#include <stdint.h>

// Problem constants
#define Bb  4
#define Ss  2048
#define Dd  1024
#define Hh  16
#define HD  64
#define BH  (Bb*Hh)     // 64
#define MM  (Bb*Ss)     // 8192

// Scratch (device globals -> no allocation)
__device__ float g_Q[(size_t)BH*Ss*HD];     // [b,h,s,hd]
__device__ float g_K[(size_t)BH*Ss*HD];
__device__ float g_V[(size_t)BH*Ss*HD];
__device__ float g_ctx[(size_t)MM*Dd];      // [b,s,h*hd]
__device__ float g_sin[Ss*32];
__device__ float g_cos[Ss*32];

__device__ __forceinline__ uint32_t smem_u32(const void* p) {
    uint32_t a;
    asm("{ .reg .u64 t; cvta.to.shared.u64 t, %1; cvt.u32.u64 %0, t; }" : "=r"(a) : "l"(p));
    return a;
}

__device__ __forceinline__ void ldsm4(uint32_t (&r)[4], uint32_t addr) {
    asm volatile("ldmatrix.sync.aligned.m8n8.x4.shared.b16 {%0,%1,%2,%3}, [%4];"
        : "=r"(r[0]), "=r"(r[1]), "=r"(r[2]), "=r"(r[3]) : "r"(addr));
}

__device__ __forceinline__ void mma16816(float (&d)[4], const uint32_t (&a)[4],
                                         uint32_t b0, uint32_t b1) {
    asm volatile("mma.sync.aligned.m16n8k16.row.col.f32.bf16.bf16.f32 "
        "{%0,%1,%2,%3}, {%4,%5,%6,%7}, {%8,%9}, {%0,%1,%2,%3};"
        : "+f"(d[0]), "+f"(d[1]), "+f"(d[2]), "+f"(d[3])
        : "r"(a[0]), "r"(a[1]), "r"(a[2]), "r"(a[3]), "r"(b0), "r"(b1));
}

__device__ __forceinline__ uint32_t pack_hi(float x, float y) {
    __nv_bfloat162 h; h.x = __float2bfloat16_rn(x); h.y = __float2bfloat16_rn(y);
    return *(uint32_t*)&h;
}
__device__ __forceinline__ uint32_t pack_lo(float x, float y) {
    __nv_bfloat16 hx = __float2bfloat16_rn(x), hy = __float2bfloat16_rn(y);
    __nv_bfloat162 l;
    l.x = __float2bfloat16_rn(x - __bfloat162float(hx));
    l.y = __float2bfloat16_rn(y - __bfloat162float(hy));
    return *(uint32_t*)&l;
}

// ============================================================================
// mma.sync bf16x3 GEMM: Y = X W^T + b
// Tile 128x128x32, 8 warps, double-buffered smem, SINGLE sync per K-iter.
// ============================================================================
#define LDA 40
#define TILE_B (128*LDA*2)
#define STAGE_B (4*TILE_B)
#define GEMM_SMEM (2*STAGE_B)

__global__ __launch_bounds__(256, 1)
void gemm_mma(const float* __restrict__ X, const float* __restrict__ W,
              const float* __restrict__ bias, float* __restrict__ out, int mode)
{
    extern __shared__ char smc[];
    const uint32_t sb = smem_u32(smc);
    const int t    = threadIdx.x;
    const int lane = t & 31;
    const int warp = t >> 5;
    const int wm   = warp >> 1;
    const int wn   = warp & 1;
    const int bn   = blockIdx.x * 128;
    const int bm   = blockIdx.y * 128;

    float acc[2][8][4];
    #pragma unroll
    for (int mt = 0; mt < 2; mt++)
        #pragma unroll
        for (int nt = 0; nt < 8; nt++)
            #pragma unroll
            for (int j = 0; j < 4; j++) acc[mt][nt][j] = 0.f;

    const int lrow[4] = { (t+0)>>3, (t+256)>>3, (t+512)>>3, (t+768)>>3 };
    const int lc4     = (t & 7) * 4;

    float4 pa[4], pb[4];
    #pragma unroll
    for (int i = 0; i < 4; i++) {
        pa[i] = *(const float4*)(X + (size_t)(bm + lrow[i]) * Dd + lc4);
        pb[i] = *(const float4*)(W + (size_t)(bn + lrow[i]) * Dd + lc4);
    }

    auto store_stage = [&](int s, const float4* va, const float4* vb) {
        const uint32_t base = sb + (uint32_t)s * STAGE_B;
        #pragma unroll
        for (int i = 0; i < 4; i++) {
            const uint32_t off = (uint32_t)(lrow[i] * LDA + lc4) * 2;
            uint32_t h0 = pack_hi(va[i].x, va[i].y), h1 = pack_hi(va[i].z, va[i].w);
            uint32_t l0 = pack_lo(va[i].x, va[i].y), l1 = pack_lo(va[i].z, va[i].w);
            asm volatile("st.shared.v2.b32 [%0], {%1,%2};" :: "r"(base + off),          "r"(h0), "r"(h1));
            asm volatile("st.shared.v2.b32 [%0], {%1,%2};" :: "r"(base + TILE_B + off), "r"(l0), "r"(l1));
            h0 = pack_hi(vb[i].x, vb[i].y); h1 = pack_hi(vb[i].z, vb[i].w);
            l0 = pack_lo(vb[i].x, vb[i].y); l1 = pack_lo(vb[i].z, vb[i].w);
            asm volatile("st.shared.v2.b32 [%0], {%1,%2};" :: "r"(base + 2*TILE_B + off), "r"(h0), "r"(h1));
            asm volatile("st.shared.v2.b32 [%0], {%1,%2};" :: "r"(base + 3*TILE_B + off), "r"(l0), "r"(l1));
        }
    };

    store_stage(0, pa, pb);
    __syncthreads();

    const int g8 = lane >> 3;
    const int l8 = lane & 7;
    const int aRow = (g8 & 1) * 8 + l8;
    const int aCol = (g8 >> 1) * 8;
    const int bRow = (g8 >> 1) * 8 + l8;
    const int bCol = (g8 & 1) * 8;

    const int NT = Dd / 32;
    for (int kt = 0; kt < NT; kt++) {
        const int s = kt & 1;
        const int last = (kt + 1 == NT);
        if (!last) {
            const int kc = (kt + 1) * 32;
            #pragma unroll
            for (int i = 0; i < 4; i++) {
                pa[i] = *(const float4*)(X + (size_t)(bm + lrow[i]) * Dd + kc + lc4);
                pb[i] = *(const float4*)(W + (size_t)(bn + lrow[i]) * Dd + kc + lc4);
            }
        }

        const uint32_t Ah = sb + (uint32_t)s * STAGE_B;
        const uint32_t Al = Ah + TILE_B;
        const uint32_t Bh = Ah + 2*TILE_B;
        const uint32_t Bl = Ah + 3*TILE_B;

        #pragma unroll
        for (int ks = 0; ks < 2; ks++) {
            const int k0 = ks * 16;
            uint32_t aH[2][4], aL[2][4], bF[4][4];
            #pragma unroll
            for (int mt = 0; mt < 2; mt++) {
                ldsm4(aH[mt], Ah + (uint32_t)((wm*32 + mt*16 + aRow) * LDA + k0 + aCol) * 2);
                ldsm4(aL[mt], Al + (uint32_t)((wm*32 + mt*16 + aRow) * LDA + k0 + aCol) * 2);
            }
            #pragma unroll
            for (int q = 0; q < 4; q++)
                ldsm4(bF[q], Bh + (uint32_t)((wn*64 + q*16 + bRow) * LDA + k0 + bCol) * 2);
            #pragma unroll
            for (int mt = 0; mt < 2; mt++)
                #pragma unroll
                for (int q = 0; q < 4; q++) {
                    mma16816(acc[mt][q*2+0], aH[mt], bF[q][0], bF[q][1]);
                    mma16816(acc[mt][q*2+1], aH[mt], bF[q][2], bF[q][3]);
                }
            #pragma unroll
            for (int mt = 0; mt < 2; mt++)
                #pragma unroll
                for (int q = 0; q < 4; q++) {
                    mma16816(acc[mt][q*2+0], aL[mt], bF[q][0], bF[q][1]);
                    mma16816(acc[mt][q*2+1], aL[mt], bF[q][2], bF[q][3]);
                }
            #pragma unroll
            for (int q = 0; q < 4; q++)
                ldsm4(bF[q], Bl + (uint32_t)((wn*64 + q*16 + bRow) * LDA + k0 + bCol) * 2);
            #pragma unroll
            for (int mt = 0; mt < 2; mt++)
                #pragma unroll
                for (int q = 0; q < 4; q++) {
                    mma16816(acc[mt][q*2+0], aH[mt], bF[q][0], bF[q][1]);
                    mma16816(acc[mt][q*2+1], aH[mt], bF[q][2], bF[q][3]);
                }
        }

        if (!last) {
            store_stage(s ^ 1, pa, pb);   // writes OTHER stage; prev readers done at last sync
            __syncthreads();
        }
    }

    #pragma unroll
    for (int mt = 0; mt < 2; mt++) {
        #pragma unroll
        for (int half = 0; half < 2; half++) {
            const int m  = bm + wm*32 + mt*16 + (lane >> 2) + half*8;
            const int bi = m >> 11;
            const int si = m & (Ss - 1);
            #pragma unroll
            for (int nt = 0; nt < 8; nt++) {
                const int eloc = wn*64 + nt*8 + (lane & 3)*2;
                const int e0   = bn + eloc;
                float2 r;
                r.x = acc[mt][nt][half*2+0] + bias[e0];
                r.y = acc[mt][nt][half*2+1] + bias[e0+1];
                if (mode == 0) {
                    const int h  = e0 >> 6;
                    const int d0 = e0 & 63;
                    *(float2*)&out[(((size_t)bi*Hh + h)*Ss + si)*HD + d0] = r;
                } else {
                    *(float2*)&out[(size_t)m*Dd + e0] = r;
                }
            }
        }
    }
}

// ============================================================================
// RoPE (table + apply)
// ============================================================================
__global__ void rope_table()
{
    const int tid = blockIdx.x * blockDim.x + threadIdx.x;
    if (tid >= Ss * 32) return;
    const int s = tid >> 5;
    const int i = tid & 31;
    const double freq = exp(-((double)(2 * i) / 64.0) * 9.210340371976184);
    const float  argf = (float)s * (float)freq;
    const double a    = (double)argf;
    g_sin[tid] = (float)sin(a);
    g_cos[tid] = (float)cos(a);
}

__global__ void rope_apply(float* __restrict__ Q, float* __restrict__ K)
{
    const int idx = blockIdx.x * blockDim.x + threadIdx.x;
    const int c   = idx & 7;
    const int row = idx >> 3;
    const int s   = row & (Ss - 1);
    const size_t b0 = (size_t)row * HD + c * 4;

    const float4 sv = *(const float4*)&g_sin[s * 32 + c * 4];
    const float4 cv = *(const float4*)&g_cos[s * 32 + c * 4];

    float4 q1 = *(float4*)&Q[b0], q2 = *(float4*)&Q[b0 + 32];
    float4 o1, o2;
    o1.x = q1.x*sv.x - q2.x*cv.x;  o2.x = q2.x*sv.x + q1.x*cv.x;
    o1.y = q1.y*sv.y - q2.y*cv.y;  o2.y = q2.y*sv.y + q1.y*cv.y;
    o1.z = q1.z*sv.z - q2.z*cv.z;  o2.z = q2.z*sv.z + q1.z*cv.z;
    o1.w = q1.w*sv.w - q2.w*cv.w;  o2.w = q2.w*sv.w + q1.w*cv.w;
    *(float4*)&Q[b0] = o1; *(float4*)&Q[b0 + 32] = o2;

    float4 k1 = *(float4*)&K[b0], k2 = *(float4*)&K[b0 + 32];
    o1.x = k1.x*sv.x - k2.x*cv.x;  o2.x = k2.x*sv.x + k1.x*cv.x;
    o1.y = k1.y*sv.y - k2.y*cv.y;  o2.y = k2.y*sv.y + k1.y*cv.y;
    o1.z = k1.z*sv.z - k2.z*cv.z;  o2.z = k2.z*sv.z + k1.z*cv.z;
    o1.w = k1.w*sv.w - k2.w*cv.w;  o2.w = k2.w*sv.w + k1.w*cv.w;
    *(float4*)&K[b0] = o1; *(float4*)&K[b0 + 32] = o2;
}

// ============================================================================
// Flash attention via mma.sync bf16x3, double-buffered K/V, single sync/iter
// ============================================================================
#define ALD 72
#define AQ_B (128*ALD*2)       // 18432
#define AK_B (64*ALD*2)        // 9216
#define KV_STAGE_B (4*AK_B)    // 36864
#define ATTN_SMEM (2*AQ_B + 2*KV_STAGE_B)   // 110592

__global__ __launch_bounds__(256, 1)
void attn_mma(const float* __restrict__ Q, const float* __restrict__ K,
              const float* __restrict__ V, float* __restrict__ ctx)
{
    extern __shared__ char smc[];
    const uint32_t sb  = smem_u32(smc);
    const uint32_t Qh  = sb;
    const uint32_t Ql  = Qh + AQ_B;
    const uint32_t KV0 = Ql + AQ_B;

    const int t    = threadIdx.x;
    const int lane = t & 31;
    const int warp = t >> 5;
    const int bh   = blockIdx.y;
    const int q0   = blockIdx.x * 128;

    const float* Qg = Q + ((size_t)bh*Ss + q0)*HD;
    const float* Kg = K + (size_t)bh*Ss*HD;
    const float* Vg = V + (size_t)bh*Ss*HD;

    // Loads + splits one KV tile into a stage
    auto load_tile = [&](int kv, int s) {
        const uint32_t Kh = KV0 + (uint32_t)s * KV_STAGE_B;
        const uint32_t Kl = Kh + AK_B;
        const uint32_t Vh = Kl + AK_B;
        const uint32_t Vl = Vh + AK_B;
        #pragma unroll
        for (int i = 0; i < 4; i++) {
            const int slot = t + i*256;      // 0..1023
            const int r  = slot >> 4;
            const int c4 = (slot & 15) * 4;
            float4 kk = *(const float4*)(Kg + (size_t)(kv + r)*HD + c4);
            const uint32_t off = (uint32_t)(r*ALD + c4) * 2;
            uint32_t h0 = pack_hi(kk.x, kk.y), h1 = pack_hi(kk.z, kk.w);
            uint32_t l0 = pack_lo(kk.x, kk.y), l1 = pack_lo(kk.z, kk.w);
            asm volatile("st.shared.v2.b32 [%0], {%1,%2};" :: "r"(Kh + off), "r"(h0), "r"(h1));
            asm volatile("st.shared.v2.b32 [%0], {%1,%2};" :: "r"(Kl + off), "r"(l0), "r"(l1));

            const int key = slot & 63;
            const int d4  = (slot >> 6) * 4;
            float4 vv = *(const float4*)(Vg + (size_t)(kv + key)*HD + d4);
            float vf[4] = { vv.x, vv.y, vv.z, vv.w };
            #pragma unroll
            for (int j = 0; j < 4; j++) {
                __nv_bfloat16 hb = __float2bfloat16_rn(vf[j]);
                __nv_bfloat16 lb = __float2bfloat16_rn(vf[j] - __bfloat162float(hb));
                const uint32_t voff = (uint32_t)((d4 + j)*ALD + key) * 2;
                asm volatile("st.shared.b16 [%0], %1;" :: "r"(Vh + voff), "h"(*(uint16_t*)&hb));
                asm volatile("st.shared.b16 [%0], %1;" :: "r"(Vl + voff), "h"(*(uint16_t*)&lb));
            }
        }
    };

    // Load + split Q tile [128][64]
    #pragma unroll
    for (int i = 0; i < 8; i++) {
        const int slot = t + i*256;
        const int r  = slot >> 4;
        const int c4 = (slot & 15) * 4;
        float4 v = *(const float4*)(Qg + (size_t)r*HD + c4);
        const uint32_t off = (uint32_t)(r*ALD + c4) * 2;
        uint32_t h0 = pack_hi(v.x, v.y), h1 = pack_hi(v.z, v.w);
        uint32_t l0 = pack_lo(v.x, v.y), l1 = pack_lo(v.z, v.w);
        asm volatile("st.shared.v2.b32 [%0], {%1,%2};" :: "r"(Qh + off), "r"(h0), "r"(h1));
        asm volatile("st.shared.v2.b32 [%0], {%1,%2};" :: "r"(Ql + off), "r"(l0), "r"(l1));
    }
    load_tile(0, 0);
    __syncthreads();

    const int g8 = lane >> 3;
    const int l8 = lane & 7;
    const int aRow = (g8 & 1) * 8 + l8;
    const int aCol = (g8 >> 1) * 8;
    const int bRow = (g8 >> 1) * 8 + l8;
    const int bCol = (g8 & 1) * 8;

    float m_i[2], l_i[2];
    float O[8][4];
    m_i[0] = m_i[1] = -1e30f;
    l_i[0] = l_i[1] = 0.f;
    #pragma unroll
    for (int nf = 0; nf < 8; nf++)
        #pragma unroll
        for (int j = 0; j < 4; j++) O[nf][j] = 0.f;

    const int NTILE = Ss / 64;   // 32
    for (int n = 0; n < NTILE; n++) {
        const int s = n & 1;
        const uint32_t Kh = KV0 + (uint32_t)s * KV_STAGE_B;
        const uint32_t Kl = Kh + AK_B;
        const uint32_t Vh = Kl + AK_B;
        const uint32_t Vl = Vh + AK_B;

        // ---- S = Q K^T (x3 split) ----
        float S[8][4];
        #pragma unroll
        for (int nf = 0; nf < 8; nf++)
            #pragma unroll
            for (int j = 0; j < 4; j++) S[nf][j] = 0.f;

        #pragma unroll
        for (int ks = 0; ks < 4; ks++) {
            const int k0 = ks * 16;
            uint32_t aH[4], aL[4], bF[4][4];
            ldsm4(aH, Qh + (uint32_t)((warp*16 + aRow)*ALD + k0 + aCol) * 2);
            ldsm4(aL, Ql + (uint32_t)((warp*16 + aRow)*ALD + k0 + aCol) * 2);
            #pragma unroll
            for (int q = 0; q < 4; q++) {
                ldsm4(bF[q], Kh + (uint32_t)((q*16 + bRow)*ALD + k0 + bCol) * 2);
                mma16816(S[2*q+0], aH, bF[q][0], bF[q][1]);
                mma16816(S[2*q+1], aH, bF[q][2], bF[q][3]);
                mma16816(S[2*q+0], aL, bF[q][0], bF[q][1]);
                mma16816(S[2*q+1], aL, bF[q][2], bF[q][3]);
            }
            #pragma unroll
            for (int q = 0; q < 4; q++) {
                ldsm4(bF[q], Kl + (uint32_t)((q*16 + bRow)*ALD + k0 + bCol) * 2);
                mma16816(S[2*q+0], aH, bF[q][0], bF[q][1]);
                mma16816(S[2*q+1], aH, bF[q][2], bF[q][3]);
            }
        }

        // ---- online softmax ----
        #pragma unroll
        for (int nf = 0; nf < 8; nf++)
            #pragma unroll
            for (int j = 0; j < 4; j++) S[nf][j] *= 0.125f;

        #pragma unroll
        for (int h = 0; h < 2; h++) {
            float mx = -1e30f;
            #pragma unroll
            for (int nf = 0; nf < 8; nf++)
                mx = fmaxf(mx, fmaxf(S[nf][2*h], S[nf][2*h+1]));
            mx = fmaxf(mx, __shfl_xor_sync(0xffffffffu, mx, 1));
            mx = fmaxf(mx, __shfl_xor_sync(0xffffffffu, mx, 2));
            const float mn    = fmaxf(m_i[h], mx);
            const float alpha = __expf(m_i[h] - mn);
            float ps = 0.f;
            #pragma unroll
            for (int nf = 0; nf < 8; nf++) {
                float p0 = __expf(S[nf][2*h]   - mn);
                float p1 = __expf(S[nf][2*h+1] - mn);
                S[nf][2*h] = p0; S[nf][2*h+1] = p1;
                ps += p0 + p1;
            }
            ps += __shfl_xor_sync(0xffffffffu, ps, 1);
            ps += __shfl_xor_sync(0xffffffffu, ps, 2);
            m_i[h] = mn;
            l_i[h] = l_i[h]*alpha + ps;
            #pragma unroll
            for (int nf = 0; nf < 8; nf++) {
                O[nf][2*h]   *= alpha;
                O[nf][2*h+1] *= alpha;
            }
        }

        // ---- O += P V  (P in registers, x3 split) ----
        #pragma unroll
        for (int ks = 0; ks < 4; ks++) {
            uint32_t aP[4], aPl[4];
            aP[0]  = pack_hi(S[2*ks][0],   S[2*ks][1]);
            aP[1]  = pack_hi(S[2*ks][2],   S[2*ks][3]);
            aP[2]  = pack_hi(S[2*ks+1][0], S[2*ks+1][1]);
            aP[3]  = pack_hi(S[2*ks+1][2], S[2*ks+1][3]);
            aPl[0] = pack_lo(S[2*ks][0],   S[2*ks][1]);
            aPl[1] = pack_lo(S[2*ks][2],   S[2*ks][3]);
            aPl[2] = pack_lo(S[2*ks+1][0], S[2*ks+1][1]);
            aPl[3] = pack_lo(S[2*ks+1][2], S[2*ks+1][3]);
            const int k0 = ks * 16;
            #pragma unroll
            for (int q = 0; q < 4; q++) {
                uint32_t bb[4];
                ldsm4(bb, Vh + (uint32_t)((q*16 + bRow)*ALD + k0 + bCol) * 2);
                mma16816(O[2*q+0], aP,  bb[0], bb[1]);
                mma16816(O[2*q+1], aP,  bb[2], bb[3]);
                mma16816(O[2*q+0], aPl, bb[0], bb[1]);
                mma16816(O[2*q+1], aPl, bb[2], bb[3]);
                ldsm4(bb, Vl + (uint32_t)((q*16 + bRow)*ALD + k0 + bCol) * 2);
                mma16816(O[2*q+0], aP, bb[0], bb[1]);
                mma16816(O[2*q+1], aP, bb[2], bb[3]);
            }
        }

        // ---- prefetch next tile into other stage, then single sync ----
        if (n + 1 < NTILE) load_tile((n + 1) * 64, s ^ 1);
        __syncthreads();
    }

    // Normalize + write ctx [b, s, h*64 + d]
    const int b_idx = bh >> 4;
    const int hidx  = bh & 15;
    #pragma unroll
    for (int h = 0; h < 2; h++) {
        const int s_idx = q0 + warp*16 + (lane >> 2) + h*8;
        const float inv = 1.f / l_i[h];
        #pragma unroll
        for (int nf = 0; nf < 8; nf++) {
            const int d0 = nf*8 + (lane & 3)*2;
            float2 r;
            r.x = O[nf][2*h]   * inv;
            r.y = O[nf][2*h+1] * inv;
            *(float2*)&ctx[((size_t)b_idx*Ss + s_idx)*Dd + hidx*HD + d0] = r;
        }
    }
}

// ---------------------------------------------------------------------------
extern "C" void kernel_launch(void* const* d_in, const int* in_sizes, int n_in,
                              void* d_out, int out_size)
{
    (void)in_sizes; (void)n_in; (void)out_size;
    const float* X  = (const float*)d_in[0];
    const float* Wq = (const float*)d_in[1];
    const float* bq = (const float*)d_in[2];
    const float* Wk = (const float*)d_in[3];
    const float* bk = (const float*)d_in[4];
    const float* Wv = (const float*)d_in[5];
    const float* bv = (const float*)d_in[6];
    const float* Wo = (const float*)d_in[7];
    const float* bo = (const float*)d_in[8];
    float* out = (float*)d_out;

    void *pQ, *pK, *pV, *pC;
    cudaGetSymbolAddress(&pQ, g_Q);
    cudaGetSymbolAddress(&pK, g_K);
    cudaGetSymbolAddress(&pV, g_V);
    cudaGetSymbolAddress(&pC, g_ctx);

    cudaFuncSetAttribute(gemm_mma, cudaFuncAttributeMaxDynamicSharedMemorySize, GEMM_SMEM);
    cudaFuncSetAttribute(attn_mma, cudaFuncAttributeMaxDynamicSharedMemorySize, ATTN_SMEM);

    rope_table<<<(Ss*32)/256, 256>>>();

    dim3 gg(Dd/128, MM/128);
    gemm_mma<<<gg, 256, GEMM_SMEM>>>(X, Wq, bq, (float*)pQ, 0);
    gemm_mma<<<gg, 256, GEMM_SMEM>>>(X, Wk, bk, (float*)pK, 0);
    gemm_mma<<<gg, 256, GEMM_SMEM>>>(X, Wv, bv, (float*)pV, 0);

    rope_apply<<<(BH*Ss*8)/256, 256>>>((float*)pQ, (float*)pK);

    attn_mma<<<dim3(Ss/128, BH), 256, ATTN_SMEM>>>(
        (const float*)pQ, (const float*)pK, (const float*)pV, (float*)pC);

    gemm_mma<<<gg, 256, GEMM_SMEM>>>((const float*)pC, Wo, bo, out, 1);
}

// round 6
// speedup vs baseline: 3.2093x; 1.1899x over previous
#include <cuda_runtime.h>
#include <cuda_bf16.h>
#include <math.h>
#include <stdint.h>

// Problem constants
#define Bb  4
#define Ss  2048
#define Dd  1024
#define Hh  16
#define HD  64
#define BH  (Bb*Hh)     // 64
#define MM  (Bb*Ss)     // 8192
#define NE  ((size_t)MM*Dd)   // 8388608 elements per activation tensor

// fp32 scratch
__device__ float g_Q[NE];
__device__ float g_K[NE];
__device__ float g_V[NE];
__device__ float g_sin[Ss*32];
__device__ float g_cos[Ss*32];
// bf16 hi/lo scratch
__device__ __nv_bfloat16 g_Xh[NE],  g_Xl[NE];
__device__ __nv_bfloat16 g_Wh[4*(size_t)Dd*Dd], g_Wl[4*(size_t)Dd*Dd];
__device__ __nv_bfloat16 g_Qh[NE],  g_Ql[NE];
__device__ __nv_bfloat16 g_Kh[NE],  g_Kl[NE];
__device__ __nv_bfloat16 g_Vth[NE], g_Vtl[NE];   // transposed [b,h,d,s]
__device__ __nv_bfloat16 g_Ch[NE],  g_Cl[NE];    // ctx split [b,s,D]

__device__ __forceinline__ uint32_t smem_u32(const void* p) {
    uint32_t a;
    asm("{ .reg .u64 t; cvta.to.shared.u64 t, %1; cvt.u32.u64 %0, t; }" : "=r"(a) : "l"(p));
    return a;
}
__device__ __forceinline__ void ldsm4(uint32_t (&r)[4], uint32_t addr) {
    asm volatile("ldmatrix.sync.aligned.m8n8.x4.shared.b16 {%0,%1,%2,%3}, [%4];"
        : "=r"(r[0]), "=r"(r[1]), "=r"(r[2]), "=r"(r[3]) : "r"(addr));
}
__device__ __forceinline__ void mma16816(float (&d)[4], const uint32_t (&a)[4],
                                         uint32_t b0, uint32_t b1) {
    asm volatile("mma.sync.aligned.m16n8k16.row.col.f32.bf16.bf16.f32 "
        "{%0,%1,%2,%3}, {%4,%5,%6,%7}, {%8,%9}, {%0,%1,%2,%3};"
        : "+f"(d[0]), "+f"(d[1]), "+f"(d[2]), "+f"(d[3])
        : "r"(a[0]), "r"(a[1]), "r"(a[2]), "r"(a[3]), "r"(b0), "r"(b1));
}
__device__ __forceinline__ uint32_t pack_hi(float x, float y) {
    __nv_bfloat162 h; h.x = __float2bfloat16_rn(x); h.y = __float2bfloat16_rn(y);
    return *(uint32_t*)&h;
}
__device__ __forceinline__ uint32_t pack_lo(float x, float y) {
    __nv_bfloat16 hx = __float2bfloat16_rn(x), hy = __float2bfloat16_rn(y);
    __nv_bfloat162 l;
    l.x = __float2bfloat16_rn(x - __bfloat162float(hx));
    l.y = __float2bfloat16_rn(y - __bfloat162float(hy));
    return *(uint32_t*)&l;
}
#define CP16(sm_addr, gptr) \
    asm volatile("cp.async.cg.shared.global [%0], [%1], 16;" :: "r"(sm_addr), "l"(gptr))
#define CP_COMMIT() asm volatile("cp.async.commit_group;" ::: "memory")
#define CP_WAIT0()  asm volatile("cp.async.wait_group 0;"  ::: "memory")

// ============================================================================
// split fp32 -> bf16 hi/lo (vectorized, pure bandwidth)
// ============================================================================
__global__ void split_f32(const float* __restrict__ src,
                          __nv_bfloat16* __restrict__ dh,
                          __nv_bfloat16* __restrict__ dl, int n4)
{
    const int i = blockIdx.x * blockDim.x + threadIdx.x;
    if (i >= n4) return;
    float4 v = ((const float4*)src)[i];
    uint2 h, l;
    h.x = pack_hi(v.x, v.y); h.y = pack_hi(v.z, v.w);
    l.x = pack_lo(v.x, v.y); l.y = pack_lo(v.z, v.w);
    ((uint2*)dh)[i] = h;
    ((uint2*)dl)[i] = l;
}

// ============================================================================
// mma.sync bf16x3 GEMM, pre-split bf16 operands, cp.async loaders, occ 2.
// Y[m,e] = sum_d A[m,d]*B[e,d] + bias[e]
// mode 0: scatter fp32 [b,h,s,hd].  mode 1: row-major fp32 [m,e].
// ============================================================================
#define LDA 40
#define TILE_B (128*LDA*2)     // 10240
#define STAGE_B (4*TILE_B)     // 40960
#define GEMM_SMEM (2*STAGE_B)  // 81920

__global__ __launch_bounds__(256, 2)
void gemm_bf(const __nv_bfloat16* __restrict__ Ahg, const __nv_bfloat16* __restrict__ Alg,
             const __nv_bfloat16* __restrict__ Bhg, const __nv_bfloat16* __restrict__ Blg,
             const float* __restrict__ bias, float* __restrict__ out, int mode)
{
    extern __shared__ char smc[];
    const uint32_t sb = smem_u32(smc);
    const int t    = threadIdx.x;
    const int lane = t & 31;
    const int warp = t >> 5;
    const int wm   = warp >> 1;
    const int wn   = warp & 1;
    const int bn   = blockIdx.x * 128;
    const int bm   = blockIdx.y * 128;

    float acc[2][8][4];
    #pragma unroll
    for (int mt = 0; mt < 2; mt++)
        #pragma unroll
        for (int nt = 0; nt < 8; nt++)
            #pragma unroll
            for (int j = 0; j < 4; j++) acc[mt][nt][j] = 0.f;

    // loader: 512 x 16B slots per matrix; thread t does slots t and t+256
    const int lr0 = t >> 2;            // 0..63
    const int lc  = (t & 3) * 8;       // 0,8,16,24

    auto load_stage = [&](int s, int kc) {
        const uint32_t base = sb + (uint32_t)s * STAGE_B;
        #pragma unroll
        for (int i = 0; i < 2; i++) {
            const int r = lr0 + i * 64;
            const uint32_t so = (uint32_t)(r * LDA + lc) * 2;
            CP16(base + 0*TILE_B + so, Ahg + (size_t)(bm + r)*Dd + kc + lc);
            CP16(base + 1*TILE_B + so, Alg + (size_t)(bm + r)*Dd + kc + lc);
            CP16(base + 2*TILE_B + so, Bhg + (size_t)(bn + r)*Dd + kc + lc);
            CP16(base + 3*TILE_B + so, Blg + (size_t)(bn + r)*Dd + kc + lc);
        }
    };

    load_stage(0, 0);
    CP_COMMIT();
    CP_WAIT0();
    __syncthreads();

    const int g8 = lane >> 3;
    const int l8 = lane & 7;
    const int aRow = (g8 & 1) * 8 + l8;
    const int aCol = (g8 >> 1) * 8;
    const int bRow = (g8 >> 1) * 8 + l8;
    const int bCol = (g8 & 1) * 8;

    const int NT = Dd / 32;   // 32
    for (int kt = 0; kt < NT; kt++) {
        const int s = kt & 1;
        const int last = (kt + 1 == NT);
        if (!last) {
            load_stage(s ^ 1, (kt + 1) * 32);
            CP_COMMIT();
        }

        const uint32_t Ah = sb + (uint32_t)s * STAGE_B;
        const uint32_t Al = Ah + TILE_B;
        const uint32_t Bh = Ah + 2*TILE_B;
        const uint32_t Bl = Ah + 3*TILE_B;

        #pragma unroll
        for (int ks = 0; ks < 2; ks++) {
            const int k0 = ks * 16;
            uint32_t aH[2][4], aL[2][4], bF[4][4];
            #pragma unroll
            for (int mt = 0; mt < 2; mt++) {
                ldsm4(aH[mt], Ah + (uint32_t)((wm*32 + mt*16 + aRow) * LDA + k0 + aCol) * 2);
                ldsm4(aL[mt], Al + (uint32_t)((wm*32 + mt*16 + aRow) * LDA + k0 + aCol) * 2);
            }
            #pragma unroll
            for (int q = 0; q < 4; q++)
                ldsm4(bF[q], Bh + (uint32_t)((wn*64 + q*16 + bRow) * LDA + k0 + bCol) * 2);
            #pragma unroll
            for (int mt = 0; mt < 2; mt++)
                #pragma unroll
                for (int q = 0; q < 4; q++) {
                    mma16816(acc[mt][q*2+0], aH[mt], bF[q][0], bF[q][1]);
                    mma16816(acc[mt][q*2+1], aH[mt], bF[q][2], bF[q][3]);
                }
            #pragma unroll
            for (int mt = 0; mt < 2; mt++)
                #pragma unroll
                for (int q = 0; q < 4; q++) {
                    mma16816(acc[mt][q*2+0], aL[mt], bF[q][0], bF[q][1]);
                    mma16816(acc[mt][q*2+1], aL[mt], bF[q][2], bF[q][3]);
                }
            #pragma unroll
            for (int q = 0; q < 4; q++)
                ldsm4(bF[q], Bl + (uint32_t)((wn*64 + q*16 + bRow) * LDA + k0 + bCol) * 2);
            #pragma unroll
            for (int mt = 0; mt < 2; mt++)
                #pragma unroll
                for (int q = 0; q < 4; q++) {
                    mma16816(acc[mt][q*2+0], aH[mt], bF[q][0], bF[q][1]);
                    mma16816(acc[mt][q*2+1], aH[mt], bF[q][2], bF[q][3]);
                }
        }

        if (!last) {
            CP_WAIT0();
            __syncthreads();
        }
    }

    #pragma unroll
    for (int mt = 0; mt < 2; mt++) {
        #pragma unroll
        for (int half = 0; half < 2; half++) {
            const int m  = bm + wm*32 + mt*16 + (lane >> 2) + half*8;
            const int bi = m >> 11;
            const int si = m & (Ss - 1);
            #pragma unroll
            for (int nt = 0; nt < 8; nt++) {
                const int e0 = bn + wn*64 + nt*8 + (lane & 3)*2;
                float2 r;
                r.x = acc[mt][nt][half*2+0] + bias[e0];
                r.y = acc[mt][nt][half*2+1] + bias[e0+1];
                if (mode == 0) {
                    const int h  = e0 >> 6;
                    const int d0 = e0 & 63;
                    *(float2*)&out[(((size_t)bi*Hh + h)*Ss + si)*HD + d0] = r;
                } else {
                    *(float2*)&out[(size_t)m*Dd + e0] = r;
                }
            }
        }
    }
}

// ============================================================================
// RoPE table + apply (apply writes SPLIT bf16 Q/K; no fp32 writeback)
// ============================================================================
__global__ void rope_table()
{
    const int tid = blockIdx.x * blockDim.x + threadIdx.x;
    if (tid >= Ss * 32) return;
    const int s = tid >> 5;
    const int i = tid & 31;
    const double freq = exp(-((double)(2 * i) / 64.0) * 9.210340371976184);
    const float  argf = (float)s * (float)freq;
    const double a    = (double)argf;
    g_sin[tid] = (float)sin(a);
    g_cos[tid] = (float)cos(a);
}

__global__ void rope_apply_split()
{
    const int idx = blockIdx.x * blockDim.x + threadIdx.x;   // BH*Ss*8
    const int c   = idx & 7;
    const int row = idx >> 3;
    const int s   = row & (Ss - 1);
    const size_t b0 = (size_t)row * HD + c * 4;

    const float4 sv = *(const float4*)&g_sin[s * 32 + c * 4];
    const float4 cv = *(const float4*)&g_cos[s * 32 + c * 4];

    float4 q1 = *(float4*)&g_Q[b0], q2 = *(float4*)&g_Q[b0 + 32];
    float4 o1, o2;
    o1.x = q1.x*sv.x - q2.x*cv.x;  o2.x = q2.x*sv.x + q1.x*cv.x;
    o1.y = q1.y*sv.y - q2.y*cv.y;  o2.y = q2.y*sv.y + q1.y*cv.y;
    o1.z = q1.z*sv.z - q2.z*cv.z;  o2.z = q2.z*sv.z + q1.z*cv.z;
    o1.w = q1.w*sv.w - q2.w*cv.w;  o2.w = q2.w*sv.w + q1.w*cv.w;
    uint2 u;
    u.x = pack_hi(o1.x, o1.y); u.y = pack_hi(o1.z, o1.w); *(uint2*)&g_Qh[b0] = u;
    u.x = pack_lo(o1.x, o1.y); u.y = pack_lo(o1.z, o1.w); *(uint2*)&g_Ql[b0] = u;
    u.x = pack_hi(o2.x, o2.y); u.y = pack_hi(o2.z, o2.w); *(uint2*)&g_Qh[b0+32] = u;
    u.x = pack_lo(o2.x, o2.y); u.y = pack_lo(o2.z, o2.w); *(uint2*)&g_Ql[b0+32] = u;

    float4 k1 = *(float4*)&g_K[b0], k2 = *(float4*)&g_K[b0 + 32];
    o1.x = k1.x*sv.x - k2.x*cv.x;  o2.x = k2.x*sv.x + k1.x*cv.x;
    o1.y = k1.y*sv.y - k2.y*cv.y;  o2.y = k2.y*sv.y + k1.y*cv.y;
    o1.z = k1.z*sv.z - k2.z*cv.z;  o2.z = k2.z*sv.z + k1.z*cv.z;
    o1.w = k1.w*sv.w - k2.w*cv.w;  o2.w = k2.w*sv.w + k1.w*cv.w;
    u.x = pack_hi(o1.x, o1.y); u.y = pack_hi(o1.z, o1.w); *(uint2*)&g_Kh[b0] = u;
    u.x = pack_lo(o1.x, o1.y); u.y = pack_lo(o1.z, o1.w); *(uint2*)&g_Kl[b0] = u;
    u.x = pack_hi(o2.x, o2.y); u.y = pack_hi(o2.z, o2.w); *(uint2*)&g_Kh[b0+32] = u;
    u.x = pack_lo(o2.x, o2.y); u.y = pack_lo(o2.z, o2.w); *(uint2*)&g_Kl[b0+32] = u;
}

// ============================================================================
// V: fp32 [b,h,s,d] -> bf16 hi/lo transposed [b,h,d,s]
// ============================================================================
__global__ void split_v_trans()
{
    __shared__ float ts[64][65];
    const int bh = blockIdx.y;
    const int s0 = blockIdx.x * 64;
    const int t  = threadIdx.x;

    #pragma unroll
    for (int i = 0; i < 4; i++) {
        const int slot = t + i*256;            // 0..1023
        const int r  = slot >> 4;
        const int c4 = (slot & 15) * 4;
        float4 v = *(const float4*)&g_V[((size_t)bh*Ss + s0 + r)*HD + c4];
        ts[r][c4+0]=v.x; ts[r][c4+1]=v.y; ts[r][c4+2]=v.z; ts[r][c4+3]=v.w;
    }
    __syncthreads();

    #pragma unroll
    for (int i = 0; i < 4; i++) {
        const int slot = t + i*256;
        const int d   = slot >> 4;
        const int sc4 = (slot & 15) * 4;
        float v0 = ts[sc4+0][d], v1 = ts[sc4+1][d], v2 = ts[sc4+2][d], v3 = ts[sc4+3][d];
        const size_t o = ((size_t)bh*HD + d)*Ss + s0 + sc4;
        uint2 u;
        u.x = pack_hi(v0, v1); u.y = pack_hi(v2, v3); *(uint2*)&g_Vth[o] = u;
        u.x = pack_lo(v0, v1); u.y = pack_lo(v2, v3); *(uint2*)&g_Vtl[o] = u;
    }
}

// ============================================================================
// Flash attention: mma.sync bf16x3, pre-split operands, cp.async loaders,
// double-buffered K/V, split ctx output.
// ============================================================================
#define ALD 72
#define AQ_B (128*ALD*2)       // 18432
#define AK_B (64*ALD*2)        // 9216
#define KV_STAGE_B (4*AK_B)    // 36864
#define ATTN_SMEM (2*AQ_B + 2*KV_STAGE_B)   // 110592

__global__ __launch_bounds__(256, 1)
void attn_bf()
{
    extern __shared__ char smc[];
    const uint32_t sb  = smem_u32(smc);
    const uint32_t Qh  = sb;
    const uint32_t Ql  = Qh + AQ_B;
    const uint32_t KV0 = Ql + AQ_B;

    const int t    = threadIdx.x;
    const int lane = t & 31;
    const int warp = t >> 5;
    const int bh   = blockIdx.y;
    const int q0   = blockIdx.x * 128;

    const __nv_bfloat16* Qhg = g_Qh + ((size_t)bh*Ss + q0)*HD;
    const __nv_bfloat16* Qlg = g_Ql + ((size_t)bh*Ss + q0)*HD;
    const __nv_bfloat16* Khg = g_Kh + (size_t)bh*Ss*HD;
    const __nv_bfloat16* Klg = g_Kl + (size_t)bh*Ss*HD;
    const __nv_bfloat16* Vhg = g_Vth + (size_t)bh*HD*Ss;
    const __nv_bfloat16* Vlg = g_Vtl + (size_t)bh*HD*Ss;

    auto load_tile = [&](int kv, int s) {
        const uint32_t Kh = KV0 + (uint32_t)s * KV_STAGE_B;
        #pragma unroll
        for (int i = 0; i < 2; i++) {
            const int slot = t + i*256;       // 0..511
            const int r  = slot >> 3;         // 0..63
            const int c8 = (slot & 7) * 8;
            const uint32_t so = (uint32_t)(r * ALD + c8) * 2;
            CP16(Kh + 0*AK_B + so, Khg + (size_t)(kv + r)*HD + c8);
            CP16(Kh + 1*AK_B + so, Klg + (size_t)(kv + r)*HD + c8);
            CP16(Kh + 2*AK_B + so, Vhg + (size_t)r*Ss + kv + c8);
            CP16(Kh + 3*AK_B + so, Vlg + (size_t)r*Ss + kv + c8);
        }
    };

    // Q tile via cp.async (1024 slots per matrix)
    #pragma unroll
    for (int i = 0; i < 4; i++) {
        const int slot = t + i*256;
        const int r  = slot >> 3;
        const int c8 = (slot & 7) * 8;
        const uint32_t so = (uint32_t)(r * ALD + c8) * 2;
        CP16(Qh + so, Qhg + (size_t)r*HD + c8);
        CP16(Ql + so, Qlg + (size_t)r*HD + c8);
    }
    load_tile(0, 0);
    CP_COMMIT();
    CP_WAIT0();
    __syncthreads();

    const int g8 = lane >> 3;
    const int l8 = lane & 7;
    const int aRow = (g8 & 1) * 8 + l8;
    const int aCol = (g8 >> 1) * 8;
    const int bRow = (g8 >> 1) * 8 + l8;
    const int bCol = (g8 & 1) * 8;

    float m_i[2], l_i[2];
    float O[8][4];
    m_i[0] = m_i[1] = -1e30f;
    l_i[0] = l_i[1] = 0.f;
    #pragma unroll
    for (int nf = 0; nf < 8; nf++)
        #pragma unroll
        for (int j = 0; j < 4; j++) O[nf][j] = 0.f;

    const int NTILE = Ss / 64;
    for (int n = 0; n < NTILE; n++) {
        const int s = n & 1;
        if (n + 1 < NTILE) {
            load_tile((n + 1) * 64, s ^ 1);
            CP_COMMIT();
        }
        const uint32_t Kh = KV0 + (uint32_t)s * KV_STAGE_B;
        const uint32_t Kl = Kh + AK_B;
        const uint32_t Vh = Kl + AK_B;
        const uint32_t Vl = Vh + AK_B;

        // ---- S = Q K^T (x3 split) ----
        float S[8][4];
        #pragma unroll
        for (int nf = 0; nf < 8; nf++)
            #pragma unroll
            for (int j = 0; j < 4; j++) S[nf][j] = 0.f;

        #pragma unroll
        for (int ks = 0; ks < 4; ks++) {
            const int k0 = ks * 16;
            uint32_t aH[4], aL[4], bF[4][4];
            ldsm4(aH, Qh + (uint32_t)((warp*16 + aRow)*ALD + k0 + aCol) * 2);
            ldsm4(aL, Ql + (uint32_t)((warp*16 + aRow)*ALD + k0 + aCol) * 2);
            #pragma unroll
            for (int q = 0; q < 4; q++) {
                ldsm4(bF[q], Kh + (uint32_t)((q*16 + bRow)*ALD + k0 + bCol) * 2);
                mma16816(S[2*q+0], aH, bF[q][0], bF[q][1]);
                mma16816(S[2*q+1], aH, bF[q][2], bF[q][3]);
                mma16816(S[2*q+0], aL, bF[q][0], bF[q][1]);
                mma16816(S[2*q+1], aL, bF[q][2], bF[q][3]);
            }
            #pragma unroll
            for (int q = 0; q < 4; q++) {
                ldsm4(bF[q], Kl + (uint32_t)((q*16 + bRow)*ALD + k0 + bCol) * 2);
                mma16816(S[2*q+0], aH, bF[q][0], bF[q][1]);
                mma16816(S[2*q+1], aH, bF[q][2], bF[q][3]);
            }
        }

        // ---- online softmax ----
        #pragma unroll
        for (int nf = 0; nf < 8; nf++)
            #pragma unroll
            for (int j = 0; j < 4; j++) S[nf][j] *= 0.125f;

        #pragma unroll
        for (int h = 0; h < 2; h++) {
            float mx = -1e30f;
            #pragma unroll
            for (int nf = 0; nf < 8; nf++)
                mx = fmaxf(mx, fmaxf(S[nf][2*h], S[nf][2*h+1]));
            mx = fmaxf(mx, __shfl_xor_sync(0xffffffffu, mx, 1));
            mx = fmaxf(mx, __shfl_xor_sync(0xffffffffu, mx, 2));
            const float mn    = fmaxf(m_i[h], mx);
            const float alpha = __expf(m_i[h] - mn);
            float ps = 0.f;
            #pragma unroll
            for (int nf = 0; nf < 8; nf++) {
                float p0 = __expf(S[nf][2*h]   - mn);
                float p1 = __expf(S[nf][2*h+1] - mn);
                S[nf][2*h] = p0; S[nf][2*h+1] = p1;
                ps += p0 + p1;
            }
            ps += __shfl_xor_sync(0xffffffffu, ps, 1);
            ps += __shfl_xor_sync(0xffffffffu, ps, 2);
            m_i[h] = mn;
            l_i[h] = l_i[h]*alpha + ps;
            #pragma unroll
            for (int nf = 0; nf < 8; nf++) {
                O[nf][2*h]   *= alpha;
                O[nf][2*h+1] *= alpha;
            }
        }

        // ---- O += P V (P in registers, x3 split) ----
        #pragma unroll
        for (int ks = 0; ks < 4; ks++) {
            uint32_t aP[4], aPl[4];
            aP[0]  = pack_hi(S[2*ks][0],   S[2*ks][1]);
            aP[1]  = pack_hi(S[2*ks][2],   S[2*ks][3]);
            aP[2]  = pack_hi(S[2*ks+1][0], S[2*ks+1][1]);
            aP[3]  = pack_hi(S[2*ks+1][2], S[2*ks+1][3]);
            aPl[0] = pack_lo(S[2*ks][0],   S[2*ks][1]);
            aPl[1] = pack_lo(S[2*ks][2],   S[2*ks][3]);
            aPl[2] = pack_lo(S[2*ks+1][0], S[2*ks+1][1]);
            aPl[3] = pack_lo(S[2*ks+1][2], S[2*ks+1][3]);
            const int k0 = ks * 16;
            #pragma unroll
            for (int q = 0; q < 4; q++) {
                uint32_t bb[4];
                ldsm4(bb, Vh + (uint32_t)((q*16 + bRow)*ALD + k0 + bCol) * 2);
                mma16816(O[2*q+0], aP,  bb[0], bb[1]);
                mma16816(O[2*q+1], aP,  bb[2], bb[3]);
                mma16816(O[2*q+0], aPl, bb[0], bb[1]);
                mma16816(O[2*q+1], aPl, bb[2], bb[3]);
                ldsm4(bb, Vl + (uint32_t)((q*16 + bRow)*ALD + k0 + bCol) * 2);
                mma16816(O[2*q+0], aP, bb[0], bb[1]);
                mma16816(O[2*q+1], aP, bb[2], bb[3]);
            }
        }

        if (n + 1 < NTILE) {
            CP_WAIT0();
            __syncthreads();
        }
    }

    // Normalize + write SPLIT ctx [b, s, h*64 + d]
    const int b_idx = bh >> 4;
    const int hidx  = bh & 15;
    #pragma unroll
    for (int h = 0; h < 2; h++) {
        const int s_idx = q0 + warp*16 + (lane >> 2) + h*8;
        const float inv = 1.f / l_i[h];
        #pragma unroll
        for (int nf = 0; nf < 8; nf++) {
            const int d0 = nf*8 + (lane & 3)*2;
            const size_t o = ((size_t)b_idx*Ss + s_idx)*Dd + hidx*HD + d0;
            const float x = O[nf][2*h] * inv;
            const float y = O[nf][2*h+1] * inv;
            *(uint32_t*)&g_Ch[o] = pack_hi(x, y);
            *(uint32_t*)&g_Cl[o] = pack_lo(x, y);
        }
    }
}

// ---------------------------------------------------------------------------
extern "C" void kernel_launch(void* const* d_in, const int* in_sizes, int n_in,
                              void* d_out, int out_size)
{
    (void)in_sizes; (void)n_in; (void)out_size;
    const float* X  = (const float*)d_in[0];
    const float* Wq = (const float*)d_in[1];
    const float* bq = (const float*)d_in[2];
    const float* Wk = (const float*)d_in[3];
    const float* bk = (const float*)d_in[4];
    const float* Wv = (const float*)d_in[5];
    const float* bv = (const float*)d_in[6];
    const float* Wo = (const float*)d_in[7];
    const float* bo = (const float*)d_in[8];
    float* out = (float*)d_out;

    void *pQ, *pK, *pXh, *pXl, *pWh, *pWl, *pCh, *pCl;
    cudaGetSymbolAddress(&pQ,  g_Q);
    cudaGetSymbolAddress(&pK,  g_K);
    void* pV; cudaGetSymbolAddress(&pV, g_V);
    cudaGetSymbolAddress(&pXh, g_Xh);
    cudaGetSymbolAddress(&pXl, g_Xl);
    cudaGetSymbolAddress(&pWh, g_Wh);
    cudaGetSymbolAddress(&pWl, g_Wl);
    cudaGetSymbolAddress(&pCh, g_Ch);
    cudaGetSymbolAddress(&pCl, g_Cl);

    __nv_bfloat16* Xh = (__nv_bfloat16*)pXh;
    __nv_bfloat16* Xl = (__nv_bfloat16*)pXl;
    __nv_bfloat16* Wh = (__nv_bfloat16*)pWh;
    __nv_bfloat16* Wl = (__nv_bfloat16*)pWl;
    const size_t WSZ = (size_t)Dd * Dd;   // 1048576

    cudaFuncSetAttribute(gemm_bf, cudaFuncAttributeMaxDynamicSharedMemorySize, GEMM_SMEM);
    cudaFuncSetAttribute(attn_bf, cudaFuncAttributeMaxDynamicSharedMemorySize, ATTN_SMEM);

    rope_table<<<(Ss*32)/256, 256>>>();

    // Pre-split inputs
    split_f32<<<(int)(NE/4/256), 256>>>(X,  Xh, Xl, (int)(NE/4));
    split_f32<<<(int)(WSZ/4/256), 256>>>(Wq, Wh + 0*WSZ, Wl + 0*WSZ, (int)(WSZ/4));
    split_f32<<<(int)(WSZ/4/256), 256>>>(Wk, Wh + 1*WSZ, Wl + 1*WSZ, (int)(WSZ/4));
    split_f32<<<(int)(WSZ/4/256), 256>>>(Wv, Wh + 2*WSZ, Wl + 2*WSZ, (int)(WSZ/4));
    split_f32<<<(int)(WSZ/4/256), 256>>>(Wo, Wh + 3*WSZ, Wl + 3*WSZ, (int)(WSZ/4));

    dim3 gg(Dd/128, MM/128);   // (8, 64)
    gemm_bf<<<gg, 256, GEMM_SMEM>>>(Xh, Xl, Wh + 0*WSZ, Wl + 0*WSZ, bq, (float*)pQ, 0);
    gemm_bf<<<gg, 256, GEMM_SMEM>>>(Xh, Xl, Wh + 1*WSZ, Wl + 1*WSZ, bk, (float*)pK, 0);
    gemm_bf<<<gg, 256, GEMM_SMEM>>>(Xh, Xl, Wh + 2*WSZ, Wl + 2*WSZ, bv, (float*)pV, 0);

    rope_apply_split<<<(BH*Ss*8)/256, 256>>>();
    split_v_trans<<<dim3(Ss/64, BH), 256>>>();

    attn_bf<<<dim3(Ss/128, BH), 256, ATTN_SMEM>>>();

    gemm_bf<<<gg, 256, GEMM_SMEM>>>((__nv_bfloat16*)pCh, (__nv_bfloat16*)pCl,
                                    Wh + 3*WSZ, Wl + 3*WSZ, bo, out, 1);
}

// round 7
// speedup vs baseline: 3.4936x; 1.0886x over previous
#include <cuda_runtime.h>
#include <cuda_bf16.h>
#include <math.h>
#include <stdint.h>

// Problem constants
#define Bb  4
#define Ss  2048
#define Dd  1024
#define Hh  16
#define HD  64
#define BH  (Bb*Hh)     // 64
#define MM  (Bb*Ss)     // 8192
#define NE  ((size_t)MM*Dd)

// Scratch (device globals -> no allocation)
__device__ float g_V[NE];                     // fp32 V (pre-transpose)
__device__ float g_sin[Ss*32];
__device__ float g_cos[Ss*32];
__device__ __nv_bfloat16 g_Xh[NE],  g_Xl[NE];
__device__ __nv_bfloat16 g_Wh[4*(size_t)Dd*Dd], g_Wl[4*(size_t)Dd*Dd];
__device__ __nv_bfloat16 g_Qh[NE],  g_Ql[NE]; // roped Q split [b,h,s,hd]
__device__ __nv_bfloat16 g_Kh[NE],  g_Kl[NE]; // roped K split [b,h,s,hd]
__device__ __nv_bfloat16 g_Vth[NE], g_Vtl[NE];// V split transposed [b,h,d,s]
__device__ __nv_bfloat16 g_Ch[NE],  g_Cl[NE]; // ctx split [b,s,D]

__device__ __forceinline__ uint32_t smem_u32(const void* p) {
    uint32_t a;
    asm("{ .reg .u64 t; cvta.to.shared.u64 t, %1; cvt.u32.u64 %0, t; }" : "=r"(a) : "l"(p));
    return a;
}
__device__ __forceinline__ void ldsm4(uint32_t (&r)[4], uint32_t addr) {
    asm volatile("ldmatrix.sync.aligned.m8n8.x4.shared.b16 {%0,%1,%2,%3}, [%4];"
        : "=r"(r[0]), "=r"(r[1]), "=r"(r[2]), "=r"(r[3]) : "r"(addr));
}
__device__ __forceinline__ void mma16816(float (&d)[4], const uint32_t (&a)[4],
                                         uint32_t b0, uint32_t b1) {
    asm volatile("mma.sync.aligned.m16n8k16.row.col.f32.bf16.bf16.f32 "
        "{%0,%1,%2,%3}, {%4,%5,%6,%7}, {%8,%9}, {%0,%1,%2,%3};"
        : "+f"(d[0]), "+f"(d[1]), "+f"(d[2]), "+f"(d[3])
        : "r"(a[0]), "r"(a[1]), "r"(a[2]), "r"(a[3]), "r"(b0), "r"(b1));
}
__device__ __forceinline__ uint32_t pack_hi(float x, float y) {
    __nv_bfloat162 h; h.x = __float2bfloat16_rn(x); h.y = __float2bfloat16_rn(y);
    return *(uint32_t*)&h;
}
__device__ __forceinline__ uint32_t pack_lo(float x, float y) {
    __nv_bfloat16 hx = __float2bfloat16_rn(x), hy = __float2bfloat16_rn(y);
    __nv_bfloat162 l;
    l.x = __float2bfloat16_rn(x - __bfloat162float(hx));
    l.y = __float2bfloat16_rn(y - __bfloat162float(hy));
    return *(uint32_t*)&l;
}
#define CP16(sm_addr, gptr) \
    asm volatile("cp.async.cg.shared.global [%0], [%1], 16;" :: "r"(sm_addr), "l"(gptr))
#define CP_COMMIT() asm volatile("cp.async.commit_group;" ::: "memory")
#define CP_WAIT0()  asm volatile("cp.async.wait_group 0;"  ::: "memory")

// ============================================================================
__global__ void rope_table()
{
    const int tid = blockIdx.x * blockDim.x + threadIdx.x;
    if (tid >= Ss * 32) return;
    const int s = tid >> 5;
    const int i = tid & 31;
    const double freq = exp(-((double)(2 * i) / 64.0) * 9.210340371976184);
    const float  argf = (float)s * (float)freq;
    const double a    = (double)argf;
    g_sin[tid] = (float)sin(a);
    g_cos[tid] = (float)cos(a);
}

__global__ void split_f32(const float* __restrict__ src,
                          __nv_bfloat16* __restrict__ dh,
                          __nv_bfloat16* __restrict__ dl, int n4)
{
    const int i = blockIdx.x * blockDim.x + threadIdx.x;
    if (i >= n4) return;
    float4 v = ((const float4*)src)[i];
    uint2 h, l;
    h.x = pack_hi(v.x, v.y); h.y = pack_hi(v.z, v.w);
    l.x = pack_lo(v.x, v.y); l.y = pack_lo(v.z, v.w);
    ((uint2*)dh)[i] = h;
    ((uint2*)dl)[i] = l;
}

// ============================================================================
// Fused QKV GEMM (gridDim.z selects weight). Epilogue applies bias (+RoPE for
// Q/K, written split bf16) ; V written fp32 for later transpose.
// ============================================================================
#define LDA 40
#define TILE_B (128*LDA*2)
#define STAGE_B (4*TILE_B)
#define GEMM_SMEM (2*STAGE_B)  // 81920

__global__ __launch_bounds__(256, 2)
void gemm_qkv(const float* __restrict__ bq, const float* __restrict__ bk,
              const float* __restrict__ bv)
{
    extern __shared__ char smc[];
    const uint32_t sb = smem_u32(smc);
    const int t    = threadIdx.x;
    const int lane = t & 31;
    const int warp = t >> 5;
    const int wm   = warp >> 1;
    const int wn   = warp & 1;
    const int bn   = blockIdx.x * 128;
    const int bm   = blockIdx.y * 128;
    const int widx = blockIdx.z;
    const size_t WSZ = (size_t)Dd * Dd;

    const __nv_bfloat16* Ahg = g_Xh;
    const __nv_bfloat16* Alg = g_Xl;
    const __nv_bfloat16* Bhg = g_Wh + (size_t)widx * WSZ;
    const __nv_bfloat16* Blg = g_Wl + (size_t)widx * WSZ;
    const float* bias = (widx == 0) ? bq : (widx == 1 ? bk : bv);

    float acc[2][8][4];
    #pragma unroll
    for (int mt = 0; mt < 2; mt++)
        #pragma unroll
        for (int nt = 0; nt < 8; nt++)
            #pragma unroll
            for (int j = 0; j < 4; j++) acc[mt][nt][j] = 0.f;

    const int lr0 = t >> 2;
    const int lc  = (t & 3) * 8;

    auto load_stage = [&](int s, int kc) {
        const uint32_t base = sb + (uint32_t)s * STAGE_B;
        #pragma unroll
        for (int i = 0; i < 2; i++) {
            const int r = lr0 + i * 64;
            const uint32_t so = (uint32_t)(r * LDA + lc) * 2;
            CP16(base + 0*TILE_B + so, Ahg + (size_t)(bm + r)*Dd + kc + lc);
            CP16(base + 1*TILE_B + so, Alg + (size_t)(bm + r)*Dd + kc + lc);
            CP16(base + 2*TILE_B + so, Bhg + (size_t)(bn + r)*Dd + kc + lc);
            CP16(base + 3*TILE_B + so, Blg + (size_t)(bn + r)*Dd + kc + lc);
        }
    };

    load_stage(0, 0);
    CP_COMMIT();
    CP_WAIT0();
    __syncthreads();

    const int g8 = lane >> 3;
    const int l8 = lane & 7;
    const int aRow = (g8 & 1) * 8 + l8;
    const int aCol = (g8 >> 1) * 8;
    const int bRow = (g8 >> 1) * 8 + l8;
    const int bCol = (g8 & 1) * 8;

    const int NT = Dd / 32;
    for (int kt = 0; kt < NT; kt++) {
        const int s = kt & 1;
        const int last = (kt + 1 == NT);
        if (!last) { load_stage(s ^ 1, (kt + 1) * 32); CP_COMMIT(); }

        const uint32_t Ah = sb + (uint32_t)s * STAGE_B;
        const uint32_t Al = Ah + TILE_B;
        const uint32_t Bh = Ah + 2*TILE_B;
        const uint32_t Bl = Ah + 3*TILE_B;

        #pragma unroll
        for (int ks = 0; ks < 2; ks++) {
            const int k0 = ks * 16;
            uint32_t aH[2][4], aL[2][4], bF[4][4];
            #pragma unroll
            for (int mt = 0; mt < 2; mt++) {
                ldsm4(aH[mt], Ah + (uint32_t)((wm*32 + mt*16 + aRow) * LDA + k0 + aCol) * 2);
                ldsm4(aL[mt], Al + (uint32_t)((wm*32 + mt*16 + aRow) * LDA + k0 + aCol) * 2);
            }
            #pragma unroll
            for (int q = 0; q < 4; q++)
                ldsm4(bF[q], Bh + (uint32_t)((wn*64 + q*16 + bRow) * LDA + k0 + bCol) * 2);
            #pragma unroll
            for (int mt = 0; mt < 2; mt++)
                #pragma unroll
                for (int q = 0; q < 4; q++) {
                    mma16816(acc[mt][q*2+0], aH[mt], bF[q][0], bF[q][1]);
                    mma16816(acc[mt][q*2+1], aH[mt], bF[q][2], bF[q][3]);
                }
            #pragma unroll
            for (int mt = 0; mt < 2; mt++)
                #pragma unroll
                for (int q = 0; q < 4; q++) {
                    mma16816(acc[mt][q*2+0], aL[mt], bF[q][0], bF[q][1]);
                    mma16816(acc[mt][q*2+1], aL[mt], bF[q][2], bF[q][3]);
                }
            #pragma unroll
            for (int q = 0; q < 4; q++)
                ldsm4(bF[q], Bl + (uint32_t)((wn*64 + q*16 + bRow) * LDA + k0 + bCol) * 2);
            #pragma unroll
            for (int mt = 0; mt < 2; mt++)
                #pragma unroll
                for (int q = 0; q < 4; q++) {
                    mma16816(acc[mt][q*2+0], aH[mt], bF[q][0], bF[q][1]);
                    mma16816(acc[mt][q*2+1], aH[mt], bF[q][2], bF[q][3]);
                }
        }

        if (!last) { CP_WAIT0(); __syncthreads(); }
    }

    // Epilogue
    const int lane2 = (lane & 3) * 2;
    #pragma unroll
    for (int mt = 0; mt < 2; mt++) {
        #pragma unroll
        for (int half = 0; half < 2; half++) {
            const int m  = bm + wm*32 + mt*16 + (lane >> 2) + half*8;
            const int bi = m >> 11;
            const int si = m & (Ss - 1);
            if (widx == 2) {
                #pragma unroll
                for (int nt = 0; nt < 8; nt++) {
                    const int e0 = bn + wn*64 + nt*8 + lane2;
                    const int h  = e0 >> 6;
                    const int d0 = e0 & 63;
                    float2 r;
                    r.x = acc[mt][nt][half*2+0] + bias[e0];
                    r.y = acc[mt][nt][half*2+1] + bias[e0+1];
                    *(float2*)&g_V[(((size_t)bi*Hh + h)*Ss + si)*HD + d0] = r;
                }
            } else {
                __nv_bfloat16* dh = widx ? g_Kh : g_Qh;
                __nv_bfloat16* dl = widx ? g_Kl : g_Ql;
                #pragma unroll
                for (int nt = 0; nt < 4; nt++) {
                    const int e0 = bn + wn*64 + nt*8 + lane2;  // d0 < 32 within head
                    const int h  = e0 >> 6;
                    const int d0 = e0 & 63;
                    float x1a = acc[mt][nt][half*2+0]   + bias[e0];
                    float x1b = acc[mt][nt][half*2+1]   + bias[e0+1];
                    float x2a = acc[mt][nt+4][half*2+0] + bias[e0+32];
                    float x2b = acc[mt][nt+4][half*2+1] + bias[e0+33];
                    const float2 sv = *(const float2*)&g_sin[si*32 + d0];
                    const float2 cv = *(const float2*)&g_cos[si*32 + d0];
                    // reference naming swap: out1 = x1*sin - x2*cos ; out2 = x2*sin + x1*cos
                    float o1a = x1a*sv.x - x2a*cv.x, o1b = x1b*sv.y - x2b*cv.y;
                    float o2a = x2a*sv.x + x1a*cv.x, o2b = x2b*sv.y + x1b*cv.y;
                    const size_t o = (((size_t)bi*Hh + h)*Ss + si)*HD + d0;
                    *(uint32_t*)&dh[o]      = pack_hi(o1a, o1b);
                    *(uint32_t*)&dl[o]      = pack_lo(o1a, o1b);
                    *(uint32_t*)&dh[o + 32] = pack_hi(o2a, o2b);
                    *(uint32_t*)&dl[o + 32] = pack_lo(o2a, o2b);
                }
            }
        }
    }
}

// ============================================================================
// O-projection GEMM (row-major out to d_out)
// ============================================================================
__global__ __launch_bounds__(256, 2)
void gemm_o(const float* __restrict__ bias, float* __restrict__ out)
{
    extern __shared__ char smc[];
    const uint32_t sb = smem_u32(smc);
    const int t    = threadIdx.x;
    const int lane = t & 31;
    const int warp = t >> 5;
    const int wm   = warp >> 1;
    const int wn   = warp & 1;
    const int bn   = blockIdx.x * 128;
    const int bm   = blockIdx.y * 128;
    const size_t WSZ = (size_t)Dd * Dd;

    const __nv_bfloat16* Ahg = g_Ch;
    const __nv_bfloat16* Alg = g_Cl;
    const __nv_bfloat16* Bhg = g_Wh + 3*WSZ;
    const __nv_bfloat16* Blg = g_Wl + 3*WSZ;

    float acc[2][8][4];
    #pragma unroll
    for (int mt = 0; mt < 2; mt++)
        #pragma unroll
        for (int nt = 0; nt < 8; nt++)
            #pragma unroll
            for (int j = 0; j < 4; j++) acc[mt][nt][j] = 0.f;

    const int lr0 = t >> 2;
    const int lc  = (t & 3) * 8;

    auto load_stage = [&](int s, int kc) {
        const uint32_t base = sb + (uint32_t)s * STAGE_B;
        #pragma unroll
        for (int i = 0; i < 2; i++) {
            const int r = lr0 + i * 64;
            const uint32_t so = (uint32_t)(r * LDA + lc) * 2;
            CP16(base + 0*TILE_B + so, Ahg + (size_t)(bm + r)*Dd + kc + lc);
            CP16(base + 1*TILE_B + so, Alg + (size_t)(bm + r)*Dd + kc + lc);
            CP16(base + 2*TILE_B + so, Bhg + (size_t)(bn + r)*Dd + kc + lc);
            CP16(base + 3*TILE_B + so, Blg + (size_t)(bn + r)*Dd + kc + lc);
        }
    };

    load_stage(0, 0);
    CP_COMMIT();
    CP_WAIT0();
    __syncthreads();

    const int g8 = lane >> 3;
    const int l8 = lane & 7;
    const int aRow = (g8 & 1) * 8 + l8;
    const int aCol = (g8 >> 1) * 8;
    const int bRow = (g8 >> 1) * 8 + l8;
    const int bCol = (g8 & 1) * 8;

    const int NT = Dd / 32;
    for (int kt = 0; kt < NT; kt++) {
        const int s = kt & 1;
        const int last = (kt + 1 == NT);
        if (!last) { load_stage(s ^ 1, (kt + 1) * 32); CP_COMMIT(); }

        const uint32_t Ah = sb + (uint32_t)s * STAGE_B;
        const uint32_t Al = Ah + TILE_B;
        const uint32_t Bh = Ah + 2*TILE_B;
        const uint32_t Bl = Ah + 3*TILE_B;

        #pragma unroll
        for (int ks = 0; ks < 2; ks++) {
            const int k0 = ks * 16;
            uint32_t aH[2][4], aL[2][4], bF[4][4];
            #pragma unroll
            for (int mt = 0; mt < 2; mt++) {
                ldsm4(aH[mt], Ah + (uint32_t)((wm*32 + mt*16 + aRow) * LDA + k0 + aCol) * 2);
                ldsm4(aL[mt], Al + (uint32_t)((wm*32 + mt*16 + aRow) * LDA + k0 + aCol) * 2);
            }
            #pragma unroll
            for (int q = 0; q < 4; q++)
                ldsm4(bF[q], Bh + (uint32_t)((wn*64 + q*16 + bRow) * LDA + k0 + bCol) * 2);
            #pragma unroll
            for (int mt = 0; mt < 2; mt++)
                #pragma unroll
                for (int q = 0; q < 4; q++) {
                    mma16816(acc[mt][q*2+0], aH[mt], bF[q][0], bF[q][1]);
                    mma16816(acc[mt][q*2+1], aH[mt], bF[q][2], bF[q][3]);
                }
            #pragma unroll
            for (int mt = 0; mt < 2; mt++)
                #pragma unroll
                for (int q = 0; q < 4; q++) {
                    mma16816(acc[mt][q*2+0], aL[mt], bF[q][0], bF[q][1]);
                    mma16816(acc[mt][q*2+1], aL[mt], bF[q][2], bF[q][3]);
                }
            #pragma unroll
            for (int q = 0; q < 4; q++)
                ldsm4(bF[q], Bl + (uint32_t)((wn*64 + q*16 + bRow) * LDA + k0 + bCol) * 2);
            #pragma unroll
            for (int mt = 0; mt < 2; mt++)
                #pragma unroll
                for (int q = 0; q < 4; q++) {
                    mma16816(acc[mt][q*2+0], aH[mt], bF[q][0], bF[q][1]);
                    mma16816(acc[mt][q*2+1], aH[mt], bF[q][2], bF[q][3]);
                }
        }

        if (!last) { CP_WAIT0(); __syncthreads(); }
    }

    #pragma unroll
    for (int mt = 0; mt < 2; mt++) {
        #pragma unroll
        for (int half = 0; half < 2; half++) {
            const int m = bm + wm*32 + mt*16 + (lane >> 2) + half*8;
            #pragma unroll
            for (int nt = 0; nt < 8; nt++) {
                const int e0 = bn + wn*64 + nt*8 + (lane & 3)*2;
                float2 r;
                r.x = acc[mt][nt][half*2+0] + bias[e0];
                r.y = acc[mt][nt][half*2+1] + bias[e0+1];
                *(float2*)&out[(size_t)m*Dd + e0] = r;
            }
        }
    }
}

// ============================================================================
// V: fp32 [b,h,s,d] -> bf16 hi/lo transposed [b,h,d,s]
// ============================================================================
__global__ void split_v_trans()
{
    __shared__ float ts[64][65];
    const int bh = blockIdx.y;
    const int s0 = blockIdx.x * 64;
    const int t  = threadIdx.x;

    #pragma unroll
    for (int i = 0; i < 4; i++) {
        const int slot = t + i*256;
        const int r  = slot >> 4;
        const int c4 = (slot & 15) * 4;
        float4 v = *(const float4*)&g_V[((size_t)bh*Ss + s0 + r)*HD + c4];
        ts[r][c4+0]=v.x; ts[r][c4+1]=v.y; ts[r][c4+2]=v.z; ts[r][c4+3]=v.w;
    }
    __syncthreads();

    #pragma unroll
    for (int i = 0; i < 4; i++) {
        const int slot = t + i*256;
        const int d   = slot >> 4;
        const int sc4 = (slot & 15) * 4;
        float v0 = ts[sc4+0][d], v1 = ts[sc4+1][d], v2 = ts[sc4+2][d], v3 = ts[sc4+3][d];
        const size_t o = ((size_t)bh*HD + d)*Ss + s0 + sc4;
        uint2 u;
        u.x = pack_hi(v0, v1); u.y = pack_hi(v2, v3); *(uint2*)&g_Vth[o] = u;
        u.x = pack_lo(v0, v1); u.y = pack_lo(v2, v3); *(uint2*)&g_Vtl[o] = u;
    }
}

// ============================================================================
// Flash attention: Q fragments in REGISTERS, occ 2, double-buffered K/V.
// ============================================================================
#define ALD 72
#define AK_B (64*ALD*2)        // 9216
#define KV_STAGE_B (4*AK_B)    // 36864
#define ATTN_SMEM (2*KV_STAGE_B)   // 73728

__global__ __launch_bounds__(256, 2)
void attn_bf()
{
    extern __shared__ char smc[];
    const uint32_t sb  = smem_u32(smc);
    const uint32_t KV0 = sb;

    const int t    = threadIdx.x;
    const int lane = t & 31;
    const int warp = t >> 5;
    const int bh   = blockIdx.y;
    const int q0   = blockIdx.x * 128;

    const __nv_bfloat16* Qhg = g_Qh + ((size_t)bh*Ss + q0)*HD;
    const __nv_bfloat16* Qlg = g_Ql + ((size_t)bh*Ss + q0)*HD;
    const __nv_bfloat16* Khg = g_Kh + (size_t)bh*Ss*HD;
    const __nv_bfloat16* Klg = g_Kl + (size_t)bh*Ss*HD;
    const __nv_bfloat16* Vhg = g_Vth + (size_t)bh*HD*Ss;
    const __nv_bfloat16* Vlg = g_Vtl + (size_t)bh*HD*Ss;

    const int g8 = lane >> 3;
    const int l8 = lane & 7;
    const int aRow = (g8 & 1) * 8 + l8;
    const int aCol = (g8 >> 1) * 8;
    const int bRow = (g8 >> 1) * 8 + l8;
    const int bCol = (g8 & 1) * 8;

    // --- Stage Q through smem once; fragment to registers ---
    {
        const uint32_t QhS = KV0;              // 18432 B
        const uint32_t QlS = KV0 + 128*ALD*2;
        #pragma unroll
        for (int i = 0; i < 4; i++) {
            const int slot = t + i*256;        // 0..1023
            const int r  = slot >> 3;
            const int c8 = (slot & 7) * 8;
            const uint32_t so = (uint32_t)(r * ALD + c8) * 2;
            CP16(QhS + so, Qhg + (size_t)r*HD + c8);
            CP16(QlS + so, Qlg + (size_t)r*HD + c8);
        }
        CP_COMMIT();
        CP_WAIT0();
        __syncthreads();
    }
    uint32_t qH[4][4], qL[4][4];
    #pragma unroll
    for (int ks = 0; ks < 4; ks++) {
        const int k0 = ks * 16;
        ldsm4(qH[ks], KV0 +              (uint32_t)((warp*16 + aRow)*ALD + k0 + aCol) * 2);
        ldsm4(qL[ks], KV0 + 128*ALD*2 + (uint32_t)((warp*16 + aRow)*ALD + k0 + aCol) * 2);
    }
    __syncthreads();   // all warps done with Q staging area

    auto load_tile = [&](int kv, int s) {
        const uint32_t Kh = KV0 + (uint32_t)s * KV_STAGE_B;
        #pragma unroll
        for (int i = 0; i < 2; i++) {
            const int slot = t + i*256;
            const int r  = slot >> 3;
            const int c8 = (slot & 7) * 8;
            const uint32_t so = (uint32_t)(r * ALD + c8) * 2;
            CP16(Kh + 0*AK_B + so, Khg + (size_t)(kv + r)*HD + c8);
            CP16(Kh + 1*AK_B + so, Klg + (size_t)(kv + r)*HD + c8);
            CP16(Kh + 2*AK_B + so, Vhg + (size_t)r*Ss + kv + c8);
            CP16(Kh + 3*AK_B + so, Vlg + (size_t)r*Ss + kv + c8);
        }
    };

    load_tile(0, 0);
    CP_COMMIT();

    float m_i[2], l_i[2];
    float O[8][4];
    m_i[0] = m_i[1] = -1e30f;
    l_i[0] = l_i[1] = 0.f;
    #pragma unroll
    for (int nf = 0; nf < 8; nf++)
        #pragma unroll
        for (int j = 0; j < 4; j++) O[nf][j] = 0.f;

    const int NTILE = Ss / 64;
    for (int n = 0; n < NTILE; n++) {
        const int s = n & 1;
        CP_WAIT0();
        __syncthreads();
        if (n + 1 < NTILE) { load_tile((n + 1) * 64, s ^ 1); CP_COMMIT(); }

        const uint32_t Kh = KV0 + (uint32_t)s * KV_STAGE_B;
        const uint32_t Kl = Kh + AK_B;
        const uint32_t Vh = Kl + AK_B;
        const uint32_t Vl = Vh + AK_B;

        // ---- S = Q K^T (x3 split), Q from registers ----
        float S[8][4];
        #pragma unroll
        for (int nf = 0; nf < 8; nf++)
            #pragma unroll
            for (int j = 0; j < 4; j++) S[nf][j] = 0.f;

        #pragma unroll
        for (int ks = 0; ks < 4; ks++) {
            const int k0 = ks * 16;
            uint32_t bF[4][4];
            #pragma unroll
            for (int q = 0; q < 4; q++) {
                ldsm4(bF[q], Kh + (uint32_t)((q*16 + bRow)*ALD + k0 + bCol) * 2);
                mma16816(S[2*q+0], qH[ks], bF[q][0], bF[q][1]);
                mma16816(S[2*q+1], qH[ks], bF[q][2], bF[q][3]);
                mma16816(S[2*q+0], qL[ks], bF[q][0], bF[q][1]);
                mma16816(S[2*q+1], qL[ks], bF[q][2], bF[q][3]);
            }
            #pragma unroll
            for (int q = 0; q < 4; q++) {
                ldsm4(bF[q], Kl + (uint32_t)((q*16 + bRow)*ALD + k0 + bCol) * 2);
                mma16816(S[2*q+0], qH[ks], bF[q][0], bF[q][1]);
                mma16816(S[2*q+1], qH[ks], bF[q][2], bF[q][3]);
            }
        }

        // ---- online softmax ----
        #pragma unroll
        for (int nf = 0; nf < 8; nf++)
            #pragma unroll
            for (int j = 0; j < 4; j++) S[nf][j] *= 0.125f;

        #pragma unroll
        for (int h = 0; h < 2; h++) {
            float mx = -1e30f;
            #pragma unroll
            for (int nf = 0; nf < 8; nf++)
                mx = fmaxf(mx, fmaxf(S[nf][2*h], S[nf][2*h+1]));
            mx = fmaxf(mx, __shfl_xor_sync(0xffffffffu, mx, 1));
            mx = fmaxf(mx, __shfl_xor_sync(0xffffffffu, mx, 2));
            const float mn    = fmaxf(m_i[h], mx);
            const float alpha = __expf(m_i[h] - mn);
            float ps = 0.f;
            #pragma unroll
            for (int nf = 0; nf < 8; nf++) {
                float p0 = __expf(S[nf][2*h]   - mn);
                float p1 = __expf(S[nf][2*h+1] - mn);
                S[nf][2*h] = p0; S[nf][2*h+1] = p1;
                ps += p0 + p1;
            }
            ps += __shfl_xor_sync(0xffffffffu, ps, 1);
            ps += __shfl_xor_sync(0xffffffffu, ps, 2);
            m_i[h] = mn;
            l_i[h] = l_i[h]*alpha + ps;
            #pragma unroll
            for (int nf = 0; nf < 8; nf++) {
                O[nf][2*h]   *= alpha;
                O[nf][2*h+1] *= alpha;
            }
        }

        // ---- O += P V (P in registers, x3 split) ----
        #pragma unroll
        for (int ks = 0; ks < 4; ks++) {
            uint32_t aP[4], aPl[4];
            aP[0]  = pack_hi(S[2*ks][0],   S[2*ks][1]);
            aP[1]  = pack_hi(S[2*ks][2],   S[2*ks][3]);
            aP[2]  = pack_hi(S[2*ks+1][0], S[2*ks+1][1]);
            aP[3]  = pack_hi(S[2*ks+1][2], S[2*ks+1][3]);
            aPl[0] = pack_lo(S[2*ks][0],   S[2*ks][1]);
            aPl[1] = pack_lo(S[2*ks][2],   S[2*ks][3]);
            aPl[2] = pack_lo(S[2*ks+1][0], S[2*ks+1][1]);
            aPl[3] = pack_lo(S[2*ks+1][2], S[2*ks+1][3]);
            const int k0 = ks * 16;
            #pragma unroll
            for (int q = 0; q < 4; q++) {
                uint32_t bb[4];
                ldsm4(bb, Vh + (uint32_t)((q*16 + bRow)*ALD + k0 + bCol) * 2);
                mma16816(O[2*q+0], aP,  bb[0], bb[1]);
                mma16816(O[2*q+1], aP,  bb[2], bb[3]);
                mma16816(O[2*q+0], aPl, bb[0], bb[1]);
                mma16816(O[2*q+1], aPl, bb[2], bb[3]);
                ldsm4(bb, Vl + (uint32_t)((q*16 + bRow)*ALD + k0 + bCol) * 2);
                mma16816(O[2*q+0], aP, bb[0], bb[1]);
                mma16816(O[2*q+1], aP, bb[2], bb[3]);
            }
        }
    }

    // Normalize + write SPLIT ctx [b, s, h*64 + d]
    const int b_idx = bh >> 4;
    const int hidx  = bh & 15;
    #pragma unroll
    for (int h = 0; h < 2; h++) {
        const int s_idx = q0 + warp*16 + (lane >> 2) + h*8;
        const float inv = 1.f / l_i[h];
        #pragma unroll
        for (int nf = 0; nf < 8; nf++) {
            const int d0 = nf*8 + (lane & 3)*2;
            const size_t o = ((size_t)b_idx*Ss + s_idx)*Dd + hidx*HD + d0;
            const float x = O[nf][2*h] * inv;
            const float y = O[nf][2*h+1] * inv;
            *(uint32_t*)&g_Ch[o] = pack_hi(x, y);
            *(uint32_t*)&g_Cl[o] = pack_lo(x, y);
        }
    }
}

// ---------------------------------------------------------------------------
extern "C" void kernel_launch(void* const* d_in, const int* in_sizes, int n_in,
                              void* d_out, int out_size)
{
    (void)in_sizes; (void)n_in; (void)out_size;
    const float* X  = (const float*)d_in[0];
    const float* Wq = (const float*)d_in[1];
    const float* bq = (const float*)d_in[2];
    const float* Wk = (const float*)d_in[3];
    const float* bk = (const float*)d_in[4];
    const float* Wv = (const float*)d_in[5];
    const float* bv = (const float*)d_in[6];
    const float* Wo = (const float*)d_in[7];
    const float* bo = (const float*)d_in[8];
    float* out = (float*)d_out;

    void *pXh, *pXl, *pWh, *pWl;
    cudaGetSymbolAddress(&pXh, g_Xh);
    cudaGetSymbolAddress(&pXl, g_Xl);
    cudaGetSymbolAddress(&pWh, g_Wh);
    cudaGetSymbolAddress(&pWl, g_Wl);
    __nv_bfloat16* Xh = (__nv_bfloat16*)pXh;
    __nv_bfloat16* Xl = (__nv_bfloat16*)pXl;
    __nv_bfloat16* Wh = (__nv_bfloat16*)pWh;
    __nv_bfloat16* Wl = (__nv_bfloat16*)pWl;
    const size_t WSZ = (size_t)Dd * Dd;

    cudaFuncSetAttribute(gemm_qkv, cudaFuncAttributeMaxDynamicSharedMemorySize, GEMM_SMEM);
    cudaFuncSetAttribute(gemm_o,   cudaFuncAttributeMaxDynamicSharedMemorySize, GEMM_SMEM);
    cudaFuncSetAttribute(attn_bf,  cudaFuncAttributeMaxDynamicSharedMemorySize, ATTN_SMEM);

    rope_table<<<(Ss*32)/256, 256>>>();
    split_f32<<<(int)(NE/4/256), 256>>>(X,  Xh, Xl, (int)(NE/4));
    split_f32<<<(int)(WSZ/4/256), 256>>>(Wq, Wh + 0*WSZ, Wl + 0*WSZ, (int)(WSZ/4));
    split_f32<<<(int)(WSZ/4/256), 256>>>(Wk, Wh + 1*WSZ, Wl + 1*WSZ, (int)(WSZ/4));
    split_f32<<<(int)(WSZ/4/256), 256>>>(Wv, Wh + 2*WSZ, Wl + 2*WSZ, (int)(WSZ/4));
    split_f32<<<(int)(WSZ/4/256), 256>>>(Wo, Wh + 3*WSZ, Wl + 3*WSZ, (int)(WSZ/4));

    gemm_qkv<<<dim3(Dd/128, MM/128, 3), 256, GEMM_SMEM>>>(bq, bk, bv);

    split_v_trans<<<dim3(Ss/64, BH), 256>>>();

    attn_bf<<<dim3(Ss/128, BH), 256, ATTN_SMEM>>>();

    gemm_o<<<dim3(Dd/128, MM/128), 256, GEMM_SMEM>>>(bo, out);
}

// round 8
// speedup vs baseline: 3.5665x; 1.0209x over previous
#include <cuda_runtime.h>
#include <cuda_bf16.h>
#include <math.h>
#include <stdint.h>

// Problem constants
#define Bb  4
#define Ss  2048
#define Dd  1024
#define Hh  16
#define HD  64
#define BH  (Bb*Hh)     // 64
#define MM  (Bb*Ss)     // 8192
#define NE  ((size_t)MM*Dd)
#define WSZ ((size_t)Dd*Dd)

// Scratch (device globals -> no allocation)
__device__ float g_sin[Ss*32];
__device__ float g_cos[Ss*32];
__device__ __nv_bfloat16 g_Xh[NE],  g_Xl[NE];
__device__ __nv_bfloat16 g_Wh[4*WSZ], g_Wl[4*WSZ];
__device__ __nv_bfloat16 g_Qh[NE],  g_Ql[NE]; // roped Q split [b,h,s,hd]
__device__ __nv_bfloat16 g_Kh[NE],  g_Kl[NE]; // roped K split [b,h,s,hd]
__device__ __nv_bfloat16 g_Vth[NE], g_Vtl[NE];// V split transposed [b,h,d,s]
__device__ __nv_bfloat16 g_Ch[NE],  g_Cl[NE]; // ctx split [b,s,D]

__device__ __forceinline__ uint32_t smem_u32(const void* p) {
    uint32_t a;
    asm("{ .reg .u64 t; cvta.to.shared.u64 t, %1; cvt.u32.u64 %0, t; }" : "=r"(a) : "l"(p));
    return a;
}
__device__ __forceinline__ void ldsm4(uint32_t (&r)[4], uint32_t addr) {
    asm volatile("ldmatrix.sync.aligned.m8n8.x4.shared.b16 {%0,%1,%2,%3}, [%4];"
        : "=r"(r[0]), "=r"(r[1]), "=r"(r[2]), "=r"(r[3]) : "r"(addr));
}
__device__ __forceinline__ void mma16816(float (&d)[4], const uint32_t (&a)[4],
                                         uint32_t b0, uint32_t b1) {
    asm volatile("mma.sync.aligned.m16n8k16.row.col.f32.bf16.bf16.f32 "
        "{%0,%1,%2,%3}, {%4,%5,%6,%7}, {%8,%9}, {%0,%1,%2,%3};"
        : "+f"(d[0]), "+f"(d[1]), "+f"(d[2]), "+f"(d[3])
        : "r"(a[0]), "r"(a[1]), "r"(a[2]), "r"(a[3]), "r"(b0), "r"(b1));
}
__device__ __forceinline__ uint32_t pack_hi(float x, float y) {
    __nv_bfloat162 h; h.x = __float2bfloat16_rn(x); h.y = __float2bfloat16_rn(y);
    return *(uint32_t*)&h;
}
__device__ __forceinline__ uint32_t pack_lo(float x, float y) {
    __nv_bfloat16 hx = __float2bfloat16_rn(x), hy = __float2bfloat16_rn(y);
    __nv_bfloat162 l;
    l.x = __float2bfloat16_rn(x - __bfloat162float(hx));
    l.y = __float2bfloat16_rn(y - __bfloat162float(hy));
    return *(uint32_t*)&l;
}
#define CP16(sm_addr, gptr) \
    asm volatile("cp.async.cg.shared.global [%0], [%1], 16;" :: "r"(sm_addr), "l"(gptr))
#define CP_COMMIT() asm volatile("cp.async.commit_group;" ::: "memory")
#define CP_WAIT0()  asm volatile("cp.async.wait_group 0;"  ::: "memory")

// ============================================================================
__global__ void rope_table()
{
    const int tid = blockIdx.x * blockDim.x + threadIdx.x;
    if (tid >= Ss * 32) return;
    const int s = tid >> 5;
    const int i = tid & 31;
    const double freq = exp(-((double)(2 * i) / 64.0) * 9.210340371976184);
    const float  argf = (float)s * (float)freq;
    const double a    = (double)argf;
    g_sin[tid] = (float)sin(a);
    g_cos[tid] = (float)cos(a);
}

// One kernel splits X and all four weights: index space = (NE + 4*WSZ)/4 float4s
__global__ void split_all(const float* __restrict__ X,
                          const float* __restrict__ Wq, const float* __restrict__ Wk,
                          const float* __restrict__ Wv, const float* __restrict__ Wo)
{
    const size_t i = (size_t)blockIdx.x * blockDim.x + threadIdx.x;
    const size_t NX4 = NE / 4;          // 2097152
    const size_t NW4 = WSZ / 4;         // 262144 = 2^18
    const float* src;
    __nv_bfloat16 *dh, *dl;
    size_t off;
    if (i < NX4) {
        src = X; dh = g_Xh; dl = g_Xl; off = i;
    } else {
        const size_t j = i - NX4;
        const int    w = (int)(j >> 18);
        off = j & (NW4 - 1);
        src = (w == 0) ? Wq : (w == 1) ? Wk : (w == 2) ? Wv : Wo;
        dh = g_Wh + (size_t)w * WSZ;
        dl = g_Wl + (size_t)w * WSZ;
    }
    float4 v = ((const float4*)src)[off];
    uint2 h, l;
    h.x = pack_hi(v.x, v.y); h.y = pack_hi(v.z, v.w);
    l.x = pack_lo(v.x, v.y); l.y = pack_lo(v.z, v.w);
    ((uint2*)dh)[off] = h;
    ((uint2*)dl)[off] = l;
}

// ============================================================================
// Fused QKV GEMM. Epilogue: Q/K -> RoPE + split bf16 [b,h,s,hd];
//                           V -> split bf16 TRANSPOSED [b,h,d,s].
// ============================================================================
#define LDA 40
#define TILE_B (128*LDA*2)
#define STAGE_B (4*TILE_B)
#define GEMM_SMEM (2*STAGE_B)  // 81920

__global__ __launch_bounds__(256, 2)
void gemm_qkv(const float* __restrict__ bq, const float* __restrict__ bk,
              const float* __restrict__ bv)
{
    extern __shared__ char smc[];
    const uint32_t sb = smem_u32(smc);
    const int t    = threadIdx.x;
    const int lane = t & 31;
    const int warp = t >> 5;
    const int wm   = warp >> 1;
    const int wn   = warp & 1;
    const int bn   = blockIdx.x * 128;
    const int bm   = blockIdx.y * 128;
    const int widx = blockIdx.z;

    const __nv_bfloat16* Ahg = g_Xh;
    const __nv_bfloat16* Alg = g_Xl;
    const __nv_bfloat16* Bhg = g_Wh + (size_t)widx * WSZ;
    const __nv_bfloat16* Blg = g_Wl + (size_t)widx * WSZ;
    const float* bias = (widx == 0) ? bq : (widx == 1 ? bk : bv);

    float acc[2][8][4];
    #pragma unroll
    for (int mt = 0; mt < 2; mt++)
        #pragma unroll
        for (int nt = 0; nt < 8; nt++)
            #pragma unroll
            for (int j = 0; j < 4; j++) acc[mt][nt][j] = 0.f;

    const int lr0 = t >> 2;
    const int lc  = (t & 3) * 8;

    auto load_stage = [&](int s, int kc) {
        const uint32_t base = sb + (uint32_t)s * STAGE_B;
        #pragma unroll
        for (int i = 0; i < 2; i++) {
            const int r = lr0 + i * 64;
            const uint32_t so = (uint32_t)(r * LDA + lc) * 2;
            CP16(base + 0*TILE_B + so, Ahg + (size_t)(bm + r)*Dd + kc + lc);
            CP16(base + 1*TILE_B + so, Alg + (size_t)(bm + r)*Dd + kc + lc);
            CP16(base + 2*TILE_B + so, Bhg + (size_t)(bn + r)*Dd + kc + lc);
            CP16(base + 3*TILE_B + so, Blg + (size_t)(bn + r)*Dd + kc + lc);
        }
    };

    load_stage(0, 0);
    CP_COMMIT();
    CP_WAIT0();
    __syncthreads();

    const int g8 = lane >> 3;
    const int l8 = lane & 7;
    const int aRow = (g8 & 1) * 8 + l8;
    const int aCol = (g8 >> 1) * 8;
    const int bRow = (g8 >> 1) * 8 + l8;
    const int bCol = (g8 & 1) * 8;

    const int NT = Dd / 32;
    for (int kt = 0; kt < NT; kt++) {
        const int s = kt & 1;
        const int last = (kt + 1 == NT);
        if (!last) { load_stage(s ^ 1, (kt + 1) * 32); CP_COMMIT(); }

        const uint32_t Ah = sb + (uint32_t)s * STAGE_B;
        const uint32_t Al = Ah + TILE_B;
        const uint32_t Bh = Ah + 2*TILE_B;
        const uint32_t Bl = Ah + 3*TILE_B;

        #pragma unroll
        for (int ks = 0; ks < 2; ks++) {
            const int k0 = ks * 16;
            uint32_t aH[2][4], aL[2][4], bF[4][4];
            #pragma unroll
            for (int mt = 0; mt < 2; mt++) {
                ldsm4(aH[mt], Ah + (uint32_t)((wm*32 + mt*16 + aRow) * LDA + k0 + aCol) * 2);
                ldsm4(aL[mt], Al + (uint32_t)((wm*32 + mt*16 + aRow) * LDA + k0 + aCol) * 2);
            }
            #pragma unroll
            for (int q = 0; q < 4; q++)
                ldsm4(bF[q], Bh + (uint32_t)((wn*64 + q*16 + bRow) * LDA + k0 + bCol) * 2);
            #pragma unroll
            for (int mt = 0; mt < 2; mt++)
                #pragma unroll
                for (int q = 0; q < 4; q++) {
                    mma16816(acc[mt][q*2+0], aH[mt], bF[q][0], bF[q][1]);
                    mma16816(acc[mt][q*2+1], aH[mt], bF[q][2], bF[q][3]);
                }
            #pragma unroll
            for (int mt = 0; mt < 2; mt++)
                #pragma unroll
                for (int q = 0; q < 4; q++) {
                    mma16816(acc[mt][q*2+0], aL[mt], bF[q][0], bF[q][1]);
                    mma16816(acc[mt][q*2+1], aL[mt], bF[q][2], bF[q][3]);
                }
            #pragma unroll
            for (int q = 0; q < 4; q++)
                ldsm4(bF[q], Bl + (uint32_t)((wn*64 + q*16 + bRow) * LDA + k0 + bCol) * 2);
            #pragma unroll
            for (int mt = 0; mt < 2; mt++)
                #pragma unroll
                for (int q = 0; q < 4; q++) {
                    mma16816(acc[mt][q*2+0], aH[mt], bF[q][0], bF[q][1]);
                    mma16816(acc[mt][q*2+1], aH[mt], bF[q][2], bF[q][3]);
                }
        }

        if (!last) { CP_WAIT0(); __syncthreads(); }
    }

    // Epilogue
    const int lane2 = (lane & 3) * 2;
    #pragma unroll
    for (int mt = 0; mt < 2; mt++) {
        #pragma unroll
        for (int half = 0; half < 2; half++) {
            const int m  = bm + wm*32 + mt*16 + (lane >> 2) + half*8;
            const int bi = m >> 11;
            const int si = m & (Ss - 1);
            if (widx == 2) {
                // V: split + transpose to [b,h,d,s]
                #pragma unroll
                for (int nt = 0; nt < 8; nt++) {
                    const int e0 = bn + wn*64 + nt*8 + lane2;
                    const int h  = e0 >> 6;
                    const int d0 = e0 & 63;
                    const float x = acc[mt][nt][half*2+0] + bias[e0];
                    const float y = acc[mt][nt][half*2+1] + bias[e0+1];
                    __nv_bfloat16 hx = __float2bfloat16_rn(x);
                    __nv_bfloat16 hy = __float2bfloat16_rn(y);
                    __nv_bfloat16 lx = __float2bfloat16_rn(x - __bfloat162float(hx));
                    __nv_bfloat16 ly = __float2bfloat16_rn(y - __bfloat162float(hy));
                    const size_t o0 = (((size_t)bi*Hh + h)*HD + d0)*Ss + si;
                    g_Vth[o0]      = hx;
                    g_Vth[o0 + Ss] = hy;
                    g_Vtl[o0]      = lx;
                    g_Vtl[o0 + Ss] = ly;
                }
            } else {
                __nv_bfloat16* dh = widx ? g_Kh : g_Qh;
                __nv_bfloat16* dl = widx ? g_Kl : g_Ql;
                #pragma unroll
                for (int nt = 0; nt < 4; nt++) {
                    const int e0 = bn + wn*64 + nt*8 + lane2;  // d0 < 32 within head
                    const int h  = e0 >> 6;
                    const int d0 = e0 & 63;
                    float x1a = acc[mt][nt][half*2+0]   + bias[e0];
                    float x1b = acc[mt][nt][half*2+1]   + bias[e0+1];
                    float x2a = acc[mt][nt+4][half*2+0] + bias[e0+32];
                    float x2b = acc[mt][nt+4][half*2+1] + bias[e0+33];
                    const float2 sv = *(const float2*)&g_sin[si*32 + d0];
                    const float2 cv = *(const float2*)&g_cos[si*32 + d0];
                    // reference naming swap: out1 = x1*sin - x2*cos ; out2 = x2*sin + x1*cos
                    float o1a = x1a*sv.x - x2a*cv.x, o1b = x1b*sv.y - x2b*cv.y;
                    float o2a = x2a*sv.x + x1a*cv.x, o2b = x2b*sv.y + x1b*cv.y;
                    const size_t o = (((size_t)bi*Hh + h)*Ss + si)*HD + d0;
                    *(uint32_t*)&dh[o]      = pack_hi(o1a, o1b);
                    *(uint32_t*)&dl[o]      = pack_lo(o1a, o1b);
                    *(uint32_t*)&dh[o + 32] = pack_hi(o2a, o2b);
                    *(uint32_t*)&dl[o + 32] = pack_lo(o2a, o2b);
                }
            }
        }
    }
}

// ============================================================================
// O-projection GEMM (row-major fp32 out to d_out)
// ============================================================================
__global__ __launch_bounds__(256, 2)
void gemm_o(const float* __restrict__ bias, float* __restrict__ out)
{
    extern __shared__ char smc[];
    const uint32_t sb = smem_u32(smc);
    const int t    = threadIdx.x;
    const int lane = t & 31;
    const int warp = t >> 5;
    const int wm   = warp >> 1;
    const int wn   = warp & 1;
    const int bn   = blockIdx.x * 128;
    const int bm   = blockIdx.y * 128;

    const __nv_bfloat16* Ahg = g_Ch;
    const __nv_bfloat16* Alg = g_Cl;
    const __nv_bfloat16* Bhg = g_Wh + 3*WSZ;
    const __nv_bfloat16* Blg = g_Wl + 3*WSZ;

    float acc[2][8][4];
    #pragma unroll
    for (int mt = 0; mt < 2; mt++)
        #pragma unroll
        for (int nt = 0; nt < 8; nt++)
            #pragma unroll
            for (int j = 0; j < 4; j++) acc[mt][nt][j] = 0.f;

    const int lr0 = t >> 2;
    const int lc  = (t & 3) * 8;

    auto load_stage = [&](int s, int kc) {
        const uint32_t base = sb + (uint32_t)s * STAGE_B;
        #pragma unroll
        for (int i = 0; i < 2; i++) {
            const int r = lr0 + i * 64;
            const uint32_t so = (uint32_t)(r * LDA + lc) * 2;
            CP16(base + 0*TILE_B + so, Ahg + (size_t)(bm + r)*Dd + kc + lc);
            CP16(base + 1*TILE_B + so, Alg + (size_t)(bm + r)*Dd + kc + lc);
            CP16(base + 2*TILE_B + so, Bhg + (size_t)(bn + r)*Dd + kc + lc);
            CP16(base + 3*TILE_B + so, Blg + (size_t)(bn + r)*Dd + kc + lc);
        }
    };

    load_stage(0, 0);
    CP_COMMIT();
    CP_WAIT0();
    __syncthreads();

    const int g8 = lane >> 3;
    const int l8 = lane & 7;
    const int aRow = (g8 & 1) * 8 + l8;
    const int aCol = (g8 >> 1) * 8;
    const int bRow = (g8 >> 1) * 8 + l8;
    const int bCol = (g8 & 1) * 8;

    const int NT = Dd / 32;
    for (int kt = 0; kt < NT; kt++) {
        const int s = kt & 1;
        const int last = (kt + 1 == NT);
        if (!last) { load_stage(s ^ 1, (kt + 1) * 32); CP_COMMIT(); }

        const uint32_t Ah = sb + (uint32_t)s * STAGE_B;
        const uint32_t Al = Ah + TILE_B;
        const uint32_t Bh = Ah + 2*TILE_B;
        const uint32_t Bl = Ah + 3*TILE_B;

        #pragma unroll
        for (int ks = 0; ks < 2; ks++) {
            const int k0 = ks * 16;
            uint32_t aH[2][4], aL[2][4], bF[4][4];
            #pragma unroll
            for (int mt = 0; mt < 2; mt++) {
                ldsm4(aH[mt], Ah + (uint32_t)((wm*32 + mt*16 + aRow) * LDA + k0 + aCol) * 2);
                ldsm4(aL[mt], Al + (uint32_t)((wm*32 + mt*16 + aRow) * LDA + k0 + aCol) * 2);
            }
            #pragma unroll
            for (int q = 0; q < 4; q++)
                ldsm4(bF[q], Bh + (uint32_t)((wn*64 + q*16 + bRow) * LDA + k0 + bCol) * 2);
            #pragma unroll
            for (int mt = 0; mt < 2; mt++)
                #pragma unroll
                for (int q = 0; q < 4; q++) {
                    mma16816(acc[mt][q*2+0], aH[mt], bF[q][0], bF[q][1]);
                    mma16816(acc[mt][q*2+1], aH[mt], bF[q][2], bF[q][3]);
                }
            #pragma unroll
            for (int mt = 0; mt < 2; mt++)
                #pragma unroll
                for (int q = 0; q < 4; q++) {
                    mma16816(acc[mt][q*2+0], aL[mt], bF[q][0], bF[q][1]);
                    mma16816(acc[mt][q*2+1], aL[mt], bF[q][2], bF[q][3]);
                }
            #pragma unroll
            for (int q = 0; q < 4; q++)
                ldsm4(bF[q], Bl + (uint32_t)((wn*64 + q*16 + bRow) * LDA + k0 + bCol) * 2);
            #pragma unroll
            for (int mt = 0; mt < 2; mt++)
                #pragma unroll
                for (int q = 0; q < 4; q++) {
                    mma16816(acc[mt][q*2+0], aH[mt], bF[q][0], bF[q][1]);
                    mma16816(acc[mt][q*2+1], aH[mt], bF[q][2], bF[q][3]);
                }
        }

        if (!last) { CP_WAIT0(); __syncthreads(); }
    }

    #pragma unroll
    for (int mt = 0; mt < 2; mt++) {
        #pragma unroll
        for (int half = 0; half < 2; half++) {
            const int m = bm + wm*32 + mt*16 + (lane >> 2) + half*8;
            #pragma unroll
            for (int nt = 0; nt < 8; nt++) {
                const int e0 = bn + wn*64 + nt*8 + (lane & 3)*2;
                float2 r;
                r.x = acc[mt][nt][half*2+0] + bias[e0];
                r.y = acc[mt][nt][half*2+1] + bias[e0+1];
                *(float2*)&out[(size_t)m*Dd + e0] = r;
            }
        }
    }
}

// ============================================================================
// Flash attention: Q resident in smem (hi+lo), occ 2, double-buffered K/V.
// ============================================================================
#define ALD 72
#define AQ_B (128*ALD*2)       // 18432
#define AK_B (64*ALD*2)        // 9216
#define KV_STAGE_B (4*AK_B)    // 36864
#define ATTN_SMEM (2*AQ_B + 2*KV_STAGE_B)   // 110592

__global__ __launch_bounds__(256, 2)
void attn_bf()
{
    extern __shared__ char smc[];
    const uint32_t sb  = smem_u32(smc);
    const uint32_t Qh  = sb;
    const uint32_t Ql  = sb + AQ_B;
    const uint32_t KV0 = sb + 2*AQ_B;

    const int t    = threadIdx.x;
    const int lane = t & 31;
    const int warp = t >> 5;
    const int bh   = blockIdx.y;
    const int q0   = blockIdx.x * 128;

    const __nv_bfloat16* Qhg = g_Qh + ((size_t)bh*Ss + q0)*HD;
    const __nv_bfloat16* Qlg = g_Ql + ((size_t)bh*Ss + q0)*HD;
    const __nv_bfloat16* Khg = g_Kh + (size_t)bh*Ss*HD;
    const __nv_bfloat16* Klg = g_Kl + (size_t)bh*Ss*HD;
    const __nv_bfloat16* Vhg = g_Vth + (size_t)bh*HD*Ss;
    const __nv_bfloat16* Vlg = g_Vtl + (size_t)bh*HD*Ss;

    auto load_tile = [&](int kv, int s) {
        const uint32_t Kh = KV0 + (uint32_t)s * KV_STAGE_B;
        #pragma unroll
        for (int i = 0; i < 2; i++) {
            const int slot = t + i*256;
            const int r  = slot >> 3;
            const int c8 = (slot & 7) * 8;
            const uint32_t so = (uint32_t)(r * ALD + c8) * 2;
            CP16(Kh + 0*AK_B + so, Khg + (size_t)(kv + r)*HD + c8);
            CP16(Kh + 1*AK_B + so, Klg + (size_t)(kv + r)*HD + c8);
            CP16(Kh + 2*AK_B + so, Vhg + (size_t)r*Ss + kv + c8);
            CP16(Kh + 3*AK_B + so, Vlg + (size_t)r*Ss + kv + c8);
        }
    };

    // Q tile (hi+lo) -> smem, plus first KV tile
    #pragma unroll
    for (int i = 0; i < 4; i++) {
        const int slot = t + i*256;
        const int r  = slot >> 3;
        const int c8 = (slot & 7) * 8;
        const uint32_t so = (uint32_t)(r * ALD + c8) * 2;
        CP16(Qh + so, Qhg + (size_t)r*HD + c8);
        CP16(Ql + so, Qlg + (size_t)r*HD + c8);
    }
    load_tile(0, 0);
    CP_COMMIT();

    const int g8 = lane >> 3;
    const int l8 = lane & 7;
    const int aRow = (g8 & 1) * 8 + l8;
    const int aCol = (g8 >> 1) * 8;
    const int bRow = (g8 >> 1) * 8 + l8;
    const int bCol = (g8 & 1) * 8;

    float m_i[2], l_i[2];
    float O[8][4];
    m_i[0] = m_i[1] = -1e30f;
    l_i[0] = l_i[1] = 0.f;
    #pragma unroll
    for (int nf = 0; nf < 8; nf++)
        #pragma unroll
        for (int j = 0; j < 4; j++) O[nf][j] = 0.f;

    const int NTILE = Ss / 64;
    for (int n = 0; n < NTILE; n++) {
        const int s = n & 1;
        CP_WAIT0();
        __syncthreads();
        if (n + 1 < NTILE) { load_tile((n + 1) * 64, s ^ 1); CP_COMMIT(); }

        const uint32_t Kh = KV0 + (uint32_t)s * KV_STAGE_B;
        const uint32_t Kl = Kh + AK_B;
        const uint32_t Vh = Kl + AK_B;
        const uint32_t Vl = Vh + AK_B;

        // ---- S = Q K^T (x3 split) ----
        float S[8][4];
        #pragma unroll
        for (int nf = 0; nf < 8; nf++)
            #pragma unroll
            for (int j = 0; j < 4; j++) S[nf][j] = 0.f;

        #pragma unroll
        for (int ks = 0; ks < 4; ks++) {
            const int k0 = ks * 16;
            uint32_t aH[4], aL[4], bF[4][4];
            ldsm4(aH, Qh + (uint32_t)((warp*16 + aRow)*ALD + k0 + aCol) * 2);
            ldsm4(aL, Ql + (uint32_t)((warp*16 + aRow)*ALD + k0 + aCol) * 2);
            #pragma unroll
            for (int q = 0; q < 4; q++) {
                ldsm4(bF[q], Kh + (uint32_t)((q*16 + bRow)*ALD + k0 + bCol) * 2);
                mma16816(S[2*q+0], aH, bF[q][0], bF[q][1]);
                mma16816(S[2*q+1], aH, bF[q][2], bF[q][3]);
                mma16816(S[2*q+0], aL, bF[q][0], bF[q][1]);
                mma16816(S[2*q+1], aL, bF[q][2], bF[q][3]);
            }
            #pragma unroll
            for (int q = 0; q < 4; q++) {
                ldsm4(bF[q], Kl + (uint32_t)((q*16 + bRow)*ALD + k0 + bCol) * 2);
                mma16816(S[2*q+0], aH, bF[q][0], bF[q][1]);
                mma16816(S[2*q+1], aH, bF[q][2], bF[q][3]);
            }
        }

        // ---- online softmax ----
        #pragma unroll
        for (int nf = 0; nf < 8; nf++)
            #pragma unroll
            for (int j = 0; j < 4; j++) S[nf][j] *= 0.125f;

        #pragma unroll
        for (int h = 0; h < 2; h++) {
            float mx = -1e30f;
            #pragma unroll
            for (int nf = 0; nf < 8; nf++)
                mx = fmaxf(mx, fmaxf(S[nf][2*h], S[nf][2*h+1]));
            mx = fmaxf(mx, __shfl_xor_sync(0xffffffffu, mx, 1));
            mx = fmaxf(mx, __shfl_xor_sync(0xffffffffu, mx, 2));
            const float mn    = fmaxf(m_i[h], mx);
            const float alpha = __expf(m_i[h] - mn);
            float ps = 0.f;
            #pragma unroll
            for (int nf = 0; nf < 8; nf++) {
                float p0 = __expf(S[nf][2*h]   - mn);
                float p1 = __expf(S[nf][2*h+1] - mn);
                S[nf][2*h] = p0; S[nf][2*h+1] = p1;
                ps += p0 + p1;
            }
            ps += __shfl_xor_sync(0xffffffffu, ps, 1);
            ps += __shfl_xor_sync(0xffffffffu, ps, 2);
            m_i[h] = mn;
            l_i[h] = l_i[h]*alpha + ps;
            #pragma unroll
            for (int nf = 0; nf < 8; nf++) {
                O[nf][2*h]   *= alpha;
                O[nf][2*h+1] *= alpha;
            }
        }

        // ---- O += P V (P in registers, x3 split) ----
        #pragma unroll
        for (int ks = 0; ks < 4; ks++) {
            uint32_t aP[4], aPl[4];
            aP[0]  = pack_hi(S[2*ks][0],   S[2*ks][1]);
            aP[1]  = pack_hi(S[2*ks][2],   S[2*ks][3]);
            aP[2]  = pack_hi(S[2*ks+1][0], S[2*ks+1][1]);
            aP[3]  = pack_hi(S[2*ks+1][2], S[2*ks+1][3]);
            aPl[0] = pack_lo(S[2*ks][0],   S[2*ks][1]);
            aPl[1] = pack_lo(S[2*ks][2],   S[2*ks][3]);
            aPl[2] = pack_lo(S[2*ks+1][0], S[2*ks+1][1]);
            aPl[3] = pack_lo(S[2*ks+1][2], S[2*ks+1][3]);
            const int k0 = ks * 16;
            #pragma unroll
            for (int q = 0; q < 4; q++) {
                uint32_t bb[4];
                ldsm4(bb, Vh + (uint32_t)((q*16 + bRow)*ALD + k0 + bCol) * 2);
                mma16816(O[2*q+0], aP,  bb[0], bb[1]);
                mma16816(O[2*q+1], aP,  bb[2], bb[3]);
                mma16816(O[2*q+0], aPl, bb[0], bb[1]);
                mma16816(O[2*q+1], aPl, bb[2], bb[3]);
                ldsm4(bb, Vl + (uint32_t)((q*16 + bRow)*ALD + k0 + bCol) * 2);
                mma16816(O[2*q+0], aP, bb[0], bb[1]);
                mma16816(O[2*q+1], aP, bb[2], bb[3]);
            }
        }
    }

    // Normalize + write SPLIT ctx [b, s, h*64 + d]
    const int b_idx = bh >> 4;
    const int hidx  = bh & 15;
    #pragma unroll
    for (int h = 0; h < 2; h++) {
        const int s_idx = q0 + warp*16 + (lane >> 2) + h*8;
        const float inv = 1.f / l_i[h];
        #pragma unroll
        for (int nf = 0; nf < 8; nf++) {
            const int d0 = nf*8 + (lane & 3)*2;
            const size_t o = ((size_t)b_idx*Ss + s_idx)*Dd + hidx*HD + d0;
            const float x = O[nf][2*h] * inv;
            const float y = O[nf][2*h+1] * inv;
            *(uint32_t*)&g_Ch[o] = pack_hi(x, y);
            *(uint32_t*)&g_Cl[o] = pack_lo(x, y);
        }
    }
}

// ---------------------------------------------------------------------------
extern "C" void kernel_launch(void* const* d_in, const int* in_sizes, int n_in,
                              void* d_out, int out_size)
{
    (void)in_sizes; (void)n_in; (void)out_size;
    const float* X  = (const float*)d_in[0];
    const float* Wq = (const float*)d_in[1];
    const float* bq = (const float*)d_in[2];
    const float* Wk = (const float*)d_in[3];
    const float* bk = (const float*)d_in[4];
    const float* Wv = (const float*)d_in[5];
    const float* bv = (const float*)d_in[6];
    const float* Wo = (const float*)d_in[7];
    const float* bo = (const float*)d_in[8];
    float* out = (float*)d_out;

    cudaFuncSetAttribute(gemm_qkv, cudaFuncAttributeMaxDynamicSharedMemorySize, GEMM_SMEM);
    cudaFuncSetAttribute(gemm_o,   cudaFuncAttributeMaxDynamicSharedMemorySize, GEMM_SMEM);
    cudaFuncSetAttribute(attn_bf,  cudaFuncAttributeMaxDynamicSharedMemorySize, ATTN_SMEM);

    rope_table<<<(Ss*32)/256, 256>>>();

    const int total4 = (int)((NE + 4*WSZ) / 4);     // 3145728
    split_all<<<total4/256, 256>>>(X, Wq, Wk, Wv, Wo);

    gemm_qkv<<<dim3(Dd/128, MM/128, 3), 256, GEMM_SMEM>>>(bq, bk, bv);

    attn_bf<<<dim3(Ss/128, BH), 256, ATTN_SMEM>>>();

    gemm_o<<<dim3(Dd/128, MM/128), 256, GEMM_SMEM>>>(bo, out);
}

// round 9
// speedup vs baseline: 3.5834x; 1.0047x over previous
#include <cuda_runtime.h>
#include <cuda_bf16.h>
#include <math.h>
#include <stdint.h>

// Problem constants
#define Bb  4
#define Ss  2048
#define Dd  1024
#define Hh  16
#define HD  64
#define BH  (Bb*Hh)     // 64
#define MM  (Bb*Ss)     // 8192
#define NE  ((size_t)MM*Dd)
#define WSZ ((size_t)Dd*Dd)

// scale folded into Q: 1/sqrt(64) * log2(e)
#define QSCL 0.18033688011112042f

// Scratch (device globals -> no allocation)
__device__ float g_sin[Ss*32];
__device__ float g_cos[Ss*32];
__device__ __nv_bfloat16 g_Xh[NE],  g_Xl[NE];
__device__ __nv_bfloat16 g_Wh[4*WSZ], g_Wl[4*WSZ];
__device__ __nv_bfloat16 g_Qh[NE],  g_Ql[NE]; // roped+scaled Q split [b,h,s,hd]
__device__ __nv_bfloat16 g_Kh[NE],  g_Kl[NE]; // roped K split [b,h,s,hd]
__device__ __nv_bfloat16 g_Vth[NE], g_Vtl[NE];// V split transposed [b,h,d,s]
__device__ __nv_bfloat16 g_Ch[NE],  g_Cl[NE]; // ctx split [b,s,D]

__device__ __forceinline__ uint32_t smem_u32(const void* p) {
    uint32_t a;
    asm("{ .reg .u64 t; cvta.to.shared.u64 t, %1; cvt.u32.u64 %0, t; }" : "=r"(a) : "l"(p));
    return a;
}
__device__ __forceinline__ void ldsm4(uint32_t (&r)[4], uint32_t addr) {
    asm volatile("ldmatrix.sync.aligned.m8n8.x4.shared.b16 {%0,%1,%2,%3}, [%4];"
        : "=r"(r[0]), "=r"(r[1]), "=r"(r[2]), "=r"(r[3]) : "r"(addr));
}
__device__ __forceinline__ void mma16816(float (&d)[4], const uint32_t (&a)[4],
                                         uint32_t b0, uint32_t b1) {
    asm volatile("mma.sync.aligned.m16n8k16.row.col.f32.bf16.bf16.f32 "
        "{%0,%1,%2,%3}, {%4,%5,%6,%7}, {%8,%9}, {%0,%1,%2,%3};"
        : "+f"(d[0]), "+f"(d[1]), "+f"(d[2]), "+f"(d[3])
        : "r"(a[0]), "r"(a[1]), "r"(a[2]), "r"(a[3]), "r"(b0), "r"(b1));
}
__device__ __forceinline__ uint32_t pack_hi(float x, float y) {
    __nv_bfloat162 h; h.x = __float2bfloat16_rn(x); h.y = __float2bfloat16_rn(y);
    return *(uint32_t*)&h;
}
__device__ __forceinline__ uint32_t pack_lo(float x, float y) {
    __nv_bfloat16 hx = __float2bfloat16_rn(x), hy = __float2bfloat16_rn(y);
    __nv_bfloat162 l;
    l.x = __float2bfloat16_rn(x - __bfloat162float(hx));
    l.y = __float2bfloat16_rn(y - __bfloat162float(hy));
    return *(uint32_t*)&l;
}
#define CP16(sm_addr, gptr) \
    asm volatile("cp.async.cg.shared.global [%0], [%1], 16;" :: "r"(sm_addr), "l"(gptr))
#define CP_COMMIT() asm volatile("cp.async.commit_group;" ::: "memory")
#define CP_WAIT0()  asm volatile("cp.async.wait_group 0;"  ::: "memory")

// ============================================================================
// One kernel: splits X + 4 weights AND builds the RoPE sin/cos table.
// ============================================================================
#define NB_SPLIT ((int)((NE + 4*WSZ) / 4 / 256))   // 12288
#define NB_TABLE ((Ss*32)/256)                     // 256

__global__ void split_all(const float* __restrict__ X,
                          const float* __restrict__ Wq, const float* __restrict__ Wk,
                          const float* __restrict__ Wv, const float* __restrict__ Wo)
{
    if (blockIdx.x >= NB_SPLIT) {
        // RoPE table blocks
        const int tid = (blockIdx.x - NB_SPLIT) * blockDim.x + threadIdx.x;
        const int s = tid >> 5;
        const int i = tid & 31;
        const double freq = exp(-((double)(2 * i) / 64.0) * 9.210340371976184);
        const float  argf = (float)s * (float)freq;
        const double a    = (double)argf;
        g_sin[tid] = (float)sin(a);
        g_cos[tid] = (float)cos(a);
        return;
    }
    const size_t i = (size_t)blockIdx.x * blockDim.x + threadIdx.x;
    const size_t NX4 = NE / 4;
    const size_t NW4 = WSZ / 4;         // 2^18
    const float* src;
    __nv_bfloat16 *dh, *dl;
    size_t off;
    if (i < NX4) {
        src = X; dh = g_Xh; dl = g_Xl; off = i;
    } else {
        const size_t j = i - NX4;
        const int    w = (int)(j >> 18);
        off = j & (NW4 - 1);
        src = (w == 0) ? Wq : (w == 1) ? Wk : (w == 2) ? Wv : Wo;
        dh = g_Wh + (size_t)w * WSZ;
        dl = g_Wl + (size_t)w * WSZ;
    }
    float4 v = ((const float4*)src)[off];
    uint2 h, l;
    h.x = pack_hi(v.x, v.y); h.y = pack_hi(v.z, v.w);
    l.x = pack_lo(v.x, v.y); l.y = pack_lo(v.z, v.w);
    ((uint2*)dh)[off] = h;
    ((uint2*)dl)[off] = l;
}

// ============================================================================
// Fused QKV GEMM. Epilogue: Q -> RoPE, pre-scale by QSCL, split bf16;
//                           K -> RoPE, split bf16;  V -> split + transpose.
// ============================================================================
#define LDA 40
#define TILE_B (128*LDA*2)
#define STAGE_B (4*TILE_B)
#define GEMM_SMEM (2*STAGE_B)  // 81920

__global__ __launch_bounds__(256, 2)
void gemm_qkv(const float* __restrict__ bq, const float* __restrict__ bk,
              const float* __restrict__ bv)
{
    extern __shared__ char smc[];
    const uint32_t sb = smem_u32(smc);
    const int t    = threadIdx.x;
    const int lane = t & 31;
    const int warp = t >> 5;
    const int wm   = warp >> 1;
    const int wn   = warp & 1;
    const int bn   = blockIdx.x * 128;
    const int bm   = blockIdx.y * 128;
    const int widx = blockIdx.z;

    const __nv_bfloat16* Ahg = g_Xh;
    const __nv_bfloat16* Alg = g_Xl;
    const __nv_bfloat16* Bhg = g_Wh + (size_t)widx * WSZ;
    const __nv_bfloat16* Blg = g_Wl + (size_t)widx * WSZ;
    const float* bias = (widx == 0) ? bq : (widx == 1 ? bk : bv);

    float acc[2][8][4];
    #pragma unroll
    for (int mt = 0; mt < 2; mt++)
        #pragma unroll
        for (int nt = 0; nt < 8; nt++)
            #pragma unroll
            for (int j = 0; j < 4; j++) acc[mt][nt][j] = 0.f;

    const int lr0 = t >> 2;
    const int lc  = (t & 3) * 8;

    auto load_stage = [&](int s, int kc) {
        const uint32_t base = sb + (uint32_t)s * STAGE_B;
        #pragma unroll
        for (int i = 0; i < 2; i++) {
            const int r = lr0 + i * 64;
            const uint32_t so = (uint32_t)(r * LDA + lc) * 2;
            CP16(base + 0*TILE_B + so, Ahg + (size_t)(bm + r)*Dd + kc + lc);
            CP16(base + 1*TILE_B + so, Alg + (size_t)(bm + r)*Dd + kc + lc);
            CP16(base + 2*TILE_B + so, Bhg + (size_t)(bn + r)*Dd + kc + lc);
            CP16(base + 3*TILE_B + so, Blg + (size_t)(bn + r)*Dd + kc + lc);
        }
    };

    load_stage(0, 0);
    CP_COMMIT();
    CP_WAIT0();
    __syncthreads();

    const int g8 = lane >> 3;
    const int l8 = lane & 7;
    const int aRow = (g8 & 1) * 8 + l8;
    const int aCol = (g8 >> 1) * 8;
    const int bRow = (g8 >> 1) * 8 + l8;
    const int bCol = (g8 & 1) * 8;

    const int NT = Dd / 32;
    for (int kt = 0; kt < NT; kt++) {
        const int s = kt & 1;
        const int last = (kt + 1 == NT);
        if (!last) { load_stage(s ^ 1, (kt + 1) * 32); CP_COMMIT(); }

        const uint32_t Ah = sb + (uint32_t)s * STAGE_B;
        const uint32_t Al = Ah + TILE_B;
        const uint32_t Bh = Ah + 2*TILE_B;
        const uint32_t Bl = Ah + 3*TILE_B;

        #pragma unroll
        for (int ks = 0; ks < 2; ks++) {
            const int k0 = ks * 16;
            uint32_t aH[2][4], aL[2][4], bF[4][4];
            #pragma unroll
            for (int mt = 0; mt < 2; mt++) {
                ldsm4(aH[mt], Ah + (uint32_t)((wm*32 + mt*16 + aRow) * LDA + k0 + aCol) * 2);
                ldsm4(aL[mt], Al + (uint32_t)((wm*32 + mt*16 + aRow) * LDA + k0 + aCol) * 2);
            }
            #pragma unroll
            for (int q = 0; q < 4; q++)
                ldsm4(bF[q], Bh + (uint32_t)((wn*64 + q*16 + bRow) * LDA + k0 + bCol) * 2);
            #pragma unroll
            for (int mt = 0; mt < 2; mt++)
                #pragma unroll
                for (int q = 0; q < 4; q++) {
                    mma16816(acc[mt][q*2+0], aH[mt], bF[q][0], bF[q][1]);
                    mma16816(acc[mt][q*2+1], aH[mt], bF[q][2], bF[q][3]);
                }
            #pragma unroll
            for (int mt = 0; mt < 2; mt++)
                #pragma unroll
                for (int q = 0; q < 4; q++) {
                    mma16816(acc[mt][q*2+0], aL[mt], bF[q][0], bF[q][1]);
                    mma16816(acc[mt][q*2+1], aL[mt], bF[q][2], bF[q][3]);
                }
            #pragma unroll
            for (int q = 0; q < 4; q++)
                ldsm4(bF[q], Bl + (uint32_t)((wn*64 + q*16 + bRow) * LDA + k0 + bCol) * 2);
            #pragma unroll
            for (int mt = 0; mt < 2; mt++)
                #pragma unroll
                for (int q = 0; q < 4; q++) {
                    mma16816(acc[mt][q*2+0], aH[mt], bF[q][0], bF[q][1]);
                    mma16816(acc[mt][q*2+1], aH[mt], bF[q][2], bF[q][3]);
                }
        }

        if (!last) { CP_WAIT0(); __syncthreads(); }
    }

    // Epilogue
    const int lane2 = (lane & 3) * 2;
    #pragma unroll
    for (int mt = 0; mt < 2; mt++) {
        #pragma unroll
        for (int half = 0; half < 2; half++) {
            const int m  = bm + wm*32 + mt*16 + (lane >> 2) + half*8;
            const int bi = m >> 11;
            const int si = m & (Ss - 1);
            if (widx == 2) {
                // V: split + transpose to [b,h,d,s]
                #pragma unroll
                for (int nt = 0; nt < 8; nt++) {
                    const int e0 = bn + wn*64 + nt*8 + lane2;
                    const int h  = e0 >> 6;
                    const int d0 = e0 & 63;
                    const float x = acc[mt][nt][half*2+0] + bias[e0];
                    const float y = acc[mt][nt][half*2+1] + bias[e0+1];
                    __nv_bfloat16 hx = __float2bfloat16_rn(x);
                    __nv_bfloat16 hy = __float2bfloat16_rn(y);
                    __nv_bfloat16 lx = __float2bfloat16_rn(x - __bfloat162float(hx));
                    __nv_bfloat16 ly = __float2bfloat16_rn(y - __bfloat162float(hy));
                    const size_t o0 = (((size_t)bi*Hh + h)*HD + d0)*Ss + si;
                    g_Vth[o0]      = hx;
                    g_Vth[o0 + Ss] = hy;
                    g_Vtl[o0]      = lx;
                    g_Vtl[o0 + Ss] = ly;
                }
            } else {
                __nv_bfloat16* dh = widx ? g_Kh : g_Qh;
                __nv_bfloat16* dl = widx ? g_Kl : g_Ql;
                const float scl = widx ? 1.0f : QSCL;   // fold 0.125*log2(e) into Q
                #pragma unroll
                for (int nt = 0; nt < 4; nt++) {
                    const int e0 = bn + wn*64 + nt*8 + lane2;  // d0 < 32 within head
                    const int h  = e0 >> 6;
                    const int d0 = e0 & 63;
                    float x1a = acc[mt][nt][half*2+0]   + bias[e0];
                    float x1b = acc[mt][nt][half*2+1]   + bias[e0+1];
                    float x2a = acc[mt][nt+4][half*2+0] + bias[e0+32];
                    float x2b = acc[mt][nt+4][half*2+1] + bias[e0+33];
                    const float2 sv = *(const float2*)&g_sin[si*32 + d0];
                    const float2 cv = *(const float2*)&g_cos[si*32 + d0];
                    // reference naming swap: out1 = x1*sin - x2*cos ; out2 = x2*sin + x1*cos
                    float o1a = (x1a*sv.x - x2a*cv.x) * scl, o1b = (x1b*sv.y - x2b*cv.y) * scl;
                    float o2a = (x2a*sv.x + x1a*cv.x) * scl, o2b = (x2b*sv.y + x1b*cv.y) * scl;
                    const size_t o = (((size_t)bi*Hh + h)*Ss + si)*HD + d0;
                    *(uint32_t*)&dh[o]      = pack_hi(o1a, o1b);
                    *(uint32_t*)&dl[o]      = pack_lo(o1a, o1b);
                    *(uint32_t*)&dh[o + 32] = pack_hi(o2a, o2b);
                    *(uint32_t*)&dl[o + 32] = pack_lo(o2a, o2b);
                }
            }
        }
    }
}

// ============================================================================
// O-projection GEMM (row-major fp32 out to d_out)
// ============================================================================
__global__ __launch_bounds__(256, 2)
void gemm_o(const float* __restrict__ bias, float* __restrict__ out)
{
    extern __shared__ char smc[];
    const uint32_t sb = smem_u32(smc);
    const int t    = threadIdx.x;
    const int lane = t & 31;
    const int warp = t >> 5;
    const int wm   = warp >> 1;
    const int wn   = warp & 1;
    const int bn   = blockIdx.x * 128;
    const int bm   = blockIdx.y * 128;

    const __nv_bfloat16* Ahg = g_Ch;
    const __nv_bfloat16* Alg = g_Cl;
    const __nv_bfloat16* Bhg = g_Wh + 3*WSZ;
    const __nv_bfloat16* Blg = g_Wl + 3*WSZ;

    float acc[2][8][4];
    #pragma unroll
    for (int mt = 0; mt < 2; mt++)
        #pragma unroll
        for (int nt = 0; nt < 8; nt++)
            #pragma unroll
            for (int j = 0; j < 4; j++) acc[mt][nt][j] = 0.f;

    const int lr0 = t >> 2;
    const int lc  = (t & 3) * 8;

    auto load_stage = [&](int s, int kc) {
        const uint32_t base = sb + (uint32_t)s * STAGE_B;
        #pragma unroll
        for (int i = 0; i < 2; i++) {
            const int r = lr0 + i * 64;
            const uint32_t so = (uint32_t)(r * LDA + lc) * 2;
            CP16(base + 0*TILE_B + so, Ahg + (size_t)(bm + r)*Dd + kc + lc);
            CP16(base + 1*TILE_B + so, Alg + (size_t)(bm + r)*Dd + kc + lc);
            CP16(base + 2*TILE_B + so, Bhg + (size_t)(bn + r)*Dd + kc + lc);
            CP16(base + 3*TILE_B + so, Blg + (size_t)(bn + r)*Dd + kc + lc);
        }
    };

    load_stage(0, 0);
    CP_COMMIT();
    CP_WAIT0();
    __syncthreads();

    const int g8 = lane >> 3;
    const int l8 = lane & 7;
    const int aRow = (g8 & 1) * 8 + l8;
    const int aCol = (g8 >> 1) * 8;
    const int bRow = (g8 >> 1) * 8 + l8;
    const int bCol = (g8 & 1) * 8;

    const int NT = Dd / 32;
    for (int kt = 0; kt < NT; kt++) {
        const int s = kt & 1;
        const int last = (kt + 1 == NT);
        if (!last) { load_stage(s ^ 1, (kt + 1) * 32); CP_COMMIT(); }

        const uint32_t Ah = sb + (uint32_t)s * STAGE_B;
        const uint32_t Al = Ah + TILE_B;
        const uint32_t Bh = Ah + 2*TILE_B;
        const uint32_t Bl = Ah + 3*TILE_B;

        #pragma unroll
        for (int ks = 0; ks < 2; ks++) {
            const int k0 = ks * 16;
            uint32_t aH[2][4], aL[2][4], bF[4][4];
            #pragma unroll
            for (int mt = 0; mt < 2; mt++) {
                ldsm4(aH[mt], Ah + (uint32_t)((wm*32 + mt*16 + aRow) * LDA + k0 + aCol) * 2);
                ldsm4(aL[mt], Al + (uint32_t)((wm*32 + mt*16 + aRow) * LDA + k0 + aCol) * 2);
            }
            #pragma unroll
            for (int q = 0; q < 4; q++)
                ldsm4(bF[q], Bh + (uint32_t)((wn*64 + q*16 + bRow) * LDA + k0 + bCol) * 2);
            #pragma unroll
            for (int mt = 0; mt < 2; mt++)
                #pragma unroll
                for (int q = 0; q < 4; q++) {
                    mma16816(acc[mt][q*2+0], aH[mt], bF[q][0], bF[q][1]);
                    mma16816(acc[mt][q*2+1], aH[mt], bF[q][2], bF[q][3]);
                }
            #pragma unroll
            for (int mt = 0; mt < 2; mt++)
                #pragma unroll
                for (int q = 0; q < 4; q++) {
                    mma16816(acc[mt][q*2+0], aL[mt], bF[q][0], bF[q][1]);
                    mma16816(acc[mt][q*2+1], aL[mt], bF[q][2], bF[q][3]);
                }
            #pragma unroll
            for (int q = 0; q < 4; q++)
                ldsm4(bF[q], Bl + (uint32_t)((wn*64 + q*16 + bRow) * LDA + k0 + bCol) * 2);
            #pragma unroll
            for (int mt = 0; mt < 2; mt++)
                #pragma unroll
                for (int q = 0; q < 4; q++) {
                    mma16816(acc[mt][q*2+0], aH[mt], bF[q][0], bF[q][1]);
                    mma16816(acc[mt][q*2+1], aH[mt], bF[q][2], bF[q][3]);
                }
        }

        if (!last) { CP_WAIT0(); __syncthreads(); }
    }

    #pragma unroll
    for (int mt = 0; mt < 2; mt++) {
        #pragma unroll
        for (int half = 0; half < 2; half++) {
            const int m = bm + wm*32 + mt*16 + (lane >> 2) + half*8;
            #pragma unroll
            for (int nt = 0; nt < 8; nt++) {
                const int e0 = bn + wn*64 + nt*8 + (lane & 3)*2;
                float2 r;
                r.x = acc[mt][nt][half*2+0] + bias[e0];
                r.y = acc[mt][nt][half*2+1] + bias[e0+1];
                *(float2*)&out[(size_t)m*Dd + e0] = r;
            }
        }
    }
}

// ============================================================================
// Flash attention: Q resident in smem (hi+lo), occ 2, double-buffered K/V,
// exp2-based softmax (scale pre-folded into Q).
// ============================================================================
#define ALD 72
#define AQ_B (128*ALD*2)       // 18432
#define AK_B (64*ALD*2)        // 9216
#define KV_STAGE_B (4*AK_B)    // 36864
#define ATTN_SMEM (2*AQ_B + 2*KV_STAGE_B)   // 110592

__global__ __launch_bounds__(256, 2)
void attn_bf()
{
    extern __shared__ char smc[];
    const uint32_t sb  = smem_u32(smc);
    const uint32_t Qh  = sb;
    const uint32_t Ql  = sb + AQ_B;
    const uint32_t KV0 = sb + 2*AQ_B;

    const int t    = threadIdx.x;
    const int lane = t & 31;
    const int warp = t >> 5;
    const int bh   = blockIdx.y;
    const int q0   = blockIdx.x * 128;

    const __nv_bfloat16* Qhg = g_Qh + ((size_t)bh*Ss + q0)*HD;
    const __nv_bfloat16* Qlg = g_Ql + ((size_t)bh*Ss + q0)*HD;
    const __nv_bfloat16* Khg = g_Kh + (size_t)bh*Ss*HD;
    const __nv_bfloat16* Klg = g_Kl + (size_t)bh*Ss*HD;
    const __nv_bfloat16* Vhg = g_Vth + (size_t)bh*HD*Ss;
    const __nv_bfloat16* Vlg = g_Vtl + (size_t)bh*HD*Ss;

    auto load_tile = [&](int kv, int s) {
        const uint32_t Kh = KV0 + (uint32_t)s * KV_STAGE_B;
        #pragma unroll
        for (int i = 0; i < 2; i++) {
            const int slot = t + i*256;
            const int r  = slot >> 3;
            const int c8 = (slot & 7) * 8;
            const uint32_t so = (uint32_t)(r * ALD + c8) * 2;
            CP16(Kh + 0*AK_B + so, Khg + (size_t)(kv + r)*HD + c8);
            CP16(Kh + 1*AK_B + so, Klg + (size_t)(kv + r)*HD + c8);
            CP16(Kh + 2*AK_B + so, Vhg + (size_t)r*Ss + kv + c8);
            CP16(Kh + 3*AK_B + so, Vlg + (size_t)r*Ss + kv + c8);
        }
    };

    // Q tile (hi+lo) -> smem, plus first KV tile
    #pragma unroll
    for (int i = 0; i < 4; i++) {
        const int slot = t + i*256;
        const int r  = slot >> 3;
        const int c8 = (slot & 7) * 8;
        const uint32_t so = (uint32_t)(r * ALD + c8) * 2;
        CP16(Qh + so, Qhg + (size_t)r*HD + c8);
        CP16(Ql + so, Qlg + (size_t)r*HD + c8);
    }
    load_tile(0, 0);
    CP_COMMIT();

    const int g8 = lane >> 3;
    const int l8 = lane & 7;
    const int aRow = (g8 & 1) * 8 + l8;
    const int aCol = (g8 >> 1) * 8;
    const int bRow = (g8 >> 1) * 8 + l8;
    const int bCol = (g8 & 1) * 8;

    float m_i[2], l_i[2];
    float O[8][4];
    m_i[0] = m_i[1] = -1e30f;
    l_i[0] = l_i[1] = 0.f;
    #pragma unroll
    for (int nf = 0; nf < 8; nf++)
        #pragma unroll
        for (int j = 0; j < 4; j++) O[nf][j] = 0.f;

    const int NTILE = Ss / 64;
    for (int n = 0; n < NTILE; n++) {
        const int s = n & 1;
        CP_WAIT0();
        __syncthreads();
        if (n + 1 < NTILE) { load_tile((n + 1) * 64, s ^ 1); CP_COMMIT(); }

        const uint32_t Kh = KV0 + (uint32_t)s * KV_STAGE_B;
        const uint32_t Kl = Kh + AK_B;
        const uint32_t Vh = Kl + AK_B;
        const uint32_t Vl = Vh + AK_B;

        // ---- S = Q K^T (x3 split); Q carries 0.125*log2e ----
        float S[8][4];
        #pragma unroll
        for (int nf = 0; nf < 8; nf++)
            #pragma unroll
            for (int j = 0; j < 4; j++) S[nf][j] = 0.f;

        #pragma unroll
        for (int ks = 0; ks < 4; ks++) {
            const int k0 = ks * 16;
            uint32_t aH[4], aL[4], bF[4][4];
            ldsm4(aH, Qh + (uint32_t)((warp*16 + aRow)*ALD + k0 + aCol) * 2);
            ldsm4(aL, Ql + (uint32_t)((warp*16 + aRow)*ALD + k0 + aCol) * 2);
            #pragma unroll
            for (int q = 0; q < 4; q++) {
                ldsm4(bF[q], Kh + (uint32_t)((q*16 + bRow)*ALD + k0 + bCol) * 2);
                mma16816(S[2*q+0], aH, bF[q][0], bF[q][1]);
                mma16816(S[2*q+1], aH, bF[q][2], bF[q][3]);
                mma16816(S[2*q+0], aL, bF[q][0], bF[q][1]);
                mma16816(S[2*q+1], aL, bF[q][2], bF[q][3]);
            }
            #pragma unroll
            for (int q = 0; q < 4; q++) {
                ldsm4(bF[q], Kl + (uint32_t)((q*16 + bRow)*ALD + k0 + bCol) * 2);
                mma16816(S[2*q+0], aH, bF[q][0], bF[q][1]);
                mma16816(S[2*q+1], aH, bF[q][2], bF[q][3]);
            }
        }

        // ---- online softmax in exp2 domain ----
        #pragma unroll
        for (int h = 0; h < 2; h++) {
            float mx = -1e30f;
            #pragma unroll
            for (int nf = 0; nf < 8; nf++)
                mx = fmaxf(mx, fmaxf(S[nf][2*h], S[nf][2*h+1]));
            mx = fmaxf(mx, __shfl_xor_sync(0xffffffffu, mx, 1));
            mx = fmaxf(mx, __shfl_xor_sync(0xffffffffu, mx, 2));
            const float mn    = fmaxf(m_i[h], mx);
            const float alpha = exp2f(m_i[h] - mn);
            float ps = 0.f;
            #pragma unroll
            for (int nf = 0; nf < 8; nf++) {
                float p0 = exp2f(S[nf][2*h]   - mn);
                float p1 = exp2f(S[nf][2*h+1] - mn);
                S[nf][2*h] = p0; S[nf][2*h+1] = p1;
                ps += p0 + p1;
            }
            ps += __shfl_xor_sync(0xffffffffu, ps, 1);
            ps += __shfl_xor_sync(0xffffffffu, ps, 2);
            m_i[h] = mn;
            l_i[h] = l_i[h]*alpha + ps;
            #pragma unroll
            for (int nf = 0; nf < 8; nf++) {
                O[nf][2*h]   *= alpha;
                O[nf][2*h+1] *= alpha;
            }
        }

        // ---- O += P V (P in registers, x3 split) ----
        #pragma unroll
        for (int ks = 0; ks < 4; ks++) {
            uint32_t aP[4], aPl[4];
            aP[0]  = pack_hi(S[2*ks][0],   S[2*ks][1]);
            aP[1]  = pack_hi(S[2*ks][2],   S[2*ks][3]);
            aP[2]  = pack_hi(S[2*ks+1][0], S[2*ks+1][1]);
            aP[3]  = pack_hi(S[2*ks+1][2], S[2*ks+1][3]);
            aPl[0] = pack_lo(S[2*ks][0],   S[2*ks][1]);
            aPl[1] = pack_lo(S[2*ks][2],   S[2*ks][3]);
            aPl[2] = pack_lo(S[2*ks+1][0], S[2*ks+1][1]);
            aPl[3] = pack_lo(S[2*ks+1][2], S[2*ks+1][3]);
            const int k0 = ks * 16;
            #pragma unroll
            for (int q = 0; q < 4; q++) {
                uint32_t bb[4];
                ldsm4(bb, Vh + (uint32_t)((q*16 + bRow)*ALD + k0 + bCol) * 2);
                mma16816(O[2*q+0], aP,  bb[0], bb[1]);
                mma16816(O[2*q+1], aP,  bb[2], bb[3]);
                mma16816(O[2*q+0], aPl, bb[0], bb[1]);
                mma16816(O[2*q+1], aPl, bb[2], bb[3]);
                ldsm4(bb, Vl + (uint32_t)((q*16 + bRow)*ALD + k0 + bCol) * 2);
                mma16816(O[2*q+0], aP, bb[0], bb[1]);
                mma16816(O[2*q+1], aP, bb[2], bb[3]);
            }
        }
    }

    // Normalize + write SPLIT ctx [b, s, h*64 + d]
    const int b_idx = bh >> 4;
    const int hidx  = bh & 15;
    #pragma unroll
    for (int h = 0; h < 2; h++) {
        const int s_idx = q0 + warp*16 + (lane >> 2) + h*8;
        const float inv = 1.f / l_i[h];
        #pragma unroll
        for (int nf = 0; nf < 8; nf++) {
            const int d0 = nf*8 + (lane & 3)*2;
            const size_t o = ((size_t)b_idx*Ss + s_idx)*Dd + hidx*HD + d0;
            const float x = O[nf][2*h] * inv;
            const float y = O[nf][2*h+1] * inv;
            *(uint32_t*)&g_Ch[o] = pack_hi(x, y);
            *(uint32_t*)&g_Cl[o] = pack_lo(x, y);
        }
    }
}

// ---------------------------------------------------------------------------
extern "C" void kernel_launch(void* const* d_in, const int* in_sizes, int n_in,
                              void* d_out, int out_size)
{
    (void)in_sizes; (void)n_in; (void)out_size;
    const float* X  = (const float*)d_in[0];
    const float* Wq = (const float*)d_in[1];
    const float* bq = (const float*)d_in[2];
    const float* Wk = (const float*)d_in[3];
    const float* bk = (const float*)d_in[4];
    const float* Wv = (const float*)d_in[5];
    const float* bv = (const float*)d_in[6];
    const float* Wo = (const float*)d_in[7];
    const float* bo = (const float*)d_in[8];
    float* out = (float*)d_out;

    cudaFuncSetAttribute(gemm_qkv, cudaFuncAttributeMaxDynamicSharedMemorySize, GEMM_SMEM);
    cudaFuncSetAttribute(gemm_o,   cudaFuncAttributeMaxDynamicSharedMemorySize, GEMM_SMEM);
    cudaFuncSetAttribute(attn_bf,  cudaFuncAttributeMaxDynamicSharedMemorySize, ATTN_SMEM);

    split_all<<<NB_SPLIT + NB_TABLE, 256>>>(X, Wq, Wk, Wv, Wo);

    gemm_qkv<<<dim3(Dd/128, MM/128, 3), 256, GEMM_SMEM>>>(bq, bk, bv);

    attn_bf<<<dim3(Ss/128, BH), 256, ATTN_SMEM>>>();

    gemm_o<<<dim3(Dd/128, MM/128), 256, GEMM_SMEM>>>(bo, out);
}